// round 7
// baseline (speedup 1.0000x reference)
#include <cuda_runtime.h>
#include <cuda_bf16.h>
#include <cstdint>
#include <math.h>

// Problem constants
#define B_   4
#define S_   2048
#define F_   2048
#define H_   16
#define G_   4
#define DH_  128
#define ROT_ 32

#define MTOT (B_*S_)   // 8192
#define QSCALE 0.12751743f   // log2(e)/sqrt(128)

// ---------------------------------------------------------------------------
// Static scratch
// ---------------------------------------------------------------------------
__device__ __align__(16) __nv_bfloat16 g_qhi[MTOT*F_];
__device__ __align__(16) __nv_bfloat16 g_qlo[MTOT*F_];
__device__ __align__(16) __nv_bfloat16 g_khi[MTOT*G_*DH_];
__device__ __align__(16) __nv_bfloat16 g_klo[MTOT*G_*DH_];
__device__ __align__(16) __nv_bfloat16 g_vhi[MTOT*G_*DH_];
__device__ __align__(16) __nv_bfloat16 g_vlo[MTOT*G_*DH_];
__device__ __align__(16) __nv_bfloat16 g_xhi[MTOT*F_];
__device__ __align__(16) __nv_bfloat16 g_xlo[MTOT*F_];
__device__ __align__(16) __nv_bfloat16 g_ahi[MTOT*F_];
__device__ __align__(16) __nv_bfloat16 g_alo[MTOT*F_];
__device__ __align__(16) __nv_bfloat16 g_wqT_hi[F_*F_];
__device__ __align__(16) __nv_bfloat16 g_wqT_lo[F_*F_];
__device__ __align__(16) __nv_bfloat16 g_wkT_hi[G_*DH_*F_];
__device__ __align__(16) __nv_bfloat16 g_wkT_lo[G_*DH_*F_];
__device__ __align__(16) __nv_bfloat16 g_wvT_hi[G_*DH_*F_];
__device__ __align__(16) __nv_bfloat16 g_wvT_lo[G_*DH_*F_];
__device__ __align__(16) __nv_bfloat16 g_woT_hi[F_*F_];
__device__ __align__(16) __nv_bfloat16 g_woT_lo[F_*F_];
__device__ float g_cos[S_*ROT_];
__device__ float g_sin[S_*ROT_];

// ---------------------------------------------------------------------------
// Baseline-legal PTX helpers (sm_80+)
// ---------------------------------------------------------------------------
__device__ __forceinline__ uint32_t smem_u32(const void* p) {
    uint32_t a;
    asm("{ .reg .u64 t; cvta.to.shared.u64 t, %1; cvt.u32.u64 %0, t; }" : "=r"(a) : "l"(p));
    return a;
}
__device__ __forceinline__ void ldsm_x4(uint32_t* r, uint32_t addr) {
    asm volatile("ldmatrix.sync.aligned.m8n8.x4.shared.b16 {%0,%1,%2,%3}, [%4];"
                 : "=r"(r[0]), "=r"(r[1]), "=r"(r[2]), "=r"(r[3]) : "r"(addr));
}
__device__ __forceinline__ void ldsm_x4_t(uint32_t* r, uint32_t addr) {
    asm volatile("ldmatrix.sync.aligned.m8n8.x4.trans.shared.b16 {%0,%1,%2,%3}, [%4];"
                 : "=r"(r[0]), "=r"(r[1]), "=r"(r[2]), "=r"(r[3]) : "r"(addr));
}
__device__ __forceinline__ void mma_bf16(float* c, const uint32_t* a, uint32_t b0, uint32_t b1) {
    asm volatile("mma.sync.aligned.m16n8k16.row.col.f32.bf16.bf16.f32 "
                 "{%0,%1,%2,%3}, {%4,%5,%6,%7}, {%8,%9}, {%0,%1,%2,%3};"
                 : "+f"(c[0]), "+f"(c[1]), "+f"(c[2]), "+f"(c[3])
                 : "r"(a[0]), "r"(a[1]), "r"(a[2]), "r"(a[3]), "r"(b0), "r"(b1));
}
#define CP_ASYNC16(dst, src) \
    asm volatile("cp.async.cg.shared.global [%0], [%1], 16;" :: "r"(dst), "l"(src) : "memory")
#define CP_COMMIT()  asm volatile("cp.async.commit_group;" ::: "memory")
#define CP_WAIT(n)   asm volatile("cp.async.wait_group %0;" :: "n"(n) : "memory")

// ---------------------------------------------------------------------------
// RoPE table init
// ---------------------------------------------------------------------------
__global__ void rope_init_kernel() {
    int idx = blockIdx.x * blockDim.x + threadIdx.x;
    if (idx < S_ * ROT_) {
        int t = idx >> 5, p = idx & 31;
        double freq = pow(10000.0, -((double)(2 * p)) / 64.0);
        double f = (double)t * freq;
        g_cos[idx] = (float)cos(f);
        g_sin[idx] = (float)sin(f);
    }
}

// ---------------------------------------------------------------------------
// fp32 -> bf16 hi/lo split
// ---------------------------------------------------------------------------
__global__ void convert_split_kernel(const float* __restrict__ src,
                                     __nv_bfloat16* __restrict__ hi,
                                     __nv_bfloat16* __restrict__ lo, int n4) {
    int i = blockIdx.x * blockDim.x + threadIdx.x;
    if (i >= n4) return;
    float4 v = ((const float4*)src)[i];
    __nv_bfloat16 h[4], l[4];
    float vv[4] = {v.x, v.y, v.z, v.w};
#pragma unroll
    for (int j = 0; j < 4; j++) {
        h[j] = __float2bfloat16(vv[j]);
        l[j] = __float2bfloat16(vv[j] - __bfloat162float(h[j]));
    }
    ((uint2*)hi)[i] = *(uint2*)h;
    ((uint2*)lo)[i] = *(uint2*)l;
}

// ---------------------------------------------------------------------------
// Weight transpose + split:  W[K][N] fp32 -> T[N][K] bf16 hi/lo
// ---------------------------------------------------------------------------
__global__ void transpose_split_kernel(const float* __restrict__ W,
                                       __nv_bfloat16* __restrict__ Thi,
                                       __nv_bfloat16* __restrict__ Tlo,
                                       int K, int N) {
    __shared__ float t[32][33];
    int k0 = blockIdx.y * 32, n0 = blockIdx.x * 32;
    int tx = threadIdx.x, ty = threadIdx.y;   // 32 x 8
#pragma unroll
    for (int j = 0; j < 4; j++)
        t[ty + j * 8][tx] = W[(size_t)(k0 + ty + j * 8) * N + n0 + tx];
    __syncthreads();
#pragma unroll
    for (int j = 0; j < 4; j++) {
        int n = n0 + ty + j * 8, k = k0 + tx;
        float v = t[tx][ty + j * 8];
        __nv_bfloat16 h = __float2bfloat16(v);
        __nv_bfloat16 l = __float2bfloat16(v - __bfloat162float(h));
        Thi[(size_t)n * K + k] = h;
        Tlo[(size_t)n * K + k] = l;
    }
}

// ---------------------------------------------------------------------------
// HMMA bf16x3 GEMM. CTA tile 128x128, BK=32, 2-stage cp.async pipeline.
// 8 warps: 2(M) x 4(N); warp tile 64x32. 2 CTAs/SM (reg cap 128).
// MMA issue ordered in passes (hh, hl, lh) across 8 accumulators per mi-pair
// so same-accumulator reuse distance is 8 (hides HMMA accumulate latency).
// mode: 0 = fp32 out, 1 = Q (rope+scale, hi/lo), 2 = K (rope, hi/lo), 3 = V.
// ---------------------------------------------------------------------------
#define GBK    32
#define TSTR   40                         // smem row stride in bf16 (80 B)
#define TILE_BYTES (128 * TSTR * 2)       // 10240
#define STAGE_BYTES (4 * TILE_BYTES)      // 40960
#define SMEM_GEMM (2 * STAGE_BYTES)       // 81920

__global__ __launch_bounds__(256, 2)
void gemm_bf16x3_mma(const __nv_bfloat16* __restrict__ Ahi,
                     const __nv_bfloat16* __restrict__ Alo,
                     const __nv_bfloat16* __restrict__ BThi,
                     const __nv_bfloat16* __restrict__ BTlo,
                     const float* __restrict__ bias,
                     float* __restrict__ C,
                     __nv_bfloat16* __restrict__ Chi,
                     __nv_bfloat16* __restrict__ Clo,
                     int M, int N, int K, int mode)
{
    extern __shared__ char smem[];
    const uint32_t smem_base = smem_u32(smem);

    const int tid = threadIdx.x;
    const int wid = tid >> 5;
    const int lid = tid & 31;
    const int warpM = wid & 1;
    const int warpN = wid >> 1;
    const size_t rowBase = (size_t)blockIdx.y * 128;
    const size_t colBase = (size_t)blockIdx.x * 128;

    const int NC = K / GBK;

    auto prefetch = [&](int stage, int k0) {
        uint32_t st = smem_base + stage * STAGE_BYTES;
#pragma unroll
        for (int t = 0; t < 2; t++) {
            int cidx = tid + t * 256;
            int r  = cidx >> 2;
            int ch = cidx & 3;
            uint32_t doff = r * (TSTR * 2) + ch * 16;
            size_t goffA = (rowBase + r) * (size_t)K + k0 + ch * 8;
            size_t goffB = (colBase + r) * (size_t)K + k0 + ch * 8;
            CP_ASYNC16(st + doff,                (const char*)(Ahi  + goffA));
            CP_ASYNC16(st + TILE_BYTES + doff,   (const char*)(Alo  + goffA));
            CP_ASYNC16(st + 2*TILE_BYTES + doff, (const char*)(BThi + goffB));
            CP_ASYNC16(st + 3*TILE_BYTES + doff, (const char*)(BTlo + goffB));
        }
        CP_COMMIT();
    };

    float acc[4][4][4];
#pragma unroll
    for (int i = 0; i < 4; i++)
#pragma unroll
        for (int j = 0; j < 4; j++)
#pragma unroll
            for (int q = 0; q < 4; q++) acc[i][j][q] = 0.f;

    const int laneRow = (lid & 7) + ((lid >> 3) & 1) * 8;
    const int laneK   = (lid >> 4) * 8;

    prefetch(0, 0);

    for (int kc = 0; kc < NC; ++kc) {
        const int s = kc & 1;
        if (kc + 1 < NC) prefetch(s ^ 1, (kc + 1) * GBK);
        if (kc + 1 < NC) { CP_WAIT(1); } else { CP_WAIT(0); }
        __syncthreads();

        const uint32_t st = smem_base + s * STAGE_BYTES;
        const uint32_t aHib = st;
        const uint32_t aLob = st + TILE_BYTES;
        const uint32_t bHib = st + 2*TILE_BYTES;
        const uint32_t bLob = st + 3*TILE_BYTES;

#pragma unroll
        for (int k16 = 0; k16 < GBK; k16 += 16) {
            const int kk = k16 + laneK;
            // B fragments (16 regs)
            uint32_t bH[2][4], bL[2][4];
#pragma unroll
            for (int nt = 0; nt < 2; nt++) {
                int row = warpN * 32 + nt * 16 + laneRow;
                uint32_t off = (row * TSTR + kk) * 2;
                ldsm_x4(bH[nt], bHib + off);
                ldsm_x4(bL[nt], bLob + off);
            }
            // A fragments streamed in mi-pairs (16 regs live)
#pragma unroll
            for (int mp = 0; mp < 4; mp += 2) {
                uint32_t aH[2][4], aL[2][4];
#pragma unroll
                for (int i = 0; i < 2; i++) {
                    int row = warpM * 64 + (mp + i) * 16 + laneRow;
                    uint32_t off = (row * TSTR + kk) * 2;
                    ldsm_x4(aH[i], aHib + off);
                    ldsm_x4(aL[i], aLob + off);
                }
                // pass 1: hi*hi — 8 MMAs, 8 distinct accumulators
#pragma unroll
                for (int i = 0; i < 2; i++)
#pragma unroll
                    for (int nt = 0; nt < 2; nt++) {
                        mma_bf16(acc[mp+i][2*nt],   aH[i], bH[nt][0], bH[nt][2]);
                        mma_bf16(acc[mp+i][2*nt+1], aH[i], bH[nt][1], bH[nt][3]);
                    }
                // pass 2: hi*lo
#pragma unroll
                for (int i = 0; i < 2; i++)
#pragma unroll
                    for (int nt = 0; nt < 2; nt++) {
                        mma_bf16(acc[mp+i][2*nt],   aH[i], bL[nt][0], bL[nt][2]);
                        mma_bf16(acc[mp+i][2*nt+1], aH[i], bL[nt][1], bL[nt][3]);
                    }
                // pass 3: lo*hi
#pragma unroll
                for (int i = 0; i < 2; i++)
#pragma unroll
                    for (int nt = 0; nt < 2; nt++) {
                        mma_bf16(acc[mp+i][2*nt],   aL[i], bH[nt][0], bH[nt][2]);
                        mma_bf16(acc[mp+i][2*nt+1], aL[i], bH[nt][1], bH[nt][3]);
                    }
            }
        }
        __syncthreads();
    }

    // Epilogue
#pragma unroll
    for (int mi = 0; mi < 4; mi++) {
#pragma unroll
        for (int nj = 0; nj < 4; nj++) {
            int row0 = (int)rowBase + warpM * 64 + mi * 16 + (lid >> 2);
            int row1 = row0 + 8;
            int col  = (int)colBase + warpN * 32 + nj * 8 + (lid & 3) * 2;
            float b0 = __ldg(bias + col), b1 = __ldg(bias + col + 1);
            float v0 = acc[mi][nj][0] + b0, v1 = acc[mi][nj][1] + b1;
            float v2 = acc[mi][nj][2] + b0, v3 = acc[mi][nj][3] + b1;
            int d = col & (DH_ - 1);
            if (mode >= 1 && mode <= 2 && d < 64) {   // RoPE for Q,K
                int p = d >> 1;
                int s0 = row0 & (S_ - 1);
                int s1 = row1 & (S_ - 1);
                float c0 = g_cos[s0 * ROT_ + p], sn0 = g_sin[s0 * ROT_ + p];
                float c1 = g_cos[s1 * ROT_ + p], sn1 = g_sin[s1 * ROT_ + p];
                float a0 = v0, bb0 = v1, a1 = v2, bb1 = v3;
                v0 = a0 * c0 - bb0 * sn0;  v1 = bb0 * c0 + a0 * sn0;
                v2 = a1 * c1 - bb1 * sn1;  v3 = bb1 * c1 + a1 * sn1;
            }
            if (mode == 0) {
                *(float2*)(C + (size_t)row0 * N + col) = make_float2(v0, v1);
                *(float2*)(C + (size_t)row1 * N + col) = make_float2(v2, v3);
            } else {
                if (mode == 1) { v0 *= QSCALE; v1 *= QSCALE; v2 *= QSCALE; v3 *= QSCALE; }
                __nv_bfloat162 h0 = __floats2bfloat162_rn(v0, v1);
                __nv_bfloat162 l0 = __floats2bfloat162_rn(v0 - __bfloat162float(h0.x),
                                                          v1 - __bfloat162float(h0.y));
                __nv_bfloat162 h1 = __floats2bfloat162_rn(v2, v3);
                __nv_bfloat162 l1 = __floats2bfloat162_rn(v2 - __bfloat162float(h1.x),
                                                          v3 - __bfloat162float(h1.y));
                *(uint32_t*)(Chi + (size_t)row0 * N + col) = *(uint32_t*)&h0;
                *(uint32_t*)(Clo + (size_t)row0 * N + col) = *(uint32_t*)&l0;
                *(uint32_t*)(Chi + (size_t)row1 * N + col) = *(uint32_t*)&h1;
                *(uint32_t*)(Clo + (size_t)row1 * N + col) = *(uint32_t*)&l1;
            }
        }
    }
}

// ---------------------------------------------------------------------------
// Tensor-core flash attention (bf16x3, causal, GQA).
// CTA: 128 q rows x 64 kv cols per block. 8 warps x 16 q rows.
// MMA passes ordered for accumulate-latency hiding (distance 4).
// ---------------------------------------------------------------------------
#define FSTR   272                 // bytes per smem row (128 bf16 + 8 pad)
#define FTILEB (64 * FSTR)         // 17408 bytes per 64-row tile
#define FQOFF  (8 * FTILEB)        // Q area after 2 KV stages
#define SMEM_FLASH (12 * FTILEB)   // 208896

__global__ __launch_bounds__(256)
void flash_mma_kernel()
{
    extern __shared__ char fsm[];
    const uint32_t sb = smem_u32(fsm);
    const int tid = threadIdx.x;
    const int wid = tid >> 5;
    const int lid = tid & 31;
    const int qb  = 15 - (int)blockIdx.x;   // big tiles first
    const int h   = blockIdx.y;
    const int b   = blockIdx.z;
    const int g   = h >> 2;
    const int qbase = qb * 128;

#pragma unroll
    for (int i = 0; i < 8; i++) {
        int q = tid + i * 256;
        int r = q >> 4, ch = q & 15;
        size_t off = (((size_t)(b * S_ + qbase + r)) * H_ + h) * DH_ + ch * 8;
        uint32_t dst = sb + FQOFF + (r >> 6) * FTILEB + (r & 63) * FSTR + ch * 16;
        CP_ASYNC16(dst,              (const char*)(g_qhi + off));
        CP_ASYNC16(dst + 2*FTILEB,   (const char*)(g_qlo + off));
    }
    CP_COMMIT();
    CP_WAIT(0);
    __syncthreads();

    auto prefetch = [&](int jblk, int stage) {
        uint32_t st = sb + stage * 4 * FTILEB;
        size_t base = (((size_t)(b * S_ + jblk * 64)) * G_ + g) * DH_;
#pragma unroll
        for (int i = 0; i < 4; i++) {
            int q = tid + i * 256;
            int r = q >> 4, ch = q & 15;
            size_t off = base + (size_t)r * (G_ * DH_) + ch * 8;
            uint32_t d = st + r * FSTR + ch * 16;
            CP_ASYNC16(d,              (const char*)(g_khi + off));
            CP_ASYNC16(d + FTILEB,     (const char*)(g_klo + off));
            CP_ASYNC16(d + 2*FTILEB,   (const char*)(g_vhi + off));
            CP_ASYNC16(d + 3*FTILEB,   (const char*)(g_vlo + off));
        }
        CP_COMMIT();
    };

    float O[16][4];
#pragma unroll
    for (int i = 0; i < 16; i++)
#pragma unroll
        for (int q = 0; q < 4; q++) O[i][q] = 0.f;
    float m2[2] = {-1e30f, -1e30f};
    float l2[2] = {0.f, 0.f};

    const int nblocks = 2 * (qb + 1);
    prefetch(0, 0);

    const int qrl = wid * 16 + (lid & 15);
    const uint32_t qaddrH = sb + FQOFF + (qrl >> 6) * FTILEB + (qrl & 63) * FSTR + (lid >> 4) * 16;
    const uint32_t lanebase = (lid & 15) * FSTR + (lid >> 4) * 16;
    const int warpRow0 = qbase + wid * 16;

    for (int j = 0; j < nblocks; j++) {
        const int st = j & 1;
        if (j + 1 < nblocks) { prefetch(j + 1, st ^ 1); CP_WAIT(1); }
        else                 { CP_WAIT(0); }
        __syncthreads();

        const uint32_t kH = sb + st * 4 * FTILEB + lanebase;

        float sacc[8][4];
#pragma unroll
        for (int nb = 0; nb < 8; nb++)
#pragma unroll
            for (int q = 0; q < 4; q++) sacc[nb][q] = 0.f;

#pragma unroll
        for (int kc = 0; kc < 8; kc++) {
            uint32_t qh[4], ql[4];
            ldsm_x4(qh, qaddrH + kc * 32);
            ldsm_x4(ql, qaddrH + 2*FTILEB + kc * 32);
            // process n16 in pairs; per pair 12 MMAs in 3 passes of 4
#pragma unroll
            for (int np = 0; np < 4; np += 2) {
                uint32_t rH[2][4], rL[2][4];
#pragma unroll
                for (int i = 0; i < 2; i++) {
                    uint32_t off = kH + (np + i) * (16 * FSTR) + kc * 32;
                    ldsm_x4(rH[i], off);
                    ldsm_x4(rL[i], off + FTILEB - (uint32_t)0 + (FTILEB - FTILEB));  // placeholder
                }
                // fix: load rL correctly
#pragma unroll
                for (int i = 0; i < 2; i++) {
                    uint32_t off = kH + FTILEB + (np + i) * (16 * FSTR) + kc * 32;
                    ldsm_x4(rL[i], off);
                }
                // pass hh
#pragma unroll
                for (int i = 0; i < 2; i++) {
                    mma_bf16(sacc[2*(np+i)],   qh, rH[i][0], rH[i][2]);
                    mma_bf16(sacc[2*(np+i)+1], qh, rH[i][1], rH[i][3]);
                }
                // pass hl
#pragma unroll
                for (int i = 0; i < 2; i++) {
                    mma_bf16(sacc[2*(np+i)],   qh, rL[i][0], rL[i][2]);
                    mma_bf16(sacc[2*(np+i)+1], qh, rL[i][1], rL[i][3]);
                }
                // pass lh
#pragma unroll
                for (int i = 0; i < 2; i++) {
                    mma_bf16(sacc[2*(np+i)],   ql, rH[i][0], rH[i][2]);
                    mma_bf16(sacc[2*(np+i)+1], ql, rH[i][1], rH[i][3]);
                }
            }
        }

        if (j * 64 + 63 > warpRow0) {
#pragma unroll
            for (int nb = 0; nb < 8; nb++)
#pragma unroll
                for (int q = 0; q < 4; q++) {
                    int col = j * 64 + nb * 8 + (lid & 3) * 2 + (q & 1);
                    int row = warpRow0 + (lid >> 2) + (q >> 1) * 8;
                    if (col > row) sacc[nb][q] = -1e30f;
                }
        }

#pragma unroll
        for (int rh = 0; rh < 2; rh++) {
            float rmax = -1e30f;
#pragma unroll
            for (int nb = 0; nb < 8; nb++)
                rmax = fmaxf(rmax, fmaxf(sacc[nb][rh*2], sacc[nb][rh*2+1]));
            rmax = fmaxf(rmax, __shfl_xor_sync(0xffffffffu, rmax, 1));
            rmax = fmaxf(rmax, __shfl_xor_sync(0xffffffffu, rmax, 2));
            float mnew = fmaxf(m2[rh], rmax);
            float alpha = exp2f(m2[rh] - mnew);
            float rsum = 0.f;
#pragma unroll
            for (int nb = 0; nb < 8; nb++) {
                float p0 = exp2f(sacc[nb][rh*2]   - mnew);
                float p1 = exp2f(sacc[nb][rh*2+1] - mnew);
                sacc[nb][rh*2] = p0; sacc[nb][rh*2+1] = p1;
                rsum += p0 + p1;
            }
            rsum += __shfl_xor_sync(0xffffffffu, rsum, 1);
            rsum += __shfl_xor_sync(0xffffffffu, rsum, 2);
            l2[rh] = l2[rh] * alpha + rsum;
            m2[rh] = mnew;
#pragma unroll
            for (int nb = 0; nb < 16; nb++) {
                O[nb][rh*2]   *= alpha;
                O[nb][rh*2+1] *= alpha;
            }
        }

        uint32_t ph[4][4], pl[4][4];
#pragma unroll
        for (int kc = 0; kc < 4; kc++)
#pragma unroll
            for (int t = 0; t < 4; t++) {
                int nb = 2*kc + (t >> 1);
                float p0 = sacc[nb][(t & 1) * 2];
                float p1 = sacc[nb][(t & 1) * 2 + 1];
                __nv_bfloat162 hh = __floats2bfloat162_rn(p0, p1);
                __nv_bfloat162 ll = __floats2bfloat162_rn(p0 - __bfloat162float(hh.x),
                                                          p1 - __bfloat162float(hh.y));
                ph[kc][t] = *(uint32_t*)&hh;
                pl[kc][t] = *(uint32_t*)&ll;
            }

        const uint32_t vbase = sb + st * 4 * FTILEB + 2*FTILEB + lanebase;
#pragma unroll
        for (int kc = 0; kc < 4; kc++) {
            uint32_t vrow = vbase + kc * (16 * FSTR);
            // process ng in pairs; 12 MMAs in 3 passes of 4
#pragma unroll
            for (int ng = 0; ng < 8; ng += 2) {
                uint32_t vh[2][4], vl[2][4];
#pragma unroll
                for (int i = 0; i < 2; i++) {
                    ldsm_x4_t(vh[i], vrow + (ng + i) * 32);
                    ldsm_x4_t(vl[i], vrow + FTILEB + (ng + i) * 32);
                }
                // pass hh
#pragma unroll
                for (int i = 0; i < 2; i++) {
                    mma_bf16(O[2*(ng+i)],   ph[kc], vh[i][0], vh[i][1]);
                    mma_bf16(O[2*(ng+i)+1], ph[kc], vh[i][2], vh[i][3]);
                }
                // pass hl
#pragma unroll
                for (int i = 0; i < 2; i++) {
                    mma_bf16(O[2*(ng+i)],   ph[kc], vl[i][0], vl[i][1]);
                    mma_bf16(O[2*(ng+i)+1], ph[kc], vl[i][2], vl[i][3]);
                }
                // pass lh
#pragma unroll
                for (int i = 0; i < 2; i++) {
                    mma_bf16(O[2*(ng+i)],   pl[kc], vh[i][0], vh[i][1]);
                    mma_bf16(O[2*(ng+i)+1], pl[kc], vh[i][2], vh[i][3]);
                }
            }
        }
        __syncthreads();
    }

    const float inv0 = 1.f / l2[0];
    const float inv1 = 1.f / l2[1];
    const int r0 = qbase + wid * 16 + (lid >> 2);
#pragma unroll
    for (int nb = 0; nb < 16; nb++) {
        int col = h * DH_ + nb * 8 + (lid & 3) * 2;
        size_t base0 = ((size_t)(b * S_ + r0)) * F_ + col;
        size_t base1 = ((size_t)(b * S_ + r0 + 8)) * F_ + col;
        float v0 = O[nb][0] * inv0, v1 = O[nb][1] * inv0;
        float v2 = O[nb][2] * inv1, v3 = O[nb][3] * inv1;
        __nv_bfloat162 h0 = __floats2bfloat162_rn(v0, v1);
        __nv_bfloat162 l0 = __floats2bfloat162_rn(v0 - __bfloat162float(h0.x),
                                                  v1 - __bfloat162float(h0.y));
        __nv_bfloat162 h1 = __floats2bfloat162_rn(v2, v3);
        __nv_bfloat162 l1 = __floats2bfloat162_rn(v2 - __bfloat162float(h1.x),
                                                  v3 - __bfloat162float(h1.y));
        *(uint32_t*)(g_ahi + base0) = *(uint32_t*)&h0;
        *(uint32_t*)(g_alo + base0) = *(uint32_t*)&l0;
        *(uint32_t*)(g_ahi + base1) = *(uint32_t*)&h1;
        *(uint32_t*)(g_alo + base1) = *(uint32_t*)&l1;
    }
}

// ---------------------------------------------------------------------------
extern "C" void kernel_launch(void* const* d_in, const int* in_sizes, int n_in,
                              void* d_out, int out_size)
{
    const float* x  = (const float*)d_in[0];
    const float* wq = (const float*)d_in[1];
    const float* bq = (const float*)d_in[2];
    const float* wk = (const float*)d_in[3];
    const float* bk = (const float*)d_in[4];
    const float* wv = (const float*)d_in[5];
    const float* bv = (const float*)d_in[6];
    const float* wo = (const float*)d_in[7];
    const float* bo = (const float*)d_in[8];
    float* out = (float*)d_out;

    __nv_bfloat16 *xhi, *xlo, *ahi, *alo;
    cudaGetSymbolAddress((void**)&xhi, g_xhi);
    cudaGetSymbolAddress((void**)&xlo, g_xlo);
    cudaGetSymbolAddress((void**)&ahi, g_ahi);
    cudaGetSymbolAddress((void**)&alo, g_alo);
    __nv_bfloat16 *qhi, *qlo, *khi, *klo, *vhi, *vlo;
    cudaGetSymbolAddress((void**)&qhi, g_qhi);
    cudaGetSymbolAddress((void**)&qlo, g_qlo);
    cudaGetSymbolAddress((void**)&khi, g_khi);
    cudaGetSymbolAddress((void**)&klo, g_klo);
    cudaGetSymbolAddress((void**)&vhi, g_vhi);
    cudaGetSymbolAddress((void**)&vlo, g_vlo);
    __nv_bfloat16 *wqh, *wql, *wkh, *wkl, *wvh, *wvl, *woh, *wol;
    cudaGetSymbolAddress((void**)&wqh, g_wqT_hi);
    cudaGetSymbolAddress((void**)&wql, g_wqT_lo);
    cudaGetSymbolAddress((void**)&wkh, g_wkT_hi);
    cudaGetSymbolAddress((void**)&wkl, g_wkT_lo);
    cudaGetSymbolAddress((void**)&wvh, g_wvT_hi);
    cudaGetSymbolAddress((void**)&wvl, g_wvT_lo);
    cudaGetSymbolAddress((void**)&woh, g_woT_hi);
    cudaGetSymbolAddress((void**)&wol, g_woT_lo);

    const int M = MTOT;       // 8192
    const int NKV = G_ * DH_; // 512

    rope_init_kernel<<<(S_ * ROT_ + 255) / 256, 256>>>();

    convert_split_kernel<<<(M * F_ / 4 + 255) / 256, 256>>>(x, xhi, xlo, M * F_ / 4);

    transpose_split_kernel<<<dim3(F_ / 32, F_ / 32), dim3(32, 8)>>>(wq, wqh, wql, F_, F_);
    transpose_split_kernel<<<dim3(NKV / 32, F_ / 32), dim3(32, 8)>>>(wk, wkh, wkl, F_, NKV);
    transpose_split_kernel<<<dim3(NKV / 32, F_ / 32), dim3(32, 8)>>>(wv, wvh, wvl, F_, NKV);
    transpose_split_kernel<<<dim3(F_ / 32, F_ / 32), dim3(32, 8)>>>(wo, woh, wol, F_, F_);

    cudaFuncSetAttribute(gemm_bf16x3_mma, cudaFuncAttributeMaxDynamicSharedMemorySize, SMEM_GEMM);

    // Q/K/V projections -> bf16 hi/lo (RoPE fused for Q,K; Q pre-scaled)
    gemm_bf16x3_mma<<<dim3(F_ / 128, M / 128), 256, SMEM_GEMM>>>(
        xhi, xlo, wqh, wql, bq, nullptr, qhi, qlo, M, F_, F_, 1);
    gemm_bf16x3_mma<<<dim3(NKV / 128, M / 128), 256, SMEM_GEMM>>>(
        xhi, xlo, wkh, wkl, bk, nullptr, khi, klo, M, NKV, F_, 2);
    gemm_bf16x3_mma<<<dim3(NKV / 128, M / 128), 256, SMEM_GEMM>>>(
        xhi, xlo, wvh, wvl, bv, nullptr, vhi, vlo, M, NKV, F_, 3);

    // Flash attention (tensor cores)
    cudaFuncSetAttribute(flash_mma_kernel, cudaFuncAttributeMaxDynamicSharedMemorySize, SMEM_FLASH);
    flash_mma_kernel<<<dim3(S_ / 128, H_, B_), 256, SMEM_FLASH>>>();

    // Output projection (fp32 out)
    gemm_bf16x3_mma<<<dim3(F_ / 128, M / 128), 256, SMEM_GEMM>>>(
        ahi, alo, woh, wol, bo, out, nullptr, nullptr, M, F_, F_, 0);
}

// round 8
// speedup vs baseline: 1.3558x; 1.3558x over previous
#include <cuda_runtime.h>
#include <cuda_fp16.h>
#include <cstdint>
#include <math.h>

// Problem constants
#define B_   4
#define S_   2048
#define F_   2048
#define H_   16
#define G_   4
#define DH_  128
#define ROT_ 32

#define MTOT (B_*S_)   // 8192
#define QSCALE 0.12751743f   // log2(e)/sqrt(128)

// ---------------------------------------------------------------------------
// Static scratch (fp16)
// ---------------------------------------------------------------------------
__device__ __align__(16) __half g_qhi[MTOT*F_];
__device__ __align__(16) __half g_qlo[MTOT*F_];
__device__ __align__(16) __half g_khi[MTOT*G_*DH_];
__device__ __align__(16) __half g_klo[MTOT*G_*DH_];
__device__ __align__(16) __half g_vhi[MTOT*G_*DH_];
__device__ __align__(16) __half g_vlo[MTOT*G_*DH_];
__device__ __align__(16) __half g_xhi[MTOT*F_];
__device__ __align__(16) __half g_ahi[MTOT*F_];
__device__ __align__(16) __half g_wqT_hi[F_*F_];
__device__ __align__(16) __half g_wqT_lo[F_*F_];
__device__ __align__(16) __half g_wkT_hi[G_*DH_*F_];
__device__ __align__(16) __half g_wkT_lo[G_*DH_*F_];
__device__ __align__(16) __half g_wvT_hi[G_*DH_*F_];
__device__ __align__(16) __half g_wvT_lo[G_*DH_*F_];
__device__ __align__(16) __half g_woT_hi[F_*F_];
__device__ __align__(16) __half g_woT_lo[F_*F_];
__device__ float g_cos[S_*ROT_];
__device__ float g_sin[S_*ROT_];

// ---------------------------------------------------------------------------
// Baseline-legal PTX helpers (sm_80+)
// ---------------------------------------------------------------------------
__device__ __forceinline__ uint32_t smem_u32(const void* p) {
    uint32_t a;
    asm("{ .reg .u64 t; cvta.to.shared.u64 t, %1; cvt.u32.u64 %0, t; }" : "=r"(a) : "l"(p));
    return a;
}
__device__ __forceinline__ void ldsm_x4(uint32_t* r, uint32_t addr) {
    asm volatile("ldmatrix.sync.aligned.m8n8.x4.shared.b16 {%0,%1,%2,%3}, [%4];"
                 : "=r"(r[0]), "=r"(r[1]), "=r"(r[2]), "=r"(r[3]) : "r"(addr));
}
__device__ __forceinline__ void ldsm_x4_t(uint32_t* r, uint32_t addr) {
    asm volatile("ldmatrix.sync.aligned.m8n8.x4.trans.shared.b16 {%0,%1,%2,%3}, [%4];"
                 : "=r"(r[0]), "=r"(r[1]), "=r"(r[2]), "=r"(r[3]) : "r"(addr));
}
__device__ __forceinline__ void mma_f16(float* c, const uint32_t* a, uint32_t b0, uint32_t b1) {
    asm volatile("mma.sync.aligned.m16n8k16.row.col.f32.f16.f16.f32 "
                 "{%0,%1,%2,%3}, {%4,%5,%6,%7}, {%8,%9}, {%0,%1,%2,%3};"
                 : "+f"(c[0]), "+f"(c[1]), "+f"(c[2]), "+f"(c[3])
                 : "r"(a[0]), "r"(a[1]), "r"(a[2]), "r"(a[3]), "r"(b0), "r"(b1));
}
#define CP_ASYNC16(dst, src) \
    asm volatile("cp.async.cg.shared.global [%0], [%1], 16;" :: "r"(dst), "l"(src) : "memory")
#define CP_COMMIT()  asm volatile("cp.async.commit_group;" ::: "memory")
#define CP_WAIT(n)   asm volatile("cp.async.wait_group %0;" :: "n"(n) : "memory")

__device__ __forceinline__ uint32_t pack_h2(float a, float b) {
    __half2 h = __floats2half2_rn(a, b);
    return *(uint32_t*)&h;
}

// ---------------------------------------------------------------------------
// RoPE table init
// ---------------------------------------------------------------------------
__global__ void rope_init_kernel() {
    int idx = blockIdx.x * blockDim.x + threadIdx.x;
    if (idx < S_ * ROT_) {
        int t = idx >> 5, p = idx & 31;
        double freq = pow(10000.0, -((double)(2 * p)) / 64.0);
        double f = (double)t * freq;
        g_cos[idx] = (float)cos(f);
        g_sin[idx] = (float)sin(f);
    }
}

// ---------------------------------------------------------------------------
// fp32 -> fp16 convert (x input; hi only — low part dropped by design)
// ---------------------------------------------------------------------------
__global__ void convert_x_kernel(const float* __restrict__ src,
                                 __half* __restrict__ hi, int n4) {
    int i = blockIdx.x * blockDim.x + threadIdx.x;
    if (i >= n4) return;
    float4 v = ((const float4*)src)[i];
    uint2 o;
    o.x = pack_h2(v.x, v.y);
    o.y = pack_h2(v.z, v.w);
    ((uint2*)hi)[i] = o;
}

// ---------------------------------------------------------------------------
// Weight transpose + split:  W[K][N] fp32 -> T[N][K] fp16 hi/lo
// ---------------------------------------------------------------------------
__global__ void transpose_split_kernel(const float* __restrict__ W,
                                       __half* __restrict__ Thi,
                                       __half* __restrict__ Tlo,
                                       int K, int N) {
    __shared__ float t[32][33];
    int k0 = blockIdx.y * 32, n0 = blockIdx.x * 32;
    int tx = threadIdx.x, ty = threadIdx.y;   // 32 x 8
#pragma unroll
    for (int j = 0; j < 4; j++)
        t[ty + j * 8][tx] = W[(size_t)(k0 + ty + j * 8) * N + n0 + tx];
    __syncthreads();
#pragma unroll
    for (int j = 0; j < 4; j++) {
        int n = n0 + ty + j * 8, k = k0 + tx;
        float v = t[tx][ty + j * 8];
        __half h = __float2half_rn(v);
        __half l = __float2half_rn(v - __half2float(h));
        Thi[(size_t)n * K + k] = h;
        Tlo[(size_t)n * K + k] = l;
    }
}

// ---------------------------------------------------------------------------
// HMMA fp16x2 GEMM: C = Ah[M,K] @ (Wh + Wl)[K,N] + bias.
// A-side: hi only. 2 MMAs per tile-pair. CTA 128x128, BK=32, 2-stage.
// 8 warps 2(M)x4(N), warp tile 64x32, 2 CTAs/SM.
// mode: 0 = fp32 out, 1 = Q (rope+scale, hi/lo out), 2 = K (rope, hi/lo),
// 3 = V (hi/lo), 4 = fp32 out no extras (unused).
// ---------------------------------------------------------------------------
#define GBK    32
#define TSTR   40                         // smem row stride in fp16 (80 B)
#define TILE_BYTES (128 * TSTR * 2)       // 10240
#define STAGE_BYTES (3 * TILE_BYTES)      // Ah, Bh, Bl = 30720
#define SMEM_GEMM (2 * STAGE_BYTES)       // 61440

__global__ __launch_bounds__(256, 2)
void gemm_f16x2_mma(const __half* __restrict__ Ahi,
                    const __half* __restrict__ BThi,
                    const __half* __restrict__ BTlo,
                    const float* __restrict__ bias,
                    float* __restrict__ C,
                    __half* __restrict__ Chi,
                    __half* __restrict__ Clo,
                    int M, int N, int K, int mode)
{
    extern __shared__ char smem[];
    const uint32_t smem_base = smem_u32(smem);

    const int tid = threadIdx.x;
    const int wid = tid >> 5;
    const int lid = tid & 31;
    const int warpM = wid & 1;
    const int warpN = wid >> 1;
    const size_t rowBase = (size_t)blockIdx.y * 128;
    const size_t colBase = (size_t)blockIdx.x * 128;

    const int NC = K / GBK;

    auto prefetch = [&](int stage, int k0) {
        uint32_t st = smem_base + stage * STAGE_BYTES;
#pragma unroll
        for (int t = 0; t < 2; t++) {
            int cidx = tid + t * 256;
            int r  = cidx >> 2;
            int ch = cidx & 3;
            uint32_t doff = r * (TSTR * 2) + ch * 16;
            size_t goffA = (rowBase + r) * (size_t)K + k0 + ch * 8;
            size_t goffB = (colBase + r) * (size_t)K + k0 + ch * 8;
            CP_ASYNC16(st + doff,                (const char*)(Ahi  + goffA));
            CP_ASYNC16(st + TILE_BYTES + doff,   (const char*)(BThi + goffB));
            CP_ASYNC16(st + 2*TILE_BYTES + doff, (const char*)(BTlo + goffB));
        }
        CP_COMMIT();
    };

    float acc[4][4][4];
#pragma unroll
    for (int i = 0; i < 4; i++)
#pragma unroll
        for (int j = 0; j < 4; j++)
#pragma unroll
            for (int q = 0; q < 4; q++) acc[i][j][q] = 0.f;

    const int laneRow = (lid & 7) + ((lid >> 3) & 1) * 8;
    const int laneK   = (lid >> 4) * 8;

    prefetch(0, 0);

    for (int kc = 0; kc < NC; ++kc) {
        const int s = kc & 1;
        if (kc + 1 < NC) prefetch(s ^ 1, (kc + 1) * GBK);
        if (kc + 1 < NC) { CP_WAIT(1); } else { CP_WAIT(0); }
        __syncthreads();

        const uint32_t st = smem_base + s * STAGE_BYTES;
        const uint32_t aHib = st;
        const uint32_t bHib = st + TILE_BYTES;
        const uint32_t bLob = st + 2*TILE_BYTES;

#pragma unroll
        for (int k16 = 0; k16 < GBK; k16 += 16) {
            const int kk = k16 + laneK;
            // B fragments (16 regs)
            uint32_t bH[2][4], bL[2][4];
#pragma unroll
            for (int nt = 0; nt < 2; nt++) {
                int row = warpN * 32 + nt * 16 + laneRow;
                uint32_t off = (row * TSTR + kk) * 2;
                ldsm_x4(bH[nt], bHib + off);
                ldsm_x4(bL[nt], bLob + off);
            }
            // A hi fragments streamed in mi-pairs
#pragma unroll
            for (int mp = 0; mp < 4; mp += 2) {
                uint32_t aH[2][4];
#pragma unroll
                for (int i = 0; i < 2; i++) {
                    int row = warpM * 64 + (mp + i) * 16 + laneRow;
                    uint32_t off = (row * TSTR + kk) * 2;
                    ldsm_x4(aH[i], aHib + off);
                }
                // pass 1: Ah*Bh — 8 distinct accumulators
#pragma unroll
                for (int i = 0; i < 2; i++)
#pragma unroll
                    for (int nt = 0; nt < 2; nt++) {
                        mma_f16(acc[mp+i][2*nt],   aH[i], bH[nt][0], bH[nt][2]);
                        mma_f16(acc[mp+i][2*nt+1], aH[i], bH[nt][1], bH[nt][3]);
                    }
                // pass 2: Ah*Bl
#pragma unroll
                for (int i = 0; i < 2; i++)
#pragma unroll
                    for (int nt = 0; nt < 2; nt++) {
                        mma_f16(acc[mp+i][2*nt],   aH[i], bL[nt][0], bL[nt][2]);
                        mma_f16(acc[mp+i][2*nt+1], aH[i], bL[nt][1], bL[nt][3]);
                    }
            }
        }
        __syncthreads();
    }

    // Epilogue
#pragma unroll
    for (int mi = 0; mi < 4; mi++) {
#pragma unroll
        for (int nj = 0; nj < 4; nj++) {
            int row0 = (int)rowBase + warpM * 64 + mi * 16 + (lid >> 2);
            int row1 = row0 + 8;
            int col  = (int)colBase + warpN * 32 + nj * 8 + (lid & 3) * 2;
            float b0 = __ldg(bias + col), b1 = __ldg(bias + col + 1);
            float v0 = acc[mi][nj][0] + b0, v1 = acc[mi][nj][1] + b1;
            float v2 = acc[mi][nj][2] + b0, v3 = acc[mi][nj][3] + b1;
            int d = col & (DH_ - 1);
            if (mode >= 1 && mode <= 2 && d < 64) {   // RoPE for Q,K
                int p = d >> 1;
                int s0 = row0 & (S_ - 1);
                int s1 = row1 & (S_ - 1);
                float c0 = g_cos[s0 * ROT_ + p], sn0 = g_sin[s0 * ROT_ + p];
                float c1 = g_cos[s1 * ROT_ + p], sn1 = g_sin[s1 * ROT_ + p];
                float a0 = v0, bb0 = v1, a1 = v2, bb1 = v3;
                v0 = a0 * c0 - bb0 * sn0;  v1 = bb0 * c0 + a0 * sn0;
                v2 = a1 * c1 - bb1 * sn1;  v3 = bb1 * c1 + a1 * sn1;
            }
            if (mode == 0) {
                *(float2*)(C + (size_t)row0 * N + col) = make_float2(v0, v1);
                *(float2*)(C + (size_t)row1 * N + col) = make_float2(v2, v3);
            } else {
                if (mode == 1) { v0 *= QSCALE; v1 *= QSCALE; v2 *= QSCALE; v3 *= QSCALE; }
                __half h00 = __float2half_rn(v0), h01 = __float2half_rn(v1);
                __half h10 = __float2half_rn(v2), h11 = __float2half_rn(v3);
                uint32_t hi0 = pack_h2(v0, v1);
                uint32_t lo0 = pack_h2(v0 - __half2float(h00), v1 - __half2float(h01));
                uint32_t hi1 = pack_h2(v2, v3);
                uint32_t lo1 = pack_h2(v2 - __half2float(h10), v3 - __half2float(h11));
                *(uint32_t*)(Chi + (size_t)row0 * N + col) = hi0;
                *(uint32_t*)(Clo + (size_t)row0 * N + col) = lo0;
                *(uint32_t*)(Chi + (size_t)row1 * N + col) = hi1;
                *(uint32_t*)(Clo + (size_t)row1 * N + col) = lo1;
            }
        }
    }
}

// ---------------------------------------------------------------------------
// Tensor-core flash attention (fp16 3-term, causal, GQA).
// CTA: 128 q rows x 64 kv cols per block. 8 warps x 16 q rows.
// ---------------------------------------------------------------------------
#define FSTR   272                 // bytes per smem row (128 fp16 + 8 pad)
#define FTILEB (64 * FSTR)         // 17408 bytes per 64-row tile
#define FQOFF  (8 * FTILEB)        // Q area after 2 KV stages
#define SMEM_FLASH (12 * FTILEB)   // 208896

__global__ __launch_bounds__(256)
void flash_mma_kernel()
{
    extern __shared__ char fsm[];
    const uint32_t sb = smem_u32(fsm);
    const int tid = threadIdx.x;
    const int wid = tid >> 5;
    const int lid = tid & 31;
    const int qb  = 15 - (int)blockIdx.x;   // big tiles first
    const int h   = blockIdx.y;
    const int b   = blockIdx.z;
    const int g   = h >> 2;
    const int qbase = qb * 128;

#pragma unroll
    for (int i = 0; i < 8; i++) {
        int q = tid + i * 256;
        int r = q >> 4, ch = q & 15;
        size_t off = (((size_t)(b * S_ + qbase + r)) * H_ + h) * DH_ + ch * 8;
        uint32_t dst = sb + FQOFF + (r >> 6) * FTILEB + (r & 63) * FSTR + ch * 16;
        CP_ASYNC16(dst,              (const char*)(g_qhi + off));
        CP_ASYNC16(dst + 2*FTILEB,   (const char*)(g_qlo + off));
    }
    CP_COMMIT();
    CP_WAIT(0);
    __syncthreads();

    auto prefetch = [&](int jblk, int stage) {
        uint32_t st = sb + stage * 4 * FTILEB;
        size_t base = (((size_t)(b * S_ + jblk * 64)) * G_ + g) * DH_;
#pragma unroll
        for (int i = 0; i < 4; i++) {
            int q = tid + i * 256;
            int r = q >> 4, ch = q & 15;
            size_t off = base + (size_t)r * (G_ * DH_) + ch * 8;
            uint32_t d = st + r * FSTR + ch * 16;
            CP_ASYNC16(d,              (const char*)(g_khi + off));
            CP_ASYNC16(d + FTILEB,     (const char*)(g_klo + off));
            CP_ASYNC16(d + 2*FTILEB,   (const char*)(g_vhi + off));
            CP_ASYNC16(d + 3*FTILEB,   (const char*)(g_vlo + off));
        }
        CP_COMMIT();
    };

    float O[16][4];
#pragma unroll
    for (int i = 0; i < 16; i++)
#pragma unroll
        for (int q = 0; q < 4; q++) O[i][q] = 0.f;
    float m2[2] = {-1e30f, -1e30f};
    float l2[2] = {0.f, 0.f};

    const int nblocks = 2 * (qb + 1);
    prefetch(0, 0);

    const int qrl = wid * 16 + (lid & 15);
    const uint32_t qaddrH = sb + FQOFF + (qrl >> 6) * FTILEB + (qrl & 63) * FSTR + (lid >> 4) * 16;
    const uint32_t lanebase = (lid & 15) * FSTR + (lid >> 4) * 16;
    const int warpRow0 = qbase + wid * 16;

    for (int j = 0; j < nblocks; j++) {
        const int st = j & 1;
        if (j + 1 < nblocks) { prefetch(j + 1, st ^ 1); CP_WAIT(1); }
        else                 { CP_WAIT(0); }
        __syncthreads();

        const uint32_t kH = sb + st * 4 * FTILEB + lanebase;

        float sacc[8][4];
#pragma unroll
        for (int nb = 0; nb < 8; nb++)
#pragma unroll
            for (int q = 0; q < 4; q++) sacc[nb][q] = 0.f;

#pragma unroll
        for (int kc = 0; kc < 8; kc++) {
            uint32_t qh[4], ql[4];
            ldsm_x4(qh, qaddrH + kc * 32);
            ldsm_x4(ql, qaddrH + 2*FTILEB + kc * 32);
#pragma unroll
            for (int n16 = 0; n16 < 4; n16++) {
                uint32_t rH[4], rL[4];
                ldsm_x4(rH, kH + n16 * (16 * FSTR) + kc * 32);
                ldsm_x4(rL, kH + FTILEB + n16 * (16 * FSTR) + kc * 32);
                mma_f16(sacc[2*n16],   qh, rH[0], rH[2]);
                mma_f16(sacc[2*n16],   qh, rL[0], rL[2]);
                mma_f16(sacc[2*n16],   ql, rH[0], rH[2]);
                mma_f16(sacc[2*n16+1], qh, rH[1], rH[3]);
                mma_f16(sacc[2*n16+1], qh, rL[1], rL[3]);
                mma_f16(sacc[2*n16+1], ql, rH[1], rH[3]);
            }
        }

        if (j * 64 + 63 > warpRow0) {
#pragma unroll
            for (int nb = 0; nb < 8; nb++)
#pragma unroll
                for (int q = 0; q < 4; q++) {
                    int col = j * 64 + nb * 8 + (lid & 3) * 2 + (q & 1);
                    int row = warpRow0 + (lid >> 2) + (q >> 1) * 8;
                    if (col > row) sacc[nb][q] = -1e30f;
                }
        }

#pragma unroll
        for (int rh = 0; rh < 2; rh++) {
            float rmax = -1e30f;
#pragma unroll
            for (int nb = 0; nb < 8; nb++)
                rmax = fmaxf(rmax, fmaxf(sacc[nb][rh*2], sacc[nb][rh*2+1]));
            rmax = fmaxf(rmax, __shfl_xor_sync(0xffffffffu, rmax, 1));
            rmax = fmaxf(rmax, __shfl_xor_sync(0xffffffffu, rmax, 2));
            float mnew = fmaxf(m2[rh], rmax);
            float alpha = exp2f(m2[rh] - mnew);
            float rsum = 0.f;
#pragma unroll
            for (int nb = 0; nb < 8; nb++) {
                float p0 = exp2f(sacc[nb][rh*2]   - mnew);
                float p1 = exp2f(sacc[nb][rh*2+1] - mnew);
                sacc[nb][rh*2] = p0; sacc[nb][rh*2+1] = p1;
                rsum += p0 + p1;
            }
            rsum += __shfl_xor_sync(0xffffffffu, rsum, 1);
            rsum += __shfl_xor_sync(0xffffffffu, rsum, 2);
            l2[rh] = l2[rh] * alpha + rsum;
            m2[rh] = mnew;
#pragma unroll
            for (int nb = 0; nb < 16; nb++) {
                O[nb][rh*2]   *= alpha;
                O[nb][rh*2+1] *= alpha;
            }
        }

        uint32_t ph[4][4], pl[4][4];
#pragma unroll
        for (int kc = 0; kc < 4; kc++)
#pragma unroll
            for (int t = 0; t < 4; t++) {
                int nb = 2*kc + (t >> 1);
                float p0 = sacc[nb][(t & 1) * 2];
                float p1 = sacc[nb][(t & 1) * 2 + 1];
                __half hp0 = __float2half_rn(p0), hp1 = __float2half_rn(p1);
                ph[kc][t] = pack_h2(p0, p1);
                pl[kc][t] = pack_h2(p0 - __half2float(hp0), p1 - __half2float(hp1));
            }

        const uint32_t vbase = sb + st * 4 * FTILEB + 2*FTILEB + lanebase;
#pragma unroll
        for (int kc = 0; kc < 4; kc++) {
            uint32_t vrow = vbase + kc * (16 * FSTR);
#pragma unroll
            for (int ng = 0; ng < 8; ng++) {
                uint32_t vh[4], vl[4];
                ldsm_x4_t(vh, vrow + ng * 32);
                ldsm_x4_t(vl, vrow + FTILEB + ng * 32);
                mma_f16(O[2*ng],   ph[kc], vh[0], vh[1]);
                mma_f16(O[2*ng],   ph[kc], vl[0], vl[1]);
                mma_f16(O[2*ng],   pl[kc], vh[0], vh[1]);
                mma_f16(O[2*ng+1], ph[kc], vh[2], vh[3]);
                mma_f16(O[2*ng+1], ph[kc], vl[2], vl[3]);
                mma_f16(O[2*ng+1], pl[kc], vh[2], vh[3]);
            }
        }
        __syncthreads();
    }

    // Epilogue: normalize, write fp16 hi only (O-projection uses A-hi only)
    const float inv0 = 1.f / l2[0];
    const float inv1 = 1.f / l2[1];
    const int r0 = qbase + wid * 16 + (lid >> 2);
#pragma unroll
    for (int nb = 0; nb < 16; nb++) {
        int col = h * DH_ + nb * 8 + (lid & 3) * 2;
        size_t base0 = ((size_t)(b * S_ + r0)) * F_ + col;
        size_t base1 = ((size_t)(b * S_ + r0 + 8)) * F_ + col;
        *(uint32_t*)(g_ahi + base0) = pack_h2(O[nb][0] * inv0, O[nb][1] * inv0);
        *(uint32_t*)(g_ahi + base1) = pack_h2(O[nb][2] * inv1, O[nb][3] * inv1);
    }
}

// ---------------------------------------------------------------------------
extern "C" void kernel_launch(void* const* d_in, const int* in_sizes, int n_in,
                              void* d_out, int out_size)
{
    const float* x  = (const float*)d_in[0];
    const float* wq = (const float*)d_in[1];
    const float* bq = (const float*)d_in[2];
    const float* wk = (const float*)d_in[3];
    const float* bk = (const float*)d_in[4];
    const float* wv = (const float*)d_in[5];
    const float* bv = (const float*)d_in[6];
    const float* wo = (const float*)d_in[7];
    const float* bo = (const float*)d_in[8];
    float* out = (float*)d_out;

    __half *xhi, *ahi;
    cudaGetSymbolAddress((void**)&xhi, g_xhi);
    cudaGetSymbolAddress((void**)&ahi, g_ahi);
    __half *qhi, *qlo, *khi, *klo, *vhi, *vlo;
    cudaGetSymbolAddress((void**)&qhi, g_qhi);
    cudaGetSymbolAddress((void**)&qlo, g_qlo);
    cudaGetSymbolAddress((void**)&khi, g_khi);
    cudaGetSymbolAddress((void**)&klo, g_klo);
    cudaGetSymbolAddress((void**)&vhi, g_vhi);
    cudaGetSymbolAddress((void**)&vlo, g_vlo);
    __half *wqh, *wql, *wkh, *wkl, *wvh, *wvl, *woh, *wol;
    cudaGetSymbolAddress((void**)&wqh, g_wqT_hi);
    cudaGetSymbolAddress((void**)&wql, g_wqT_lo);
    cudaGetSymbolAddress((void**)&wkh, g_wkT_hi);
    cudaGetSymbolAddress((void**)&wkl, g_wkT_lo);
    cudaGetSymbolAddress((void**)&wvh, g_wvT_hi);
    cudaGetSymbolAddress((void**)&wvl, g_wvT_lo);
    cudaGetSymbolAddress((void**)&woh, g_woT_hi);
    cudaGetSymbolAddress((void**)&wol, g_woT_lo);

    const int M = MTOT;       // 8192
    const int NKV = G_ * DH_; // 512

    rope_init_kernel<<<(S_ * ROT_ + 255) / 256, 256>>>();

    convert_x_kernel<<<(M * F_ / 4 + 255) / 256, 256>>>(x, xhi, M * F_ / 4);

    transpose_split_kernel<<<dim3(F_ / 32, F_ / 32), dim3(32, 8)>>>(wq, wqh, wql, F_, F_);
    transpose_split_kernel<<<dim3(NKV / 32, F_ / 32), dim3(32, 8)>>>(wk, wkh, wkl, F_, NKV);
    transpose_split_kernel<<<dim3(NKV / 32, F_ / 32), dim3(32, 8)>>>(wv, wvh, wvl, F_, NKV);
    transpose_split_kernel<<<dim3(F_ / 32, F_ / 32), dim3(32, 8)>>>(wo, woh, wol, F_, F_);

    cudaFuncSetAttribute(gemm_f16x2_mma, cudaFuncAttributeMaxDynamicSharedMemorySize, SMEM_GEMM);

    // Q/K/V projections -> fp16 hi/lo (RoPE fused for Q,K; Q pre-scaled)
    gemm_f16x2_mma<<<dim3(F_ / 128, M / 128), 256, SMEM_GEMM>>>(
        xhi, wqh, wql, bq, nullptr, qhi, qlo, M, F_, F_, 1);
    gemm_f16x2_mma<<<dim3(NKV / 128, M / 128), 256, SMEM_GEMM>>>(
        xhi, wkh, wkl, bk, nullptr, khi, klo, M, NKV, F_, 2);
    gemm_f16x2_mma<<<dim3(NKV / 128, M / 128), 256, SMEM_GEMM>>>(
        xhi, wvh, wvl, bv, nullptr, vhi, vlo, M, NKV, F_, 3);

    // Flash attention (tensor cores, fp16 3-term)
    cudaFuncSetAttribute(flash_mma_kernel, cudaFuncAttributeMaxDynamicSharedMemorySize, SMEM_FLASH);
    flash_mma_kernel<<<dim3(S_ / 128, H_, B_), 256, SMEM_FLASH>>>();

    // Output projection (fp32 out)
    gemm_f16x2_mma<<<dim3(F_ / 128, M / 128), 256, SMEM_GEMM>>>(
        ahi, woh, wol, bo, out, nullptr, nullptr, M, F_, F_, 0);
}

// round 9
// speedup vs baseline: 1.4419x; 1.0636x over previous
#include <cuda_runtime.h>
#include <cuda_fp16.h>
#include <cstdint>
#include <math.h>

// Problem constants
#define B_   4
#define S_   2048
#define F_   2048
#define H_   16
#define G_   4
#define DH_  128
#define ROT_ 32

#define MTOT (B_*S_)   // 8192
#define QSCALE 0.12751743f   // log2(e)/sqrt(128)

// ---------------------------------------------------------------------------
// Static scratch (fp16)
// ---------------------------------------------------------------------------
__device__ __align__(16) __half g_qhi[MTOT*F_];
__device__ __align__(16) __half g_khi[MTOT*G_*DH_];
__device__ __align__(16) __half g_klo[MTOT*G_*DH_];
__device__ __align__(16) __half g_vhi[MTOT*G_*DH_];
__device__ __align__(16) __half g_vlo[MTOT*G_*DH_];
__device__ __align__(16) __half g_xhi[MTOT*F_];
__device__ __align__(16) __half g_ahi[MTOT*F_];
__device__ __align__(16) __half g_wqT_hi[F_*F_];
__device__ __align__(16) __half g_wqT_lo[F_*F_];
__device__ __align__(16) __half g_wkT_hi[G_*DH_*F_];
__device__ __align__(16) __half g_wkT_lo[G_*DH_*F_];
__device__ __align__(16) __half g_wvT_hi[G_*DH_*F_];
__device__ __align__(16) __half g_wvT_lo[G_*DH_*F_];
__device__ __align__(16) __half g_woT_hi[F_*F_];
__device__ __align__(16) __half g_woT_lo[F_*F_];
__device__ float g_cos[S_*ROT_];
__device__ float g_sin[S_*ROT_];

// ---------------------------------------------------------------------------
// Baseline-legal PTX helpers (sm_80+)
// ---------------------------------------------------------------------------
__device__ __forceinline__ uint32_t smem_u32(const void* p) {
    uint32_t a;
    asm("{ .reg .u64 t; cvta.to.shared.u64 t, %1; cvt.u32.u64 %0, t; }" : "=r"(a) : "l"(p));
    return a;
}
__device__ __forceinline__ void ldsm_x4(uint32_t* r, uint32_t addr) {
    asm volatile("ldmatrix.sync.aligned.m8n8.x4.shared.b16 {%0,%1,%2,%3}, [%4];"
                 : "=r"(r[0]), "=r"(r[1]), "=r"(r[2]), "=r"(r[3]) : "r"(addr));
}
__device__ __forceinline__ void ldsm_x4_t(uint32_t* r, uint32_t addr) {
    asm volatile("ldmatrix.sync.aligned.m8n8.x4.trans.shared.b16 {%0,%1,%2,%3}, [%4];"
                 : "=r"(r[0]), "=r"(r[1]), "=r"(r[2]), "=r"(r[3]) : "r"(addr));
}
__device__ __forceinline__ void mma_f16(float* c, const uint32_t* a, uint32_t b0, uint32_t b1) {
    asm volatile("mma.sync.aligned.m16n8k16.row.col.f32.f16.f16.f32 "
                 "{%0,%1,%2,%3}, {%4,%5,%6,%7}, {%8,%9}, {%0,%1,%2,%3};"
                 : "+f"(c[0]), "+f"(c[1]), "+f"(c[2]), "+f"(c[3])
                 : "r"(a[0]), "r"(a[1]), "r"(a[2]), "r"(a[3]), "r"(b0), "r"(b1));
}
#define CP_ASYNC16(dst, src) \
    asm volatile("cp.async.cg.shared.global [%0], [%1], 16;" :: "r"(dst), "l"(src) : "memory")
#define CP_COMMIT()  asm volatile("cp.async.commit_group;" ::: "memory")
#define CP_WAIT(n)   asm volatile("cp.async.wait_group %0;" :: "n"(n) : "memory")

__device__ __forceinline__ uint32_t pack_h2(float a, float b) {
    __half2 h = __floats2half2_rn(a, b);
    return *(uint32_t*)&h;
}

// ---------------------------------------------------------------------------
// RoPE table init
// ---------------------------------------------------------------------------
__global__ void rope_init_kernel() {
    int idx = blockIdx.x * blockDim.x + threadIdx.x;
    if (idx < S_ * ROT_) {
        int t = idx >> 5, p = idx & 31;
        double freq = pow(10000.0, -((double)(2 * p)) / 64.0);
        double f = (double)t * freq;
        g_cos[idx] = (float)cos(f);
        g_sin[idx] = (float)sin(f);
    }
}

// ---------------------------------------------------------------------------
// fp32 -> fp16 convert (x input; hi only)
// ---------------------------------------------------------------------------
__global__ void convert_x_kernel(const float* __restrict__ src,
                                 __half* __restrict__ hi, int n4) {
    int i = blockIdx.x * blockDim.x + threadIdx.x;
    if (i >= n4) return;
    float4 v = ((const float4*)src)[i];
    uint2 o;
    o.x = pack_h2(v.x, v.y);
    o.y = pack_h2(v.z, v.w);
    ((uint2*)hi)[i] = o;
}

// ---------------------------------------------------------------------------
// Weight transpose + split:  W[K][N] fp32 -> T[N][K] fp16 hi/lo
// ---------------------------------------------------------------------------
__global__ void transpose_split_kernel(const float* __restrict__ W,
                                       __half* __restrict__ Thi,
                                       __half* __restrict__ Tlo,
                                       int K, int N) {
    __shared__ float t[32][33];
    int k0 = blockIdx.y * 32, n0 = blockIdx.x * 32;
    int tx = threadIdx.x, ty = threadIdx.y;   // 32 x 8
#pragma unroll
    for (int j = 0; j < 4; j++)
        t[ty + j * 8][tx] = W[(size_t)(k0 + ty + j * 8) * N + n0 + tx];
    __syncthreads();
#pragma unroll
    for (int j = 0; j < 4; j++) {
        int n = n0 + ty + j * 8, k = k0 + tx;
        float v = t[tx][ty + j * 8];
        __half h = __float2half_rn(v);
        __half l = __float2half_rn(v - __half2float(h));
        Thi[(size_t)n * K + k] = h;
        Tlo[(size_t)n * K + k] = l;
    }
}

// ---------------------------------------------------------------------------
// HMMA fp16x2 GEMM: C = Ah[M,K] @ (Wh + Wl)[K,N] + bias.
// mode: 0 = fp32 out, 1 = Q (rope+scale, hi only), 2 = K (rope, hi/lo), 3 = V (hi/lo).
// ---------------------------------------------------------------------------
#define GBK    32
#define TSTR   40                         // smem row stride in fp16 (80 B)
#define TILE_BYTES (128 * TSTR * 2)       // 10240
#define STAGE_BYTES (3 * TILE_BYTES)      // Ah, Bh, Bl = 30720
#define SMEM_GEMM (2 * STAGE_BYTES)       // 61440

__global__ __launch_bounds__(256, 2)
void gemm_f16x2_mma(const __half* __restrict__ Ahi,
                    const __half* __restrict__ BThi,
                    const __half* __restrict__ BTlo,
                    const float* __restrict__ bias,
                    float* __restrict__ C,
                    __half* __restrict__ Chi,
                    __half* __restrict__ Clo,
                    int M, int N, int K, int mode)
{
    extern __shared__ char smem[];
    const uint32_t smem_base = smem_u32(smem);

    const int tid = threadIdx.x;
    const int wid = tid >> 5;
    const int lid = tid & 31;
    const int warpM = wid & 1;
    const int warpN = wid >> 1;
    const size_t rowBase = (size_t)blockIdx.y * 128;
    const size_t colBase = (size_t)blockIdx.x * 128;

    const int NC = K / GBK;

    auto prefetch = [&](int stage, int k0) {
        uint32_t st = smem_base + stage * STAGE_BYTES;
#pragma unroll
        for (int t = 0; t < 2; t++) {
            int cidx = tid + t * 256;
            int r  = cidx >> 2;
            int ch = cidx & 3;
            uint32_t doff = r * (TSTR * 2) + ch * 16;
            size_t goffA = (rowBase + r) * (size_t)K + k0 + ch * 8;
            size_t goffB = (colBase + r) * (size_t)K + k0 + ch * 8;
            CP_ASYNC16(st + doff,                (const char*)(Ahi  + goffA));
            CP_ASYNC16(st + TILE_BYTES + doff,   (const char*)(BThi + goffB));
            CP_ASYNC16(st + 2*TILE_BYTES + doff, (const char*)(BTlo + goffB));
        }
        CP_COMMIT();
    };

    float acc[4][4][4];
#pragma unroll
    for (int i = 0; i < 4; i++)
#pragma unroll
        for (int j = 0; j < 4; j++)
#pragma unroll
            for (int q = 0; q < 4; q++) acc[i][j][q] = 0.f;

    const int laneRow = (lid & 7) + ((lid >> 3) & 1) * 8;
    const int laneK   = (lid >> 4) * 8;

    prefetch(0, 0);

    for (int kc = 0; kc < NC; ++kc) {
        const int s = kc & 1;
        if (kc + 1 < NC) prefetch(s ^ 1, (kc + 1) * GBK);
        if (kc + 1 < NC) { CP_WAIT(1); } else { CP_WAIT(0); }
        __syncthreads();

        const uint32_t st = smem_base + s * STAGE_BYTES;
        const uint32_t aHib = st;
        const uint32_t bHib = st + TILE_BYTES;
        const uint32_t bLob = st + 2*TILE_BYTES;

#pragma unroll
        for (int k16 = 0; k16 < GBK; k16 += 16) {
            const int kk = k16 + laneK;
            uint32_t bH[2][4], bL[2][4];
#pragma unroll
            for (int nt = 0; nt < 2; nt++) {
                int row = warpN * 32 + nt * 16 + laneRow;
                uint32_t off = (row * TSTR + kk) * 2;
                ldsm_x4(bH[nt], bHib + off);
                ldsm_x4(bL[nt], bLob + off);
            }
#pragma unroll
            for (int mp = 0; mp < 4; mp += 2) {
                uint32_t aH[2][4];
#pragma unroll
                for (int i = 0; i < 2; i++) {
                    int row = warpM * 64 + (mp + i) * 16 + laneRow;
                    uint32_t off = (row * TSTR + kk) * 2;
                    ldsm_x4(aH[i], aHib + off);
                }
#pragma unroll
                for (int i = 0; i < 2; i++)
#pragma unroll
                    for (int nt = 0; nt < 2; nt++) {
                        mma_f16(acc[mp+i][2*nt],   aH[i], bH[nt][0], bH[nt][2]);
                        mma_f16(acc[mp+i][2*nt+1], aH[i], bH[nt][1], bH[nt][3]);
                    }
#pragma unroll
                for (int i = 0; i < 2; i++)
#pragma unroll
                    for (int nt = 0; nt < 2; nt++) {
                        mma_f16(acc[mp+i][2*nt],   aH[i], bL[nt][0], bL[nt][2]);
                        mma_f16(acc[mp+i][2*nt+1], aH[i], bL[nt][1], bL[nt][3]);
                    }
            }
        }
        __syncthreads();
    }

    // Epilogue
#pragma unroll
    for (int mi = 0; mi < 4; mi++) {
#pragma unroll
        for (int nj = 0; nj < 4; nj++) {
            int row0 = (int)rowBase + warpM * 64 + mi * 16 + (lid >> 2);
            int row1 = row0 + 8;
            int col  = (int)colBase + warpN * 32 + nj * 8 + (lid & 3) * 2;
            float b0 = __ldg(bias + col), b1 = __ldg(bias + col + 1);
            float v0 = acc[mi][nj][0] + b0, v1 = acc[mi][nj][1] + b1;
            float v2 = acc[mi][nj][2] + b0, v3 = acc[mi][nj][3] + b1;
            int d = col & (DH_ - 1);
            if (mode >= 1 && mode <= 2 && d < 64) {   // RoPE for Q,K
                int p = d >> 1;
                int s0 = row0 & (S_ - 1);
                int s1 = row1 & (S_ - 1);
                float c0 = g_cos[s0 * ROT_ + p], sn0 = g_sin[s0 * ROT_ + p];
                float c1 = g_cos[s1 * ROT_ + p], sn1 = g_sin[s1 * ROT_ + p];
                float a0 = v0, bb0 = v1, a1 = v2, bb1 = v3;
                v0 = a0 * c0 - bb0 * sn0;  v1 = bb0 * c0 + a0 * sn0;
                v2 = a1 * c1 - bb1 * sn1;  v3 = bb1 * c1 + a1 * sn1;
            }
            if (mode == 0) {
                *(float2*)(C + (size_t)row0 * N + col) = make_float2(v0, v1);
                *(float2*)(C + (size_t)row1 * N + col) = make_float2(v2, v3);
            } else if (mode == 1) {
                v0 *= QSCALE; v1 *= QSCALE; v2 *= QSCALE; v3 *= QSCALE;
                *(uint32_t*)(Chi + (size_t)row0 * N + col) = pack_h2(v0, v1);
                *(uint32_t*)(Chi + (size_t)row1 * N + col) = pack_h2(v2, v3);
            } else {
                __half h00 = __float2half_rn(v0), h01 = __float2half_rn(v1);
                __half h10 = __float2half_rn(v2), h11 = __float2half_rn(v3);
                *(uint32_t*)(Chi + (size_t)row0 * N + col) = pack_h2(v0, v1);
                *(uint32_t*)(Clo + (size_t)row0 * N + col) =
                    pack_h2(v0 - __half2float(h00), v1 - __half2float(h01));
                *(uint32_t*)(Chi + (size_t)row1 * N + col) = pack_h2(v2, v3);
                *(uint32_t*)(Clo + (size_t)row1 * N + col) =
                    pack_h2(v2 - __half2float(h10), v3 - __half2float(h11));
            }
        }
    }
}

// ---------------------------------------------------------------------------
// Tensor-core flash attention (fp16 2-term, causal, GQA).
// Scores: q_hi·(k_hi + k_lo).  PV: p_hi·(v_hi + v_lo).
// CTA: 128 q rows x 64 kv cols per block. 8 warps x 16 q rows.
// ---------------------------------------------------------------------------
#define FSTR   272                 // bytes per smem row (128 fp16 + 8 pad)
#define FTILEB (64 * FSTR)         // 17408 bytes per 64-row tile
#define FQOFF  (8 * FTILEB)        // Q (hi only) after 2 KV stages
#define SMEM_FLASH (10 * FTILEB)   // 174080

__global__ __launch_bounds__(256)
void flash_mma_kernel()
{
    extern __shared__ char fsm[];
    const uint32_t sb = smem_u32(fsm);
    const int tid = threadIdx.x;
    const int wid = tid >> 5;
    const int lid = tid & 31;
    const int qb  = 15 - (int)blockIdx.x;   // big tiles first
    const int h   = blockIdx.y;
    const int b   = blockIdx.z;
    const int g   = h >> 2;
    const int qbase = qb * 128;

    // Q hi only: 128 rows x 128 fp16 = 2048 16B chunks
#pragma unroll
    for (int i = 0; i < 8; i++) {
        int q = tid + i * 256;
        int r = q >> 4, ch = q & 15;
        size_t off = (((size_t)(b * S_ + qbase + r)) * H_ + h) * DH_ + ch * 8;
        uint32_t dst = sb + FQOFF + (r >> 6) * FTILEB + (r & 63) * FSTR + ch * 16;
        CP_ASYNC16(dst, (const char*)(g_qhi + off));
    }
    CP_COMMIT();
    CP_WAIT(0);
    __syncthreads();

    auto prefetch = [&](int jblk, int stage) {
        uint32_t st = sb + stage * 4 * FTILEB;
        size_t base = (((size_t)(b * S_ + jblk * 64)) * G_ + g) * DH_;
#pragma unroll
        for (int i = 0; i < 4; i++) {
            int q = tid + i * 256;
            int r = q >> 4, ch = q & 15;
            size_t off = base + (size_t)r * (G_ * DH_) + ch * 8;
            uint32_t d = st + r * FSTR + ch * 16;
            CP_ASYNC16(d,              (const char*)(g_khi + off));
            CP_ASYNC16(d + FTILEB,     (const char*)(g_klo + off));
            CP_ASYNC16(d + 2*FTILEB,   (const char*)(g_vhi + off));
            CP_ASYNC16(d + 3*FTILEB,   (const char*)(g_vlo + off));
        }
        CP_COMMIT();
    };

    float O[16][4];
#pragma unroll
    for (int i = 0; i < 16; i++)
#pragma unroll
        for (int q = 0; q < 4; q++) O[i][q] = 0.f;
    float m2[2] = {-1e30f, -1e30f};
    float l2[2] = {0.f, 0.f};

    const int nblocks = 2 * (qb + 1);
    prefetch(0, 0);

    const int qrl = wid * 16 + (lid & 15);
    const uint32_t qaddrH = sb + FQOFF + (qrl >> 6) * FTILEB + (qrl & 63) * FSTR + (lid >> 4) * 16;
    const uint32_t lanebase = (lid & 15) * FSTR + (lid >> 4) * 16;
    const int warpRow0 = qbase + wid * 16;

    for (int j = 0; j < nblocks; j++) {
        const int st = j & 1;
        if (j + 1 < nblocks) { prefetch(j + 1, st ^ 1); CP_WAIT(1); }
        else                 { CP_WAIT(0); }
        __syncthreads();

        const uint32_t kH = sb + st * 4 * FTILEB + lanebase;

        float sacc[8][4];
#pragma unroll
        for (int nb = 0; nb < 8; nb++)
#pragma unroll
            for (int q = 0; q < 4; q++) sacc[nb][q] = 0.f;

#pragma unroll
        for (int kc = 0; kc < 8; kc++) {
            uint32_t qh[4];
            ldsm_x4(qh, qaddrH + kc * 32);
#pragma unroll
            for (int n16 = 0; n16 < 4; n16++) {
                uint32_t rH[4], rL[4];
                ldsm_x4(rH, kH + n16 * (16 * FSTR) + kc * 32);
                ldsm_x4(rL, kH + FTILEB + n16 * (16 * FSTR) + kc * 32);
                mma_f16(sacc[2*n16],   qh, rH[0], rH[2]);
                mma_f16(sacc[2*n16+1], qh, rH[1], rH[3]);
                mma_f16(sacc[2*n16],   qh, rL[0], rL[2]);
                mma_f16(sacc[2*n16+1], qh, rL[1], rL[3]);
            }
        }

        if (j * 64 + 63 > warpRow0) {
#pragma unroll
            for (int nb = 0; nb < 8; nb++)
#pragma unroll
                for (int q = 0; q < 4; q++) {
                    int col = j * 64 + nb * 8 + (lid & 3) * 2 + (q & 1);
                    int row = warpRow0 + (lid >> 2) + (q >> 1) * 8;
                    if (col > row) sacc[nb][q] = -1e30f;
                }
        }

#pragma unroll
        for (int rh = 0; rh < 2; rh++) {
            float rmax = -1e30f;
#pragma unroll
            for (int nb = 0; nb < 8; nb++)
                rmax = fmaxf(rmax, fmaxf(sacc[nb][rh*2], sacc[nb][rh*2+1]));
            rmax = fmaxf(rmax, __shfl_xor_sync(0xffffffffu, rmax, 1));
            rmax = fmaxf(rmax, __shfl_xor_sync(0xffffffffu, rmax, 2));
            float mnew = fmaxf(m2[rh], rmax);
            float alpha = exp2f(m2[rh] - mnew);
            float rsum = 0.f;
#pragma unroll
            for (int nb = 0; nb < 8; nb++) {
                float p0 = exp2f(sacc[nb][rh*2]   - mnew);
                float p1 = exp2f(sacc[nb][rh*2+1] - mnew);
                sacc[nb][rh*2] = p0; sacc[nb][rh*2+1] = p1;
                rsum += p0 + p1;
            }
            rsum += __shfl_xor_sync(0xffffffffu, rsum, 1);
            rsum += __shfl_xor_sync(0xffffffffu, rsum, 2);
            l2[rh] = l2[rh] * alpha + rsum;
            m2[rh] = mnew;
#pragma unroll
            for (int nb = 0; nb < 16; nb++) {
                O[nb][rh*2]   *= alpha;
                O[nb][rh*2+1] *= alpha;
            }
        }

        // P hi fragments only
        uint32_t ph[4][4];
#pragma unroll
        for (int kc = 0; kc < 4; kc++)
#pragma unroll
            for (int t = 0; t < 4; t++) {
                int nb = 2*kc + (t >> 1);
                ph[kc][t] = pack_h2(sacc[nb][(t & 1) * 2], sacc[nb][(t & 1) * 2 + 1]);
            }

        const uint32_t vbase = sb + st * 4 * FTILEB + 2*FTILEB + lanebase;
#pragma unroll
        for (int kc = 0; kc < 4; kc++) {
            uint32_t vrow = vbase + kc * (16 * FSTR);
#pragma unroll
            for (int ng = 0; ng < 8; ng++) {
                uint32_t vh[4], vl[4];
                ldsm_x4_t(vh, vrow + ng * 32);
                ldsm_x4_t(vl, vrow + FTILEB + ng * 32);
                mma_f16(O[2*ng],   ph[kc], vh[0], vh[1]);
                mma_f16(O[2*ng+1], ph[kc], vh[2], vh[3]);
                mma_f16(O[2*ng],   ph[kc], vl[0], vl[1]);
                mma_f16(O[2*ng+1], ph[kc], vl[2], vl[3]);
            }
        }
        __syncthreads();
    }

    // Epilogue: normalize, write fp16 hi
    const float inv0 = 1.f / l2[0];
    const float inv1 = 1.f / l2[1];
    const int r0 = qbase + wid * 16 + (lid >> 2);
#pragma unroll
    for (int nb = 0; nb < 16; nb++) {
        int col = h * DH_ + nb * 8 + (lid & 3) * 2;
        size_t base0 = ((size_t)(b * S_ + r0)) * F_ + col;
        size_t base1 = ((size_t)(b * S_ + r0 + 8)) * F_ + col;
        *(uint32_t*)(g_ahi + base0) = pack_h2(O[nb][0] * inv0, O[nb][1] * inv0);
        *(uint32_t*)(g_ahi + base1) = pack_h2(O[nb][2] * inv1, O[nb][3] * inv1);
    }
}

// ---------------------------------------------------------------------------
extern "C" void kernel_launch(void* const* d_in, const int* in_sizes, int n_in,
                              void* d_out, int out_size)
{
    const float* x  = (const float*)d_in[0];
    const float* wq = (const float*)d_in[1];
    const float* bq = (const float*)d_in[2];
    const float* wk = (const float*)d_in[3];
    const float* bk = (const float*)d_in[4];
    const float* wv = (const float*)d_in[5];
    const float* bv = (const float*)d_in[6];
    const float* wo = (const float*)d_in[7];
    const float* bo = (const float*)d_in[8];
    float* out = (float*)d_out;

    __half *xhi, *ahi;
    cudaGetSymbolAddress((void**)&xhi, g_xhi);
    cudaGetSymbolAddress((void**)&ahi, g_ahi);
    __half *qhi, *khi, *klo, *vhi, *vlo;
    cudaGetSymbolAddress((void**)&qhi, g_qhi);
    cudaGetSymbolAddress((void**)&khi, g_khi);
    cudaGetSymbolAddress((void**)&klo, g_klo);
    cudaGetSymbolAddress((void**)&vhi, g_vhi);
    cudaGetSymbolAddress((void**)&vlo, g_vlo);
    __half *wqh, *wql, *wkh, *wkl, *wvh, *wvl, *woh, *wol;
    cudaGetSymbolAddress((void**)&wqh, g_wqT_hi);
    cudaGetSymbolAddress((void**)&wql, g_wqT_lo);
    cudaGetSymbolAddress((void**)&wkh, g_wkT_hi);
    cudaGetSymbolAddress((void**)&wkl, g_wkT_lo);
    cudaGetSymbolAddress((void**)&wvh, g_wvT_hi);
    cudaGetSymbolAddress((void**)&wvl, g_wvT_lo);
    cudaGetSymbolAddress((void**)&woh, g_woT_hi);
    cudaGetSymbolAddress((void**)&wol, g_woT_lo);

    const int M = MTOT;       // 8192
    const int NKV = G_ * DH_; // 512

    rope_init_kernel<<<(S_ * ROT_ + 255) / 256, 256>>>();

    convert_x_kernel<<<(M * F_ / 4 + 255) / 256, 256>>>(x, xhi, M * F_ / 4);

    transpose_split_kernel<<<dim3(F_ / 32, F_ / 32), dim3(32, 8)>>>(wq, wqh, wql, F_, F_);
    transpose_split_kernel<<<dim3(NKV / 32, F_ / 32), dim3(32, 8)>>>(wk, wkh, wkl, F_, NKV);
    transpose_split_kernel<<<dim3(NKV / 32, F_ / 32), dim3(32, 8)>>>(wv, wvh, wvl, F_, NKV);
    transpose_split_kernel<<<dim3(F_ / 32, F_ / 32), dim3(32, 8)>>>(wo, woh, wol, F_, F_);

    cudaFuncSetAttribute(gemm_f16x2_mma, cudaFuncAttributeMaxDynamicSharedMemorySize, SMEM_GEMM);

    // Q/K/V projections (RoPE fused for Q,K; Q pre-scaled, hi only)
    gemm_f16x2_mma<<<dim3(F_ / 128, M / 128), 256, SMEM_GEMM>>>(
        xhi, wqh, wql, bq, nullptr, qhi, nullptr, M, F_, F_, 1);
    gemm_f16x2_mma<<<dim3(NKV / 128, M / 128), 256, SMEM_GEMM>>>(
        xhi, wkh, wkl, bk, nullptr, khi, klo, M, NKV, F_, 2);
    gemm_f16x2_mma<<<dim3(NKV / 128, M / 128), 256, SMEM_GEMM>>>(
        xhi, wvh, wvl, bv, nullptr, vhi, vlo, M, NKV, F_, 3);

    // Flash attention (tensor cores, fp16 2-term)
    cudaFuncSetAttribute(flash_mma_kernel, cudaFuncAttributeMaxDynamicSharedMemorySize, SMEM_FLASH);
    flash_mma_kernel<<<dim3(S_ / 128, H_, B_), 256, SMEM_FLASH>>>();

    // Output projection (fp32 out)
    gemm_f16x2_mma<<<dim3(F_ / 128, M / 128), 256, SMEM_GEMM>>>(
        ahi, woh, wol, bo, out, nullptr, nullptr, M, F_, F_, 0);
}

// round 10
// speedup vs baseline: 1.9434x; 1.3478x over previous
#include <cuda_runtime.h>
#include <cuda_fp16.h>
#include <cstdint>
#include <math.h>

// Problem constants
#define B_   4
#define S_   2048
#define F_   2048
#define H_   16
#define G_   4
#define DH_  128
#define ROT_ 32

#define MTOT (B_*S_)   // 8192
#define QSCALE 0.12751743f   // log2(e)/sqrt(128)

// ---------------------------------------------------------------------------
// Static scratch (fp16)
// ---------------------------------------------------------------------------
__device__ __align__(16) __half g_qhi[MTOT*F_];
__device__ __align__(16) __half g_khi[MTOT*G_*DH_];
__device__ __align__(16) __half g_vhi[MTOT*G_*DH_];
__device__ __align__(16) __half g_xhi[MTOT*F_];
__device__ __align__(16) __half g_ahi[MTOT*F_];
__device__ __align__(16) __half g_wqT_hi[F_*F_];
__device__ __align__(16) __half g_wqT_lo[F_*F_];
__device__ __align__(16) __half g_wkT_hi[G_*DH_*F_];
__device__ __align__(16) __half g_wkT_lo[G_*DH_*F_];
__device__ __align__(16) __half g_wvT_hi[G_*DH_*F_];
__device__ __align__(16) __half g_woT_hi[F_*F_];
__device__ float g_cos[S_*ROT_];
__device__ float g_sin[S_*ROT_];

// ---------------------------------------------------------------------------
// Baseline-legal PTX helpers (sm_80+)
// ---------------------------------------------------------------------------
__device__ __forceinline__ uint32_t smem_u32(const void* p) {
    uint32_t a;
    asm("{ .reg .u64 t; cvta.to.shared.u64 t, %1; cvt.u32.u64 %0, t; }" : "=r"(a) : "l"(p));
    return a;
}
__device__ __forceinline__ void ldsm_x4(uint32_t* r, uint32_t addr) {
    asm volatile("ldmatrix.sync.aligned.m8n8.x4.shared.b16 {%0,%1,%2,%3}, [%4];"
                 : "=r"(r[0]), "=r"(r[1]), "=r"(r[2]), "=r"(r[3]) : "r"(addr));
}
__device__ __forceinline__ void ldsm_x4_t(uint32_t* r, uint32_t addr) {
    asm volatile("ldmatrix.sync.aligned.m8n8.x4.trans.shared.b16 {%0,%1,%2,%3}, [%4];"
                 : "=r"(r[0]), "=r"(r[1]), "=r"(r[2]), "=r"(r[3]) : "r"(addr));
}
__device__ __forceinline__ void mma_f16(float* c, const uint32_t* a, uint32_t b0, uint32_t b1) {
    asm volatile("mma.sync.aligned.m16n8k16.row.col.f32.f16.f16.f32 "
                 "{%0,%1,%2,%3}, {%4,%5,%6,%7}, {%8,%9}, {%0,%1,%2,%3};"
                 : "+f"(c[0]), "+f"(c[1]), "+f"(c[2]), "+f"(c[3])
                 : "r"(a[0]), "r"(a[1]), "r"(a[2]), "r"(a[3]), "r"(b0), "r"(b1));
}
#define CP_ASYNC16(dst, src) \
    asm volatile("cp.async.cg.shared.global [%0], [%1], 16;" :: "r"(dst), "l"(src) : "memory")
#define CP_COMMIT()  asm volatile("cp.async.commit_group;" ::: "memory")
#define CP_WAIT(n)   asm volatile("cp.async.wait_group %0;" :: "n"(n) : "memory")

__device__ __forceinline__ uint32_t pack_h2(float a, float b) {
    __half2 h = __floats2half2_rn(a, b);
    return *(uint32_t*)&h;
}

// ---------------------------------------------------------------------------
// RoPE table init
// ---------------------------------------------------------------------------
__global__ void rope_init_kernel() {
    int idx = blockIdx.x * blockDim.x + threadIdx.x;
    if (idx < S_ * ROT_) {
        int t = idx >> 5, p = idx & 31;
        double freq = pow(10000.0, -((double)(2 * p)) / 64.0);
        double f = (double)t * freq;
        g_cos[idx] = (float)cos(f);
        g_sin[idx] = (float)sin(f);
    }
}

// ---------------------------------------------------------------------------
// fp32 -> fp16 convert (x input; hi only)
// ---------------------------------------------------------------------------
__global__ void convert_x_kernel(const float* __restrict__ src,
                                 __half* __restrict__ hi, int n4) {
    int i = blockIdx.x * blockDim.x + threadIdx.x;
    if (i >= n4) return;
    float4 v = ((const float4*)src)[i];
    uint2 o;
    o.x = pack_h2(v.x, v.y);
    o.y = pack_h2(v.z, v.w);
    ((uint2*)hi)[i] = o;
}

// ---------------------------------------------------------------------------
// Weight transpose + split:  W[K][N] fp32 -> T[N][K] fp16 hi (+ optional lo)
// ---------------------------------------------------------------------------
__global__ void transpose_split_kernel(const float* __restrict__ W,
                                       __half* __restrict__ Thi,
                                       __half* __restrict__ Tlo,
                                       int K, int N) {
    __shared__ float t[32][33];
    int k0 = blockIdx.y * 32, n0 = blockIdx.x * 32;
    int tx = threadIdx.x, ty = threadIdx.y;   // 32 x 8
#pragma unroll
    for (int j = 0; j < 4; j++)
        t[ty + j * 8][tx] = W[(size_t)(k0 + ty + j * 8) * N + n0 + tx];
    __syncthreads();
#pragma unroll
    for (int j = 0; j < 4; j++) {
        int n = n0 + ty + j * 8, k = k0 + tx;
        float v = t[tx][ty + j * 8];
        __half h = __float2half_rn(v);
        Thi[(size_t)n * K + k] = h;
        if (Tlo)
            Tlo[(size_t)n * K + k] = __float2half_rn(v - __half2float(h));
    }
}

// ---------------------------------------------------------------------------
// HMMA fp16 GEMM, templated on TERMS (1: Ah*Bh, 2: Ah*(Bh+Bl)).
// CTA 128x128, BK=32, 2-stage cp.async, 8 warps 2(M)x4(N), 2 CTAs/SM.
// mode: 0 = fp32 out, 1 = Q (rope+scale, hi), 2 = K (rope, hi), 3 = V (hi).
// ---------------------------------------------------------------------------
#define GBK    32
#define TSTR   40                         // smem row stride in fp16 (80 B)
#define TILE_BYTES (128 * TSTR * 2)       // 10240

template<int TERMS>
__global__ __launch_bounds__(256, 2)
void gemm_f16_mma(const __half* __restrict__ Ahi,
                  const __half* __restrict__ BThi,
                  const __half* __restrict__ BTlo,
                  const float* __restrict__ bias,
                  float* __restrict__ C,
                  __half* __restrict__ Chi,
                  int M, int N, int K, int mode)
{
    constexpr int NTILES = 1 + TERMS;               // A + B(h[,l])
    constexpr int STAGE_BYTES = NTILES * TILE_BYTES;

    extern __shared__ char smem[];
    const uint32_t smem_base = smem_u32(smem);

    const int tid = threadIdx.x;
    const int wid = tid >> 5;
    const int lid = tid & 31;
    const int warpM = wid & 1;
    const int warpN = wid >> 1;
    const size_t rowBase = (size_t)blockIdx.y * 128;
    const size_t colBase = (size_t)blockIdx.x * 128;

    const int NC = K / GBK;

    auto prefetch = [&](int stage, int k0) {
        uint32_t st = smem_base + stage * STAGE_BYTES;
#pragma unroll
        for (int t = 0; t < 2; t++) {
            int cidx = tid + t * 256;
            int r  = cidx >> 2;
            int ch = cidx & 3;
            uint32_t doff = r * (TSTR * 2) + ch * 16;
            size_t goffA = (rowBase + r) * (size_t)K + k0 + ch * 8;
            size_t goffB = (colBase + r) * (size_t)K + k0 + ch * 8;
            CP_ASYNC16(st + doff,              (const char*)(Ahi  + goffA));
            CP_ASYNC16(st + TILE_BYTES + doff, (const char*)(BThi + goffB));
            if (TERMS == 2)
                CP_ASYNC16(st + 2*TILE_BYTES + doff, (const char*)(BTlo + goffB));
        }
        CP_COMMIT();
    };

    float acc[4][4][4];
#pragma unroll
    for (int i = 0; i < 4; i++)
#pragma unroll
        for (int j = 0; j < 4; j++)
#pragma unroll
            for (int q = 0; q < 4; q++) acc[i][j][q] = 0.f;

    const int laneRow = (lid & 7) + ((lid >> 3) & 1) * 8;
    const int laneK   = (lid >> 4) * 8;

    prefetch(0, 0);

    for (int kc = 0; kc < NC; ++kc) {
        const int s = kc & 1;
        if (kc + 1 < NC) prefetch(s ^ 1, (kc + 1) * GBK);
        if (kc + 1 < NC) { CP_WAIT(1); } else { CP_WAIT(0); }
        __syncthreads();

        const uint32_t st = smem_base + s * STAGE_BYTES;
        const uint32_t aHib = st;
        const uint32_t bHib = st + TILE_BYTES;
        const uint32_t bLob = st + 2*TILE_BYTES;

#pragma unroll
        for (int k16 = 0; k16 < GBK; k16 += 16) {
            const int kk = k16 + laneK;
            uint32_t bH[2][4], bL[2][4];
#pragma unroll
            for (int nt = 0; nt < 2; nt++) {
                int row = warpN * 32 + nt * 16 + laneRow;
                uint32_t off = (row * TSTR + kk) * 2;
                ldsm_x4(bH[nt], bHib + off);
                if (TERMS == 2) ldsm_x4(bL[nt], bLob + off);
            }
#pragma unroll
            for (int mp = 0; mp < 4; mp += 2) {
                uint32_t aH[2][4];
#pragma unroll
                for (int i = 0; i < 2; i++) {
                    int row = warpM * 64 + (mp + i) * 16 + laneRow;
                    uint32_t off = (row * TSTR + kk) * 2;
                    ldsm_x4(aH[i], aHib + off);
                }
#pragma unroll
                for (int i = 0; i < 2; i++)
#pragma unroll
                    for (int nt = 0; nt < 2; nt++) {
                        mma_f16(acc[mp+i][2*nt],   aH[i], bH[nt][0], bH[nt][2]);
                        mma_f16(acc[mp+i][2*nt+1], aH[i], bH[nt][1], bH[nt][3]);
                    }
                if (TERMS == 2) {
#pragma unroll
                    for (int i = 0; i < 2; i++)
#pragma unroll
                        for (int nt = 0; nt < 2; nt++) {
                            mma_f16(acc[mp+i][2*nt],   aH[i], bL[nt][0], bL[nt][2]);
                            mma_f16(acc[mp+i][2*nt+1], aH[i], bL[nt][1], bL[nt][3]);
                        }
                }
            }
        }
        __syncthreads();
    }

    // Epilogue
#pragma unroll
    for (int mi = 0; mi < 4; mi++) {
#pragma unroll
        for (int nj = 0; nj < 4; nj++) {
            int row0 = (int)rowBase + warpM * 64 + mi * 16 + (lid >> 2);
            int row1 = row0 + 8;
            int col  = (int)colBase + warpN * 32 + nj * 8 + (lid & 3) * 2;
            float b0 = __ldg(bias + col), b1 = __ldg(bias + col + 1);
            float v0 = acc[mi][nj][0] + b0, v1 = acc[mi][nj][1] + b1;
            float v2 = acc[mi][nj][2] + b0, v3 = acc[mi][nj][3] + b1;
            int d = col & (DH_ - 1);
            if (mode >= 1 && mode <= 2 && d < 64) {   // RoPE for Q,K
                int p = d >> 1;
                int s0 = row0 & (S_ - 1);
                int s1 = row1 & (S_ - 1);
                float c0 = g_cos[s0 * ROT_ + p], sn0 = g_sin[s0 * ROT_ + p];
                float c1 = g_cos[s1 * ROT_ + p], sn1 = g_sin[s1 * ROT_ + p];
                float a0 = v0, bb0 = v1, a1 = v2, bb1 = v3;
                v0 = a0 * c0 - bb0 * sn0;  v1 = bb0 * c0 + a0 * sn0;
                v2 = a1 * c1 - bb1 * sn1;  v3 = bb1 * c1 + a1 * sn1;
            }
            if (mode == 0) {
                *(float2*)(C + (size_t)row0 * N + col) = make_float2(v0, v1);
                *(float2*)(C + (size_t)row1 * N + col) = make_float2(v2, v3);
            } else {
                if (mode == 1) { v0 *= QSCALE; v1 *= QSCALE; v2 *= QSCALE; v3 *= QSCALE; }
                *(uint32_t*)(Chi + (size_t)row0 * N + col) = pack_h2(v0, v1);
                *(uint32_t*)(Chi + (size_t)row1 * N + col) = pack_h2(v2, v3);
            }
        }
    }
}

// ---------------------------------------------------------------------------
// Tensor-core flash attention (plain fp16 operands, fp32 accum, causal, GQA).
// Scores: q_hi·k_hi.  PV: p_hi·v_hi.
// CTA: 128 q rows x 64 kv cols per block. 8 warps x 16 q rows.
// ---------------------------------------------------------------------------
#define FSTR   272                 // bytes per smem row (128 fp16 + 8 pad)
#define FTILEB (64 * FSTR)         // 17408 bytes per 64-row tile
#define FQOFF  (4 * FTILEB)        // Q after 2 KV stages (2 tiles each)
#define SMEM_FLASH (6 * FTILEB)    // 104448

__global__ __launch_bounds__(256)
void flash_mma_kernel()
{
    extern __shared__ char fsm[];
    const uint32_t sb = smem_u32(fsm);
    const int tid = threadIdx.x;
    const int wid = tid >> 5;
    const int lid = tid & 31;
    const int qb  = 15 - (int)blockIdx.x;   // big tiles first
    const int h   = blockIdx.y;
    const int b   = blockIdx.z;
    const int g   = h >> 2;
    const int qbase = qb * 128;

    // Q: 128 rows x 128 fp16
#pragma unroll
    for (int i = 0; i < 8; i++) {
        int q = tid + i * 256;
        int r = q >> 4, ch = q & 15;
        size_t off = (((size_t)(b * S_ + qbase + r)) * H_ + h) * DH_ + ch * 8;
        uint32_t dst = sb + FQOFF + (r >> 6) * FTILEB + (r & 63) * FSTR + ch * 16;
        CP_ASYNC16(dst, (const char*)(g_qhi + off));
    }
    CP_COMMIT();
    CP_WAIT(0);
    __syncthreads();

    auto prefetch = [&](int jblk, int stage) {
        uint32_t st = sb + stage * 2 * FTILEB;
        size_t base = (((size_t)(b * S_ + jblk * 64)) * G_ + g) * DH_;
#pragma unroll
        for (int i = 0; i < 4; i++) {
            int q = tid + i * 256;
            int r = q >> 4, ch = q & 15;
            size_t off = base + (size_t)r * (G_ * DH_) + ch * 8;
            uint32_t d = st + r * FSTR + ch * 16;
            CP_ASYNC16(d,          (const char*)(g_khi + off));
            CP_ASYNC16(d + FTILEB, (const char*)(g_vhi + off));
        }
        CP_COMMIT();
    };

    float O[16][4];
#pragma unroll
    for (int i = 0; i < 16; i++)
#pragma unroll
        for (int q = 0; q < 4; q++) O[i][q] = 0.f;
    float m2[2] = {-1e30f, -1e30f};
    float l2[2] = {0.f, 0.f};

    const int nblocks = 2 * (qb + 1);
    prefetch(0, 0);

    const int qrl = wid * 16 + (lid & 15);
    const uint32_t qaddrH = sb + FQOFF + (qrl >> 6) * FTILEB + (qrl & 63) * FSTR + (lid >> 4) * 16;
    const uint32_t lanebase = (lid & 15) * FSTR + (lid >> 4) * 16;
    const int warpRow0 = qbase + wid * 16;

    for (int j = 0; j < nblocks; j++) {
        const int st = j & 1;
        if (j + 1 < nblocks) { prefetch(j + 1, st ^ 1); CP_WAIT(1); }
        else                 { CP_WAIT(0); }
        __syncthreads();

        const uint32_t kH = sb + st * 2 * FTILEB + lanebase;

        float sacc[8][4];
#pragma unroll
        for (int nb = 0; nb < 8; nb++)
#pragma unroll
            for (int q = 0; q < 4; q++) sacc[nb][q] = 0.f;

#pragma unroll
        for (int kc = 0; kc < 8; kc++) {
            uint32_t qh[4];
            ldsm_x4(qh, qaddrH + kc * 32);
#pragma unroll
            for (int n16 = 0; n16 < 4; n16++) {
                uint32_t rH[4];
                ldsm_x4(rH, kH + n16 * (16 * FSTR) + kc * 32);
                mma_f16(sacc[2*n16],   qh, rH[0], rH[2]);
                mma_f16(sacc[2*n16+1], qh, rH[1], rH[3]);
            }
        }

        if (j * 64 + 63 > warpRow0) {
#pragma unroll
            for (int nb = 0; nb < 8; nb++)
#pragma unroll
                for (int q = 0; q < 4; q++) {
                    int col = j * 64 + nb * 8 + (lid & 3) * 2 + (q & 1);
                    int row = warpRow0 + (lid >> 2) + (q >> 1) * 8;
                    if (col > row) sacc[nb][q] = -1e30f;
                }
        }

#pragma unroll
        for (int rh = 0; rh < 2; rh++) {
            float rmax = -1e30f;
#pragma unroll
            for (int nb = 0; nb < 8; nb++)
                rmax = fmaxf(rmax, fmaxf(sacc[nb][rh*2], sacc[nb][rh*2+1]));
            rmax = fmaxf(rmax, __shfl_xor_sync(0xffffffffu, rmax, 1));
            rmax = fmaxf(rmax, __shfl_xor_sync(0xffffffffu, rmax, 2));
            float mnew = fmaxf(m2[rh], rmax);
            float alpha = exp2f(m2[rh] - mnew);
            float rsum = 0.f;
#pragma unroll
            for (int nb = 0; nb < 8; nb++) {
                float p0 = exp2f(sacc[nb][rh*2]   - mnew);
                float p1 = exp2f(sacc[nb][rh*2+1] - mnew);
                sacc[nb][rh*2] = p0; sacc[nb][rh*2+1] = p1;
                rsum += p0 + p1;
            }
            rsum += __shfl_xor_sync(0xffffffffu, rsum, 1);
            rsum += __shfl_xor_sync(0xffffffffu, rsum, 2);
            l2[rh] = l2[rh] * alpha + rsum;
            m2[rh] = mnew;
#pragma unroll
            for (int nb = 0; nb < 16; nb++) {
                O[nb][rh*2]   *= alpha;
                O[nb][rh*2+1] *= alpha;
            }
        }

        // P hi fragments
        uint32_t ph[4][4];
#pragma unroll
        for (int kc = 0; kc < 4; kc++)
#pragma unroll
            for (int t = 0; t < 4; t++) {
                int nb = 2*kc + (t >> 1);
                ph[kc][t] = pack_h2(sacc[nb][(t & 1) * 2], sacc[nb][(t & 1) * 2 + 1]);
            }

        const uint32_t vbase = sb + st * 2 * FTILEB + FTILEB + lanebase;
#pragma unroll
        for (int kc = 0; kc < 4; kc++) {
            uint32_t vrow = vbase + kc * (16 * FSTR);
#pragma unroll
            for (int ng = 0; ng < 8; ng++) {
                uint32_t vh[4];
                ldsm_x4_t(vh, vrow + ng * 32);
                mma_f16(O[2*ng],   ph[kc], vh[0], vh[1]);
                mma_f16(O[2*ng+1], ph[kc], vh[2], vh[3]);
            }
        }
        __syncthreads();
    }

    // Epilogue: normalize, write fp16
    const float inv0 = 1.f / l2[0];
    const float inv1 = 1.f / l2[1];
    const int r0 = qbase + wid * 16 + (lid >> 2);
#pragma unroll
    for (int nb = 0; nb < 16; nb++) {
        int col = h * DH_ + nb * 8 + (lid & 3) * 2;
        size_t base0 = ((size_t)(b * S_ + r0)) * F_ + col;
        size_t base1 = ((size_t)(b * S_ + r0 + 8)) * F_ + col;
        *(uint32_t*)(g_ahi + base0) = pack_h2(O[nb][0] * inv0, O[nb][1] * inv0);
        *(uint32_t*)(g_ahi + base1) = pack_h2(O[nb][2] * inv1, O[nb][3] * inv1);
    }
}

// ---------------------------------------------------------------------------
extern "C" void kernel_launch(void* const* d_in, const int* in_sizes, int n_in,
                              void* d_out, int out_size)
{
    const float* x  = (const float*)d_in[0];
    const float* wq = (const float*)d_in[1];
    const float* bq = (const float*)d_in[2];
    const float* wk = (const float*)d_in[3];
    const float* bk = (const float*)d_in[4];
    const float* wv = (const float*)d_in[5];
    const float* bv = (const float*)d_in[6];
    const float* wo = (const float*)d_in[7];
    const float* bo = (const float*)d_in[8];
    float* out = (float*)d_out;

    __half *xhi, *ahi;
    cudaGetSymbolAddress((void**)&xhi, g_xhi);
    cudaGetSymbolAddress((void**)&ahi, g_ahi);
    __half *qhi, *khi, *vhi;
    cudaGetSymbolAddress((void**)&qhi, g_qhi);
    cudaGetSymbolAddress((void**)&khi, g_khi);
    cudaGetSymbolAddress((void**)&vhi, g_vhi);
    __half *wqh, *wql, *wkh, *wkl, *wvh, *woh;
    cudaGetSymbolAddress((void**)&wqh, g_wqT_hi);
    cudaGetSymbolAddress((void**)&wql, g_wqT_lo);
    cudaGetSymbolAddress((void**)&wkh, g_wkT_hi);
    cudaGetSymbolAddress((void**)&wkl, g_wkT_lo);
    cudaGetSymbolAddress((void**)&wvh, g_wvT_hi);
    cudaGetSymbolAddress((void**)&woh, g_woT_hi);

    const int M = MTOT;       // 8192
    const int NKV = G_ * DH_; // 512

    const int SMEM_G2 = 2 * 3 * TILE_BYTES;   // TERMS=2: 61440
    const int SMEM_G1 = 2 * 2 * TILE_BYTES;   // TERMS=1: 40960

    rope_init_kernel<<<(S_ * ROT_ + 255) / 256, 256>>>();

    convert_x_kernel<<<(M * F_ / 4 + 255) / 256, 256>>>(x, xhi, M * F_ / 4);

    transpose_split_kernel<<<dim3(F_ / 32, F_ / 32), dim3(32, 8)>>>(wq, wqh, wql, F_, F_);
    transpose_split_kernel<<<dim3(NKV / 32, F_ / 32), dim3(32, 8)>>>(wk, wkh, wkl, F_, NKV);
    transpose_split_kernel<<<dim3(NKV / 32, F_ / 32), dim3(32, 8)>>>(wv, wvh, nullptr, F_, NKV);
    transpose_split_kernel<<<dim3(F_ / 32, F_ / 32), dim3(32, 8)>>>(wo, woh, nullptr, F_, F_);

    cudaFuncSetAttribute(gemm_f16_mma<2>, cudaFuncAttributeMaxDynamicSharedMemorySize, SMEM_G2);
    cudaFuncSetAttribute(gemm_f16_mma<1>, cudaFuncAttributeMaxDynamicSharedMemorySize, SMEM_G1);

    // Q/K projections: 2-term (score path); V projection: 1-term
    gemm_f16_mma<2><<<dim3(F_ / 128, M / 128), 256, SMEM_G2>>>(
        xhi, wqh, wql, bq, nullptr, qhi, M, F_, F_, 1);
    gemm_f16_mma<2><<<dim3(NKV / 128, M / 128), 256, SMEM_G2>>>(
        xhi, wkh, wkl, bk, nullptr, khi, M, NKV, F_, 2);
    gemm_f16_mma<1><<<dim3(NKV / 128, M / 128), 256, SMEM_G1>>>(
        xhi, wvh, nullptr, bv, nullptr, vhi, M, NKV, F_, 3);

    // Flash attention (plain fp16 operands, fp32 accum)
    cudaFuncSetAttribute(flash_mma_kernel, cudaFuncAttributeMaxDynamicSharedMemorySize, SMEM_FLASH);
    flash_mma_kernel<<<dim3(S_ / 128, H_, B_), 256, SMEM_FLASH>>>();

    // Output projection: 1-term, fp32 out
    gemm_f16_mma<1><<<dim3(F_ / 128, M / 128), 256, SMEM_G1>>>(
        ahi, woh, nullptr, bo, out, nullptr, M, F_, F_, 0);
}

// round 11
// speedup vs baseline: 2.2216x; 1.1432x over previous
#include <cuda_runtime.h>
#include <cuda_fp16.h>
#include <cstdint>
#include <math.h>

// Problem constants
#define B_   4
#define S_   2048
#define F_   2048
#define H_   16
#define G_   4
#define DH_  128
#define ROT_ 32

#define MTOT (B_*S_)   // 8192
#define QSCALE 0.12751743f   // log2(e)/sqrt(128)

// ---------------------------------------------------------------------------
// Static scratch (fp16)
// ---------------------------------------------------------------------------
__device__ __align__(16) __half g_qhi[MTOT*F_];
__device__ __align__(16) __half g_khi[MTOT*G_*DH_];
__device__ __align__(16) __half g_vhi[MTOT*G_*DH_];
__device__ __align__(16) __half g_xhi[MTOT*F_];
__device__ __align__(16) __half g_ahi[MTOT*F_];
__device__ __align__(16) __half g_wqT_hi[F_*F_];
__device__ __align__(16) __half g_wkT_hi[G_*DH_*F_];
__device__ __align__(16) __half g_wkT_lo[G_*DH_*F_];
__device__ __align__(16) __half g_wvT_hi[G_*DH_*F_];
__device__ __align__(16) __half g_woT_hi[F_*F_];
__device__ float g_cos[S_*ROT_];
__device__ float g_sin[S_*ROT_];

// ---------------------------------------------------------------------------
// Baseline-legal PTX helpers (sm_80+)
// ---------------------------------------------------------------------------
__device__ __forceinline__ uint32_t smem_u32(const void* p) {
    uint32_t a;
    asm("{ .reg .u64 t; cvta.to.shared.u64 t, %1; cvt.u32.u64 %0, t; }" : "=r"(a) : "l"(p));
    return a;
}
__device__ __forceinline__ void ldsm_x4(uint32_t* r, uint32_t addr) {
    asm volatile("ldmatrix.sync.aligned.m8n8.x4.shared.b16 {%0,%1,%2,%3}, [%4];"
                 : "=r"(r[0]), "=r"(r[1]), "=r"(r[2]), "=r"(r[3]) : "r"(addr));
}
__device__ __forceinline__ void ldsm_x4_t(uint32_t* r, uint32_t addr) {
    asm volatile("ldmatrix.sync.aligned.m8n8.x4.trans.shared.b16 {%0,%1,%2,%3}, [%4];"
                 : "=r"(r[0]), "=r"(r[1]), "=r"(r[2]), "=r"(r[3]) : "r"(addr));
}
__device__ __forceinline__ void mma_f16(float* c, const uint32_t* a, uint32_t b0, uint32_t b1) {
    asm volatile("mma.sync.aligned.m16n8k16.row.col.f32.f16.f16.f32 "
                 "{%0,%1,%2,%3}, {%4,%5,%6,%7}, {%8,%9}, {%0,%1,%2,%3};"
                 : "+f"(c[0]), "+f"(c[1]), "+f"(c[2]), "+f"(c[3])
                 : "r"(a[0]), "r"(a[1]), "r"(a[2]), "r"(a[3]), "r"(b0), "r"(b1));
}
#define CP_ASYNC16(dst, src) \
    asm volatile("cp.async.cg.shared.global [%0], [%1], 16;" :: "r"(dst), "l"(src) : "memory")
#define CP_COMMIT()  asm volatile("cp.async.commit_group;" ::: "memory")
#define CP_WAIT(n)   asm volatile("cp.async.wait_group %0;" :: "n"(n) : "memory")

__device__ __forceinline__ uint32_t pack_h2(float a, float b) {
    __half2 h = __floats2half2_rn(a, b);
    return *(uint32_t*)&h;
}

// ---------------------------------------------------------------------------
// RoPE table init
// ---------------------------------------------------------------------------
__global__ void rope_init_kernel() {
    int idx = blockIdx.x * blockDim.x + threadIdx.x;
    if (idx < S_ * ROT_) {
        int t = idx >> 5, p = idx & 31;
        double freq = pow(10000.0, -((double)(2 * p)) / 64.0);
        double f = (double)t * freq;
        g_cos[idx] = (float)cos(f);
        g_sin[idx] = (float)sin(f);
    }
}

// ---------------------------------------------------------------------------
// fp32 -> fp16 convert (x input; hi only)
// ---------------------------------------------------------------------------
__global__ void convert_x_kernel(const float* __restrict__ src,
                                 __half* __restrict__ hi, int n4) {
    int i = blockIdx.x * blockDim.x + threadIdx.x;
    if (i >= n4) return;
    float4 v = ((const float4*)src)[i];
    uint2 o;
    o.x = pack_h2(v.x, v.y);
    o.y = pack_h2(v.z, v.w);
    ((uint2*)hi)[i] = o;
}

// ---------------------------------------------------------------------------
// Weight transpose + split:  W[K][N] fp32 -> T[N][K] fp16 hi (+ optional lo)
// ---------------------------------------------------------------------------
__global__ void transpose_split_kernel(const float* __restrict__ W,
                                       __half* __restrict__ Thi,
                                       __half* __restrict__ Tlo,
                                       int K, int N) {
    __shared__ float t[32][33];
    int k0 = blockIdx.y * 32, n0 = blockIdx.x * 32;
    int tx = threadIdx.x, ty = threadIdx.y;   // 32 x 8
#pragma unroll
    for (int j = 0; j < 4; j++)
        t[ty + j * 8][tx] = W[(size_t)(k0 + ty + j * 8) * N + n0 + tx];
    __syncthreads();
#pragma unroll
    for (int j = 0; j < 4; j++) {
        int n = n0 + ty + j * 8, k = k0 + tx;
        float v = t[tx][ty + j * 8];
        __half h = __float2half_rn(v);
        Thi[(size_t)n * K + k] = h;
        if (Tlo)
            Tlo[(size_t)n * K + k] = __float2half_rn(v - __half2float(h));
    }
}

// ---------------------------------------------------------------------------
// HMMA fp16 GEMM, templated on TERMS (1: Ah*Bh, 2: Ah*(Bh+Bl)).
// CTA 128x128, BK=32, 2-stage cp.async, 8 warps 2(M)x4(N), 2 CTAs/SM.
// mode: 0 = fp32 out, 1 = Q (rope+scale, hi), 2 = K (rope, hi), 3 = V (hi).
// ---------------------------------------------------------------------------
#define GBK    32
#define TSTR   40                         // smem row stride in fp16 (80 B)
#define TILE_BYTES (128 * TSTR * 2)       // 10240

template<int TERMS>
__global__ __launch_bounds__(256, 2)
void gemm_f16_mma(const __half* __restrict__ Ahi,
                  const __half* __restrict__ BThi,
                  const __half* __restrict__ BTlo,
                  const float* __restrict__ bias,
                  float* __restrict__ C,
                  __half* __restrict__ Chi,
                  int M, int N, int K, int mode)
{
    constexpr int NTILES = 1 + TERMS;               // A + B(h[,l])
    constexpr int STAGE_BYTES = NTILES * TILE_BYTES;

    extern __shared__ char smem[];
    const uint32_t smem_base = smem_u32(smem);

    const int tid = threadIdx.x;
    const int wid = tid >> 5;
    const int lid = tid & 31;
    const int warpM = wid & 1;
    const int warpN = wid >> 1;
    const size_t rowBase = (size_t)blockIdx.y * 128;
    const size_t colBase = (size_t)blockIdx.x * 128;

    const int NC = K / GBK;

    auto prefetch = [&](int stage, int k0) {
        uint32_t st = smem_base + stage * STAGE_BYTES;
#pragma unroll
        for (int t = 0; t < 2; t++) {
            int cidx = tid + t * 256;
            int r  = cidx >> 2;
            int ch = cidx & 3;
            uint32_t doff = r * (TSTR * 2) + ch * 16;
            size_t goffA = (rowBase + r) * (size_t)K + k0 + ch * 8;
            size_t goffB = (colBase + r) * (size_t)K + k0 + ch * 8;
            CP_ASYNC16(st + doff,              (const char*)(Ahi  + goffA));
            CP_ASYNC16(st + TILE_BYTES + doff, (const char*)(BThi + goffB));
            if (TERMS == 2)
                CP_ASYNC16(st + 2*TILE_BYTES + doff, (const char*)(BTlo + goffB));
        }
        CP_COMMIT();
    };

    float acc[4][4][4];
#pragma unroll
    for (int i = 0; i < 4; i++)
#pragma unroll
        for (int j = 0; j < 4; j++)
#pragma unroll
            for (int q = 0; q < 4; q++) acc[i][j][q] = 0.f;

    const int laneRow = (lid & 7) + ((lid >> 3) & 1) * 8;
    const int laneK   = (lid >> 4) * 8;

    prefetch(0, 0);

    for (int kc = 0; kc < NC; ++kc) {
        const int s = kc & 1;
        if (kc + 1 < NC) prefetch(s ^ 1, (kc + 1) * GBK);
        if (kc + 1 < NC) { CP_WAIT(1); } else { CP_WAIT(0); }
        __syncthreads();

        const uint32_t st = smem_base + s * STAGE_BYTES;
        const uint32_t aHib = st;
        const uint32_t bHib = st + TILE_BYTES;
        const uint32_t bLob = st + 2*TILE_BYTES;

#pragma unroll
        for (int k16 = 0; k16 < GBK; k16 += 16) {
            const int kk = k16 + laneK;
            uint32_t bH[2][4], bL[2][4];
#pragma unroll
            for (int nt = 0; nt < 2; nt++) {
                int row = warpN * 32 + nt * 16 + laneRow;
                uint32_t off = (row * TSTR + kk) * 2;
                ldsm_x4(bH[nt], bHib + off);
                if (TERMS == 2) ldsm_x4(bL[nt], bLob + off);
            }
#pragma unroll
            for (int mp = 0; mp < 4; mp += 2) {
                uint32_t aH[2][4];
#pragma unroll
                for (int i = 0; i < 2; i++) {
                    int row = warpM * 64 + (mp + i) * 16 + laneRow;
                    uint32_t off = (row * TSTR + kk) * 2;
                    ldsm_x4(aH[i], aHib + off);
                }
#pragma unroll
                for (int i = 0; i < 2; i++)
#pragma unroll
                    for (int nt = 0; nt < 2; nt++) {
                        mma_f16(acc[mp+i][2*nt],   aH[i], bH[nt][0], bH[nt][2]);
                        mma_f16(acc[mp+i][2*nt+1], aH[i], bH[nt][1], bH[nt][3]);
                    }
                if (TERMS == 2) {
#pragma unroll
                    for (int i = 0; i < 2; i++)
#pragma unroll
                        for (int nt = 0; nt < 2; nt++) {
                            mma_f16(acc[mp+i][2*nt],   aH[i], bL[nt][0], bL[nt][2]);
                            mma_f16(acc[mp+i][2*nt+1], aH[i], bL[nt][1], bL[nt][3]);
                        }
                }
            }
        }
        __syncthreads();
    }

    // Epilogue
#pragma unroll
    for (int mi = 0; mi < 4; mi++) {
#pragma unroll
        for (int nj = 0; nj < 4; nj++) {
            int row0 = (int)rowBase + warpM * 64 + mi * 16 + (lid >> 2);
            int row1 = row0 + 8;
            int col  = (int)colBase + warpN * 32 + nj * 8 + (lid & 3) * 2;
            float b0 = __ldg(bias + col), b1 = __ldg(bias + col + 1);
            float v0 = acc[mi][nj][0] + b0, v1 = acc[mi][nj][1] + b1;
            float v2 = acc[mi][nj][2] + b0, v3 = acc[mi][nj][3] + b1;
            int d = col & (DH_ - 1);
            if (mode >= 1 && mode <= 2 && d < 64) {   // RoPE for Q,K
                int p = d >> 1;
                int s0 = row0 & (S_ - 1);
                int s1 = row1 & (S_ - 1);
                float c0 = g_cos[s0 * ROT_ + p], sn0 = g_sin[s0 * ROT_ + p];
                float c1 = g_cos[s1 * ROT_ + p], sn1 = g_sin[s1 * ROT_ + p];
                float a0 = v0, bb0 = v1, a1 = v2, bb1 = v3;
                v0 = a0 * c0 - bb0 * sn0;  v1 = bb0 * c0 + a0 * sn0;
                v2 = a1 * c1 - bb1 * sn1;  v3 = bb1 * c1 + a1 * sn1;
            }
            if (mode == 0) {
                *(float2*)(C + (size_t)row0 * N + col) = make_float2(v0, v1);
                *(float2*)(C + (size_t)row1 * N + col) = make_float2(v2, v3);
            } else {
                if (mode == 1) { v0 *= QSCALE; v1 *= QSCALE; v2 *= QSCALE; v3 *= QSCALE; }
                *(uint32_t*)(Chi + (size_t)row0 * N + col) = pack_h2(v0, v1);
                *(uint32_t*)(Chi + (size_t)row1 * N + col) = pack_h2(v2, v3);
            }
        }
    }
}

// ---------------------------------------------------------------------------
// Tensor-core flash attention (plain fp16 operands, fp32 accum, causal, GQA).
// Scores: q_hi·k_hi.  PV: p_hi·v_hi.
// CTA: 128 q rows x 64 kv cols per block. 8 warps x 16 q rows.
// ---------------------------------------------------------------------------
#define FSTR   272                 // bytes per smem row (128 fp16 + 8 pad)
#define FTILEB (64 * FSTR)         // 17408 bytes per 64-row tile
#define FQOFF  (4 * FTILEB)        // Q after 2 KV stages (2 tiles each)
#define SMEM_FLASH (6 * FTILEB)    // 104448

__global__ __launch_bounds__(256)
void flash_mma_kernel()
{
    extern __shared__ char fsm[];
    const uint32_t sb = smem_u32(fsm);
    const int tid = threadIdx.x;
    const int wid = tid >> 5;
    const int lid = tid & 31;
    const int qb  = 15 - (int)blockIdx.x;   // big tiles first
    const int h   = blockIdx.y;
    const int b   = blockIdx.z;
    const int g   = h >> 2;
    const int qbase = qb * 128;

    // Q: 128 rows x 128 fp16
#pragma unroll
    for (int i = 0; i < 8; i++) {
        int q = tid + i * 256;
        int r = q >> 4, ch = q & 15;
        size_t off = (((size_t)(b * S_ + qbase + r)) * H_ + h) * DH_ + ch * 8;
        uint32_t dst = sb + FQOFF + (r >> 6) * FTILEB + (r & 63) * FSTR + ch * 16;
        CP_ASYNC16(dst, (const char*)(g_qhi + off));
    }
    CP_COMMIT();
    CP_WAIT(0);
    __syncthreads();

    auto prefetch = [&](int jblk, int stage) {
        uint32_t st = sb + stage * 2 * FTILEB;
        size_t base = (((size_t)(b * S_ + jblk * 64)) * G_ + g) * DH_;
#pragma unroll
        for (int i = 0; i < 4; i++) {
            int q = tid + i * 256;
            int r = q >> 4, ch = q & 15;
            size_t off = base + (size_t)r * (G_ * DH_) + ch * 8;
            uint32_t d = st + r * FSTR + ch * 16;
            CP_ASYNC16(d,          (const char*)(g_khi + off));
            CP_ASYNC16(d + FTILEB, (const char*)(g_vhi + off));
        }
        CP_COMMIT();
    };

    float O[16][4];
#pragma unroll
    for (int i = 0; i < 16; i++)
#pragma unroll
        for (int q = 0; q < 4; q++) O[i][q] = 0.f;
    float m2[2] = {-1e30f, -1e30f};
    float l2[2] = {0.f, 0.f};

    const int nblocks = 2 * (qb + 1);
    prefetch(0, 0);

    const int qrl = wid * 16 + (lid & 15);
    const uint32_t qaddrH = sb + FQOFF + (qrl >> 6) * FTILEB + (qrl & 63) * FSTR + (lid >> 4) * 16;
    const uint32_t lanebase = (lid & 15) * FSTR + (lid >> 4) * 16;
    const int warpRow0 = qbase + wid * 16;

    for (int j = 0; j < nblocks; j++) {
        const int st = j & 1;
        if (j + 1 < nblocks) { prefetch(j + 1, st ^ 1); CP_WAIT(1); }
        else                 { CP_WAIT(0); }
        __syncthreads();

        const uint32_t kH = sb + st * 2 * FTILEB + lanebase;

        float sacc[8][4];
#pragma unroll
        for (int nb = 0; nb < 8; nb++)
#pragma unroll
            for (int q = 0; q < 4; q++) sacc[nb][q] = 0.f;

#pragma unroll
        for (int kc = 0; kc < 8; kc++) {
            uint32_t qh[4];
            ldsm_x4(qh, qaddrH + kc * 32);
#pragma unroll
            for (int n16 = 0; n16 < 4; n16++) {
                uint32_t rH[4];
                ldsm_x4(rH, kH + n16 * (16 * FSTR) + kc * 32);
                mma_f16(sacc[2*n16],   qh, rH[0], rH[2]);
                mma_f16(sacc[2*n16+1], qh, rH[1], rH[3]);
            }
        }

        if (j * 64 + 63 > warpRow0) {
#pragma unroll
            for (int nb = 0; nb < 8; nb++)
#pragma unroll
                for (int q = 0; q < 4; q++) {
                    int col = j * 64 + nb * 8 + (lid & 3) * 2 + (q & 1);
                    int row = warpRow0 + (lid >> 2) + (q >> 1) * 8;
                    if (col > row) sacc[nb][q] = -1e30f;
                }
        }

#pragma unroll
        for (int rh = 0; rh < 2; rh++) {
            float rmax = -1e30f;
#pragma unroll
            for (int nb = 0; nb < 8; nb++)
                rmax = fmaxf(rmax, fmaxf(sacc[nb][rh*2], sacc[nb][rh*2+1]));
            rmax = fmaxf(rmax, __shfl_xor_sync(0xffffffffu, rmax, 1));
            rmax = fmaxf(rmax, __shfl_xor_sync(0xffffffffu, rmax, 2));
            float mnew = fmaxf(m2[rh], rmax);
            float alpha = exp2f(m2[rh] - mnew);
            float rsum = 0.f;
#pragma unroll
            for (int nb = 0; nb < 8; nb++) {
                float p0 = exp2f(sacc[nb][rh*2]   - mnew);
                float p1 = exp2f(sacc[nb][rh*2+1] - mnew);
                sacc[nb][rh*2] = p0; sacc[nb][rh*2+1] = p1;
                rsum += p0 + p1;
            }
            rsum += __shfl_xor_sync(0xffffffffu, rsum, 1);
            rsum += __shfl_xor_sync(0xffffffffu, rsum, 2);
            l2[rh] = l2[rh] * alpha + rsum;
            m2[rh] = mnew;
#pragma unroll
            for (int nb = 0; nb < 16; nb++) {
                O[nb][rh*2]   *= alpha;
                O[nb][rh*2+1] *= alpha;
            }
        }

        // P hi fragments
        uint32_t ph[4][4];
#pragma unroll
        for (int kc = 0; kc < 4; kc++)
#pragma unroll
            for (int t = 0; t < 4; t++) {
                int nb = 2*kc + (t >> 1);
                ph[kc][t] = pack_h2(sacc[nb][(t & 1) * 2], sacc[nb][(t & 1) * 2 + 1]);
            }

        const uint32_t vbase = sb + st * 2 * FTILEB + FTILEB + lanebase;
#pragma unroll
        for (int kc = 0; kc < 4; kc++) {
            uint32_t vrow = vbase + kc * (16 * FSTR);
#pragma unroll
            for (int ng = 0; ng < 8; ng++) {
                uint32_t vh[4];
                ldsm_x4_t(vh, vrow + ng * 32);
                mma_f16(O[2*ng],   ph[kc], vh[0], vh[1]);
                mma_f16(O[2*ng+1], ph[kc], vh[2], vh[3]);
            }
        }
        __syncthreads();
    }

    // Epilogue: normalize, write fp16
    const float inv0 = 1.f / l2[0];
    const float inv1 = 1.f / l2[1];
    const int r0 = qbase + wid * 16 + (lid >> 2);
#pragma unroll
    for (int nb = 0; nb < 16; nb++) {
        int col = h * DH_ + nb * 8 + (lid & 3) * 2;
        size_t base0 = ((size_t)(b * S_ + r0)) * F_ + col;
        size_t base1 = ((size_t)(b * S_ + r0 + 8)) * F_ + col;
        *(uint32_t*)(g_ahi + base0) = pack_h2(O[nb][0] * inv0, O[nb][1] * inv0);
        *(uint32_t*)(g_ahi + base1) = pack_h2(O[nb][2] * inv1, O[nb][3] * inv1);
    }
}

// ---------------------------------------------------------------------------
extern "C" void kernel_launch(void* const* d_in, const int* in_sizes, int n_in,
                              void* d_out, int out_size)
{
    const float* x  = (const float*)d_in[0];
    const float* wq = (const float*)d_in[1];
    const float* bq = (const float*)d_in[2];
    const float* wk = (const float*)d_in[3];
    const float* bk = (const float*)d_in[4];
    const float* wv = (const float*)d_in[5];
    const float* bv = (const float*)d_in[6];
    const float* wo = (const float*)d_in[7];
    const float* bo = (const float*)d_in[8];
    float* out = (float*)d_out;

    __half *xhi, *ahi;
    cudaGetSymbolAddress((void**)&xhi, g_xhi);
    cudaGetSymbolAddress((void**)&ahi, g_ahi);
    __half *qhi, *khi, *vhi;
    cudaGetSymbolAddress((void**)&qhi, g_qhi);
    cudaGetSymbolAddress((void**)&khi, g_khi);
    cudaGetSymbolAddress((void**)&vhi, g_vhi);
    __half *wqh, *wkh, *wkl, *wvh, *woh;
    cudaGetSymbolAddress((void**)&wqh, g_wqT_hi);
    cudaGetSymbolAddress((void**)&wkh, g_wkT_hi);
    cudaGetSymbolAddress((void**)&wkl, g_wkT_lo);
    cudaGetSymbolAddress((void**)&wvh, g_wvT_hi);
    cudaGetSymbolAddress((void**)&woh, g_woT_hi);

    const int M = MTOT;       // 8192
    const int NKV = G_ * DH_; // 512

    const int SMEM_G2 = 2 * 3 * TILE_BYTES;   // TERMS=2: 61440
    const int SMEM_G1 = 2 * 2 * TILE_BYTES;   // TERMS=1: 40960

    rope_init_kernel<<<(S_ * ROT_ + 255) / 256, 256>>>();

    convert_x_kernel<<<(M * F_ / 4 + 255) / 256, 256>>>(x, xhi, M * F_ / 4);

    transpose_split_kernel<<<dim3(F_ / 32, F_ / 32), dim3(32, 8)>>>(wq, wqh, nullptr, F_, F_);
    transpose_split_kernel<<<dim3(NKV / 32, F_ / 32), dim3(32, 8)>>>(wk, wkh, wkl, F_, NKV);
    transpose_split_kernel<<<dim3(NKV / 32, F_ / 32), dim3(32, 8)>>>(wv, wvh, nullptr, F_, NKV);
    transpose_split_kernel<<<dim3(F_ / 32, F_ / 32), dim3(32, 8)>>>(wo, woh, nullptr, F_, F_);

    cudaFuncSetAttribute(gemm_f16_mma<2>, cudaFuncAttributeMaxDynamicSharedMemorySize, SMEM_G2);
    cudaFuncSetAttribute(gemm_f16_mma<1>, cudaFuncAttributeMaxDynamicSharedMemorySize, SMEM_G1);

    // Q projection: 1-term; K projection: 2-term (score-path anchor); V: 1-term
    gemm_f16_mma<1><<<dim3(F_ / 128, M / 128), 256, SMEM_G1>>>(
        xhi, wqh, nullptr, bq, nullptr, qhi, M, F_, F_, 1);
    gemm_f16_mma<2><<<dim3(NKV / 128, M / 128), 256, SMEM_G2>>>(
        xhi, wkh, wkl, bk, nullptr, khi, M, NKV, F_, 2);
    gemm_f16_mma<1><<<dim3(NKV / 128, M / 128), 256, SMEM_G1>>>(
        xhi, wvh, nullptr, bv, nullptr, vhi, M, NKV, F_, 3);

    // Flash attention (plain fp16 operands, fp32 accum)
    cudaFuncSetAttribute(flash_mma_kernel, cudaFuncAttributeMaxDynamicSharedMemorySize, SMEM_FLASH);
    flash_mma_kernel<<<dim3(S_ / 128, H_, B_), 256, SMEM_FLASH>>>();

    // Output projection: 1-term, fp32 out
    gemm_f16_mma<1><<<dim3(F_ / 128, M / 128), 256, SMEM_G1>>>(
        ahi, woh, nullptr, bo, out, nullptr, M, F_, F_, 0);
}

// round 12
// speedup vs baseline: 2.3975x; 1.0791x over previous
#include <cuda_runtime.h>
#include <cuda_fp16.h>
#include <cstdint>
#include <math.h>

// Problem constants
#define B_   4
#define S_   2048
#define F_   2048
#define H_   16
#define G_   4
#define DH_  128
#define ROT_ 32

#define MTOT (B_*S_)   // 8192
#define QSCALE 0.12751743f   // log2(e)/sqrt(128)

// ---------------------------------------------------------------------------
// Static scratch (fp16)
// ---------------------------------------------------------------------------
__device__ __align__(16) __half g_qhi[MTOT*F_];
__device__ __align__(16) __half g_khi[MTOT*G_*DH_];
__device__ __align__(16) __half g_vhi[MTOT*G_*DH_];
__device__ __align__(16) __half g_xhi[MTOT*F_];
__device__ __align__(16) __half g_ahi[MTOT*F_];
__device__ __align__(16) __half g_wqT_hi[F_*F_];
__device__ __align__(16) __half g_wkT_hi[G_*DH_*F_];
__device__ __align__(16) __half g_wvT_hi[G_*DH_*F_];
__device__ __align__(16) __half g_woT_hi[F_*F_];
__device__ float g_cos[S_*ROT_];
__device__ float g_sin[S_*ROT_];

// ---------------------------------------------------------------------------
// Baseline-legal PTX helpers (sm_80+)
// ---------------------------------------------------------------------------
__device__ __forceinline__ uint32_t smem_u32(const void* p) {
    uint32_t a;
    asm("{ .reg .u64 t; cvta.to.shared.u64 t, %1; cvt.u32.u64 %0, t; }" : "=r"(a) : "l"(p));
    return a;
}
__device__ __forceinline__ void ldsm_x4(uint32_t* r, uint32_t addr) {
    asm volatile("ldmatrix.sync.aligned.m8n8.x4.shared.b16 {%0,%1,%2,%3}, [%4];"
                 : "=r"(r[0]), "=r"(r[1]), "=r"(r[2]), "=r"(r[3]) : "r"(addr));
}
__device__ __forceinline__ void ldsm_x4_t(uint32_t* r, uint32_t addr) {
    asm volatile("ldmatrix.sync.aligned.m8n8.x4.trans.shared.b16 {%0,%1,%2,%3}, [%4];"
                 : "=r"(r[0]), "=r"(r[1]), "=r"(r[2]), "=r"(r[3]) : "r"(addr));
}
__device__ __forceinline__ void mma_f16(float* c, const uint32_t* a, uint32_t b0, uint32_t b1) {
    asm volatile("mma.sync.aligned.m16n8k16.row.col.f32.f16.f16.f32 "
                 "{%0,%1,%2,%3}, {%4,%5,%6,%7}, {%8,%9}, {%0,%1,%2,%3};"
                 : "+f"(c[0]), "+f"(c[1]), "+f"(c[2]), "+f"(c[3])
                 : "r"(a[0]), "r"(a[1]), "r"(a[2]), "r"(a[3]), "r"(b0), "r"(b1));
}
#define CP_ASYNC16(dst, src) \
    asm volatile("cp.async.cg.shared.global [%0], [%1], 16;" :: "r"(dst), "l"(src) : "memory")
#define CP_COMMIT()  asm volatile("cp.async.commit_group;" ::: "memory")
#define CP_WAIT(n)   asm volatile("cp.async.wait_group %0;" :: "n"(n) : "memory")

__device__ __forceinline__ uint32_t pack_h2(float a, float b) {
    __half2 h = __floats2half2_rn(a, b);
    return *(uint32_t*)&h;
}

// ---------------------------------------------------------------------------
// RoPE table init
// ---------------------------------------------------------------------------
__global__ void rope_init_kernel() {
    int idx = blockIdx.x * blockDim.x + threadIdx.x;
    if (idx < S_ * ROT_) {
        int t = idx >> 5, p = idx & 31;
        double freq = pow(10000.0, -((double)(2 * p)) / 64.0);
        double f = (double)t * freq;
        g_cos[idx] = (float)cos(f);
        g_sin[idx] = (float)sin(f);
    }
}

// ---------------------------------------------------------------------------
// fp32 -> fp16 convert (x input)
// ---------------------------------------------------------------------------
__global__ void convert_x_kernel(const float* __restrict__ src,
                                 __half* __restrict__ hi, int n4) {
    int i = blockIdx.x * blockDim.x + threadIdx.x;
    if (i >= n4) return;
    float4 v = ((const float4*)src)[i];
    uint2 o;
    o.x = pack_h2(v.x, v.y);
    o.y = pack_h2(v.z, v.w);
    ((uint2*)hi)[i] = o;
}

// ---------------------------------------------------------------------------
// Weight transpose:  W[K][N] fp32 -> T[N][K] fp16
// ---------------------------------------------------------------------------
__global__ void transpose_h_kernel(const float* __restrict__ W,
                                   __half* __restrict__ Thi,
                                   int K, int N) {
    __shared__ float t[32][33];
    int k0 = blockIdx.y * 32, n0 = blockIdx.x * 32;
    int tx = threadIdx.x, ty = threadIdx.y;   // 32 x 8
#pragma unroll
    for (int j = 0; j < 4; j++)
        t[ty + j * 8][tx] = W[(size_t)(k0 + ty + j * 8) * N + n0 + tx];
    __syncthreads();
#pragma unroll
    for (int j = 0; j < 4; j++) {
        int n = n0 + ty + j * 8, k = k0 + tx;
        Thi[(size_t)n * K + k] = __float2half_rn(t[tx][ty + j * 8]);
    }
}

// ---------------------------------------------------------------------------
// Shared GEMM body (fp16 1-term, fp32 accum). CTA tile 128x128, BK=32,
// 2-stage cp.async, 8 warps 2(M)x4(N).
// mode: 0 = fp32 out, 1 = Q (rope+scale, fp16), 2 = K (rope, fp16), 3 = V (fp16).
// ---------------------------------------------------------------------------
#define GBK    32
#define TSTR   40                         // smem row stride in fp16 (80 B)
#define TILE_BYTES (128 * TSTR * 2)       // 10240
#define STAGE_BYTES (2 * TILE_BYTES)      // A + B = 20480
#define SMEM_GEMM (2 * STAGE_BYTES)       // 40960

__device__ __forceinline__ void gemm_body(
    uint32_t smem_base, int tid,
    const __half* __restrict__ Ahi,
    const __half* __restrict__ BThi,
    const float* __restrict__ bias,
    float* __restrict__ C,
    __half* __restrict__ Chi,
    size_t rowBase, size_t colBase,
    int N, int K, int mode)
{
    const int wid = tid >> 5;
    const int lid = tid & 31;
    const int warpM = wid & 1;
    const int warpN = wid >> 1;

    const int NC = K / GBK;

    auto prefetch = [&](int stage, int k0) {
        uint32_t st = smem_base + stage * STAGE_BYTES;
#pragma unroll
        for (int t = 0; t < 2; t++) {
            int cidx = tid + t * 256;
            int r  = cidx >> 2;
            int ch = cidx & 3;
            uint32_t doff = r * (TSTR * 2) + ch * 16;
            size_t goffA = (rowBase + r) * (size_t)K + k0 + ch * 8;
            size_t goffB = (colBase + r) * (size_t)K + k0 + ch * 8;
            CP_ASYNC16(st + doff,              (const char*)(Ahi  + goffA));
            CP_ASYNC16(st + TILE_BYTES + doff, (const char*)(BThi + goffB));
        }
        CP_COMMIT();
    };

    float acc[4][4][4];
#pragma unroll
    for (int i = 0; i < 4; i++)
#pragma unroll
        for (int j = 0; j < 4; j++)
#pragma unroll
            for (int q = 0; q < 4; q++) acc[i][j][q] = 0.f;

    const int laneRow = (lid & 7) + ((lid >> 3) & 1) * 8;
    const int laneK   = (lid >> 4) * 8;

    prefetch(0, 0);

    for (int kc = 0; kc < NC; ++kc) {
        const int s = kc & 1;
        if (kc + 1 < NC) prefetch(s ^ 1, (kc + 1) * GBK);
        if (kc + 1 < NC) { CP_WAIT(1); } else { CP_WAIT(0); }
        __syncthreads();

        const uint32_t st = smem_base + s * STAGE_BYTES;
        const uint32_t aHib = st;
        const uint32_t bHib = st + TILE_BYTES;

#pragma unroll
        for (int k16 = 0; k16 < GBK; k16 += 16) {
            const int kk = k16 + laneK;
            uint32_t bH[2][4];
#pragma unroll
            for (int nt = 0; nt < 2; nt++) {
                int row = warpN * 32 + nt * 16 + laneRow;
                uint32_t off = (row * TSTR + kk) * 2;
                ldsm_x4(bH[nt], bHib + off);
            }
#pragma unroll
            for (int mp = 0; mp < 4; mp += 2) {
                uint32_t aH[2][4];
#pragma unroll
                for (int i = 0; i < 2; i++) {
                    int row = warpM * 64 + (mp + i) * 16 + laneRow;
                    uint32_t off = (row * TSTR + kk) * 2;
                    ldsm_x4(aH[i], aHib + off);
                }
#pragma unroll
                for (int i = 0; i < 2; i++)
#pragma unroll
                    for (int nt = 0; nt < 2; nt++) {
                        mma_f16(acc[mp+i][2*nt],   aH[i], bH[nt][0], bH[nt][2]);
                        mma_f16(acc[mp+i][2*nt+1], aH[i], bH[nt][1], bH[nt][3]);
                    }
            }
        }
        __syncthreads();
    }

    // Epilogue
#pragma unroll
    for (int mi = 0; mi < 4; mi++) {
#pragma unroll
        for (int nj = 0; nj < 4; nj++) {
            int row0 = (int)rowBase + warpM * 64 + mi * 16 + (lid >> 2);
            int row1 = row0 + 8;
            int col  = (int)colBase + warpN * 32 + nj * 8 + (lid & 3) * 2;
            float b0 = __ldg(bias + col), b1 = __ldg(bias + col + 1);
            float v0 = acc[mi][nj][0] + b0, v1 = acc[mi][nj][1] + b1;
            float v2 = acc[mi][nj][2] + b0, v3 = acc[mi][nj][3] + b1;
            int d = col & (DH_ - 1);
            if (mode >= 1 && mode <= 2 && d < 64) {   // RoPE for Q,K
                int p = d >> 1;
                int s0 = row0 & (S_ - 1);
                int s1 = row1 & (S_ - 1);
                float c0 = g_cos[s0 * ROT_ + p], sn0 = g_sin[s0 * ROT_ + p];
                float c1 = g_cos[s1 * ROT_ + p], sn1 = g_sin[s1 * ROT_ + p];
                float a0 = v0, bb0 = v1, a1 = v2, bb1 = v3;
                v0 = a0 * c0 - bb0 * sn0;  v1 = bb0 * c0 + a0 * sn0;
                v2 = a1 * c1 - bb1 * sn1;  v3 = bb1 * c1 + a1 * sn1;
            }
            if (mode == 0) {
                *(float2*)(C + (size_t)row0 * N + col) = make_float2(v0, v1);
                *(float2*)(C + (size_t)row1 * N + col) = make_float2(v2, v3);
            } else {
                if (mode == 1) { v0 *= QSCALE; v1 *= QSCALE; v2 *= QSCALE; v3 *= QSCALE; }
                *(uint32_t*)(Chi + (size_t)row0 * N + col) = pack_h2(v0, v1);
                *(uint32_t*)(Chi + (size_t)row1 * N + col) = pack_h2(v2, v3);
            }
        }
    }
}

// ---------------------------------------------------------------------------
// Merged Q/K/V projection: grid (24, 64). bx<16 -> Q, 16..19 -> K, 20..23 -> V.
// ---------------------------------------------------------------------------
__global__ __launch_bounds__(256, 2)
void qkv_proj_kernel(const __half* __restrict__ xhi,
                     const __half* __restrict__ wq,
                     const __half* __restrict__ wk,
                     const __half* __restrict__ wv,
                     const float* __restrict__ bq,
                     const float* __restrict__ bk,
                     const float* __restrict__ bv,
                     __half* __restrict__ qout,
                     __half* __restrict__ kout,
                     __half* __restrict__ vout)
{
    extern __shared__ char smem[];
    const uint32_t smem_base = smem_u32(smem);
    const int bx = blockIdx.x;
    const size_t rowBase = (size_t)blockIdx.y * 128;

    const __half* B;
    const float* bias;
    __half* Chi;
    size_t colBase;
    int N, mode;
    if (bx < 16)      { B = wq; bias = bq; Chi = qout; colBase = (size_t)bx * 128;        N = F_;       mode = 1; }
    else if (bx < 20) { B = wk; bias = bk; Chi = kout; colBase = (size_t)(bx - 16) * 128; N = G_ * DH_; mode = 2; }
    else              { B = wv; bias = bv; Chi = vout; colBase = (size_t)(bx - 20) * 128; N = G_ * DH_; mode = 3; }

    gemm_body(smem_base, threadIdx.x, xhi, B, bias, nullptr, Chi,
              rowBase, colBase, N, F_, mode);
}

// ---------------------------------------------------------------------------
// O projection (fp32 out)
// ---------------------------------------------------------------------------
__global__ __launch_bounds__(256, 2)
void o_proj_kernel(const __half* __restrict__ ahi,
                   const __half* __restrict__ wo,
                   const float* __restrict__ bo,
                   float* __restrict__ out)
{
    extern __shared__ char smem[];
    const uint32_t smem_base = smem_u32(smem);
    gemm_body(smem_base, threadIdx.x, ahi, wo, bo, out, nullptr,
              (size_t)blockIdx.y * 128, (size_t)blockIdx.x * 128, F_, F_, 0);
}

// ---------------------------------------------------------------------------
// Tensor-core flash attention (plain fp16 operands, fp32 accum, causal, GQA).
// CTA: 128 q rows x 64 kv cols per block. 8 warps x 16 q rows.
// ---------------------------------------------------------------------------
#define FSTR   272                 // bytes per smem row (128 fp16 + 8 pad)
#define FTILEB (64 * FSTR)         // 17408 bytes per 64-row tile
#define FQOFF  (4 * FTILEB)        // Q after 2 KV stages (2 tiles each)
#define SMEM_FLASH (6 * FTILEB)    // 104448

__global__ __launch_bounds__(256)
void flash_mma_kernel()
{
    extern __shared__ char fsm[];
    const uint32_t sb = smem_u32(fsm);
    const int tid = threadIdx.x;
    const int wid = tid >> 5;
    const int lid = tid & 31;
    const int qb  = 15 - (int)blockIdx.x;   // big tiles first
    const int h   = blockIdx.y;
    const int b   = blockIdx.z;
    const int g   = h >> 2;
    const int qbase = qb * 128;

    // Q: 128 rows x 128 fp16
#pragma unroll
    for (int i = 0; i < 8; i++) {
        int q = tid + i * 256;
        int r = q >> 4, ch = q & 15;
        size_t off = (((size_t)(b * S_ + qbase + r)) * H_ + h) * DH_ + ch * 8;
        uint32_t dst = sb + FQOFF + (r >> 6) * FTILEB + (r & 63) * FSTR + ch * 16;
        CP_ASYNC16(dst, (const char*)(g_qhi + off));
    }
    CP_COMMIT();
    CP_WAIT(0);
    __syncthreads();

    auto prefetch = [&](int jblk, int stage) {
        uint32_t st = sb + stage * 2 * FTILEB;
        size_t base = (((size_t)(b * S_ + jblk * 64)) * G_ + g) * DH_;
#pragma unroll
        for (int i = 0; i < 4; i++) {
            int q = tid + i * 256;
            int r = q >> 4, ch = q & 15;
            size_t off = base + (size_t)r * (G_ * DH_) + ch * 8;
            uint32_t d = st + r * FSTR + ch * 16;
            CP_ASYNC16(d,          (const char*)(g_khi + off));
            CP_ASYNC16(d + FTILEB, (const char*)(g_vhi + off));
        }
        CP_COMMIT();
    };

    float O[16][4];
#pragma unroll
    for (int i = 0; i < 16; i++)
#pragma unroll
        for (int q = 0; q < 4; q++) O[i][q] = 0.f;
    float m2[2] = {-1e30f, -1e30f};
    float l2[2] = {0.f, 0.f};

    const int nblocks = 2 * (qb + 1);
    prefetch(0, 0);

    const int qrl = wid * 16 + (lid & 15);
    const uint32_t qaddrH = sb + FQOFF + (qrl >> 6) * FTILEB + (qrl & 63) * FSTR + (lid >> 4) * 16;
    const uint32_t lanebase = (lid & 15) * FSTR + (lid >> 4) * 16;
    const int warpRow0 = qbase + wid * 16;

    for (int j = 0; j < nblocks; j++) {
        const int st = j & 1;
        if (j + 1 < nblocks) { prefetch(j + 1, st ^ 1); CP_WAIT(1); }
        else                 { CP_WAIT(0); }
        __syncthreads();

        const uint32_t kH = sb + st * 2 * FTILEB + lanebase;

        float sacc[8][4];
#pragma unroll
        for (int nb = 0; nb < 8; nb++)
#pragma unroll
            for (int q = 0; q < 4; q++) sacc[nb][q] = 0.f;

#pragma unroll
        for (int kc = 0; kc < 8; kc++) {
            uint32_t qh[4];
            ldsm_x4(qh, qaddrH + kc * 32);
#pragma unroll
            for (int n16 = 0; n16 < 4; n16++) {
                uint32_t rH[4];
                ldsm_x4(rH, kH + n16 * (16 * FSTR) + kc * 32);
                mma_f16(sacc[2*n16],   qh, rH[0], rH[2]);
                mma_f16(sacc[2*n16+1], qh, rH[1], rH[3]);
            }
        }

        if (j * 64 + 63 > warpRow0) {
#pragma unroll
            for (int nb = 0; nb < 8; nb++)
#pragma unroll
                for (int q = 0; q < 4; q++) {
                    int col = j * 64 + nb * 8 + (lid & 3) * 2 + (q & 1);
                    int row = warpRow0 + (lid >> 2) + (q >> 1) * 8;
                    if (col > row) sacc[nb][q] = -1e30f;
                }
        }

#pragma unroll
        for (int rh = 0; rh < 2; rh++) {
            float rmax = -1e30f;
#pragma unroll
            for (int nb = 0; nb < 8; nb++)
                rmax = fmaxf(rmax, fmaxf(sacc[nb][rh*2], sacc[nb][rh*2+1]));
            rmax = fmaxf(rmax, __shfl_xor_sync(0xffffffffu, rmax, 1));
            rmax = fmaxf(rmax, __shfl_xor_sync(0xffffffffu, rmax, 2));
            float mnew = fmaxf(m2[rh], rmax);
            float alpha = exp2f(m2[rh] - mnew);
            float rsum = 0.f;
#pragma unroll
            for (int nb = 0; nb < 8; nb++) {
                float p0 = exp2f(sacc[nb][rh*2]   - mnew);
                float p1 = exp2f(sacc[nb][rh*2+1] - mnew);
                sacc[nb][rh*2] = p0; sacc[nb][rh*2+1] = p1;
                rsum += p0 + p1;
            }
            rsum += __shfl_xor_sync(0xffffffffu, rsum, 1);
            rsum += __shfl_xor_sync(0xffffffffu, rsum, 2);
            l2[rh] = l2[rh] * alpha + rsum;
            m2[rh] = mnew;
#pragma unroll
            for (int nb = 0; nb < 16; nb++) {
                O[nb][rh*2]   *= alpha;
                O[nb][rh*2+1] *= alpha;
            }
        }

        // P hi fragments
        uint32_t ph[4][4];
#pragma unroll
        for (int kc = 0; kc < 4; kc++)
#pragma unroll
            for (int t = 0; t < 4; t++) {
                int nb = 2*kc + (t >> 1);
                ph[kc][t] = pack_h2(sacc[nb][(t & 1) * 2], sacc[nb][(t & 1) * 2 + 1]);
            }

        const uint32_t vbase = sb + st * 2 * FTILEB + FTILEB + lanebase;
#pragma unroll
        for (int kc = 0; kc < 4; kc++) {
            uint32_t vrow = vbase + kc * (16 * FSTR);
#pragma unroll
            for (int ng = 0; ng < 8; ng++) {
                uint32_t vh[4];
                ldsm_x4_t(vh, vrow + ng * 32);
                mma_f16(O[2*ng],   ph[kc], vh[0], vh[1]);
                mma_f16(O[2*ng+1], ph[kc], vh[2], vh[3]);
            }
        }
        __syncthreads();
    }

    // Epilogue: normalize, write fp16
    const float inv0 = 1.f / l2[0];
    const float inv1 = 1.f / l2[1];
    const int r0 = qbase + wid * 16 + (lid >> 2);
#pragma unroll
    for (int nb = 0; nb < 16; nb++) {
        int col = h * DH_ + nb * 8 + (lid & 3) * 2;
        size_t base0 = ((size_t)(b * S_ + r0)) * F_ + col;
        size_t base1 = ((size_t)(b * S_ + r0 + 8)) * F_ + col;
        *(uint32_t*)(g_ahi + base0) = pack_h2(O[nb][0] * inv0, O[nb][1] * inv0);
        *(uint32_t*)(g_ahi + base1) = pack_h2(O[nb][2] * inv1, O[nb][3] * inv1);
    }
}

// ---------------------------------------------------------------------------
extern "C" void kernel_launch(void* const* d_in, const int* in_sizes, int n_in,
                              void* d_out, int out_size)
{
    const float* x  = (const float*)d_in[0];
    const float* wq = (const float*)d_in[1];
    const float* bq = (const float*)d_in[2];
    const float* wk = (const float*)d_in[3];
    const float* bk = (const float*)d_in[4];
    const float* wv = (const float*)d_in[5];
    const float* bv = (const float*)d_in[6];
    const float* wo = (const float*)d_in[7];
    const float* bo = (const float*)d_in[8];
    float* out = (float*)d_out;

    __half *xhi, *ahi;
    cudaGetSymbolAddress((void**)&xhi, g_xhi);
    cudaGetSymbolAddress((void**)&ahi, g_ahi);
    __half *qhi, *khi, *vhi;
    cudaGetSymbolAddress((void**)&qhi, g_qhi);
    cudaGetSymbolAddress((void**)&khi, g_khi);
    cudaGetSymbolAddress((void**)&vhi, g_vhi);
    __half *wqh, *wkh, *wvh, *woh;
    cudaGetSymbolAddress((void**)&wqh, g_wqT_hi);
    cudaGetSymbolAddress((void**)&wkh, g_wkT_hi);
    cudaGetSymbolAddress((void**)&wvh, g_wvT_hi);
    cudaGetSymbolAddress((void**)&woh, g_woT_hi);

    const int M = MTOT;       // 8192
    const int NKV = G_ * DH_; // 512

    rope_init_kernel<<<(S_ * ROT_ + 255) / 256, 256>>>();

    convert_x_kernel<<<(M * F_ / 4 + 255) / 256, 256>>>(x, xhi, M * F_ / 4);

    transpose_h_kernel<<<dim3(F_ / 32, F_ / 32), dim3(32, 8)>>>(wq, wqh, F_, F_);
    transpose_h_kernel<<<dim3(NKV / 32, F_ / 32), dim3(32, 8)>>>(wk, wkh, F_, NKV);
    transpose_h_kernel<<<dim3(NKV / 32, F_ / 32), dim3(32, 8)>>>(wv, wvh, F_, NKV);
    transpose_h_kernel<<<dim3(F_ / 32, F_ / 32), dim3(32, 8)>>>(wo, woh, F_, F_);

    cudaFuncSetAttribute(qkv_proj_kernel, cudaFuncAttributeMaxDynamicSharedMemorySize, SMEM_GEMM);
    cudaFuncSetAttribute(o_proj_kernel, cudaFuncAttributeMaxDynamicSharedMemorySize, SMEM_GEMM);

    // Merged Q/K/V projection (all 1-term, RoPE fused for Q,K; Q pre-scaled)
    qkv_proj_kernel<<<dim3(24, M / 128), 256, SMEM_GEMM>>>(
        xhi, wqh, wkh, wvh, bq, bk, bv, qhi, khi, vhi);

    // Flash attention (plain fp16 operands, fp32 accum)
    cudaFuncSetAttribute(flash_mma_kernel, cudaFuncAttributeMaxDynamicSharedMemorySize, SMEM_FLASH);
    flash_mma_kernel<<<dim3(S_ / 128, H_, B_), 256, SMEM_FLASH>>>();

    // Output projection (1-term, fp32 out)
    o_proj_kernel<<<dim3(F_ / 128, M / 128), 256, SMEM_GEMM>>>(ahi, woh, bo, out);
}

// round 13
// speedup vs baseline: 2.5005x; 1.0430x over previous
#include <cuda_runtime.h>
#include <cuda_fp16.h>
#include <cstdint>
#include <math.h>

// Problem constants
#define B_   4
#define S_   2048
#define F_   2048
#define H_   16
#define G_   4
#define DH_  128
#define ROT_ 32

#define MTOT (B_*S_)   // 8192
#define QSCALE 0.12751743f   // log2(e)/sqrt(128)

// ---------------------------------------------------------------------------
// Static scratch (fp16)
// ---------------------------------------------------------------------------
__device__ __align__(16) __half g_qhi[MTOT*F_];
__device__ __align__(16) __half g_khi[MTOT*G_*DH_];
__device__ __align__(16) __half g_vhi[MTOT*G_*DH_];
__device__ __align__(16) __half g_xhi[MTOT*F_];
__device__ __align__(16) __half g_ahi[MTOT*F_];
__device__ __align__(16) __half g_wqT_hi[F_*F_];
__device__ __align__(16) __half g_wkT_hi[G_*DH_*F_];
__device__ __align__(16) __half g_wvT_hi[G_*DH_*F_];
__device__ __align__(16) __half g_woT_hi[F_*F_];
__device__ float g_cos[S_*ROT_];
__device__ float g_sin[S_*ROT_];

// ---------------------------------------------------------------------------
// Baseline-legal PTX helpers (sm_80+)
// ---------------------------------------------------------------------------
__device__ __forceinline__ uint32_t smem_u32(const void* p) {
    uint32_t a;
    asm("{ .reg .u64 t; cvta.to.shared.u64 t, %1; cvt.u32.u64 %0, t; }" : "=r"(a) : "l"(p));
    return a;
}
__device__ __forceinline__ void ldsm_x4(uint32_t* r, uint32_t addr) {
    asm volatile("ldmatrix.sync.aligned.m8n8.x4.shared.b16 {%0,%1,%2,%3}, [%4];"
                 : "=r"(r[0]), "=r"(r[1]), "=r"(r[2]), "=r"(r[3]) : "r"(addr));
}
__device__ __forceinline__ void ldsm_x4_t(uint32_t* r, uint32_t addr) {
    asm volatile("ldmatrix.sync.aligned.m8n8.x4.trans.shared.b16 {%0,%1,%2,%3}, [%4];"
                 : "=r"(r[0]), "=r"(r[1]), "=r"(r[2]), "=r"(r[3]) : "r"(addr));
}
__device__ __forceinline__ void mma_f16(float* c, const uint32_t* a, uint32_t b0, uint32_t b1) {
    asm volatile("mma.sync.aligned.m16n8k16.row.col.f32.f16.f16.f32 "
                 "{%0,%1,%2,%3}, {%4,%5,%6,%7}, {%8,%9}, {%0,%1,%2,%3};"
                 : "+f"(c[0]), "+f"(c[1]), "+f"(c[2]), "+f"(c[3])
                 : "r"(a[0]), "r"(a[1]), "r"(a[2]), "r"(a[3]), "r"(b0), "r"(b1));
}
#define CP_ASYNC16(dst, src) \
    asm volatile("cp.async.cg.shared.global [%0], [%1], 16;" :: "r"(dst), "l"(src) : "memory")
#define CP_COMMIT()  asm volatile("cp.async.commit_group;" ::: "memory")
#define CP_WAIT(n)   asm volatile("cp.async.wait_group %0;" :: "n"(n) : "memory")

__device__ __forceinline__ uint32_t pack_h2(float a, float b) {
    __half2 h = __floats2half2_rn(a, b);
    return *(uint32_t*)&h;
}

// ---------------------------------------------------------------------------
// RoPE table init
// ---------------------------------------------------------------------------
__global__ void rope_init_kernel() {
    int idx = blockIdx.x * blockDim.x + threadIdx.x;
    if (idx < S_ * ROT_) {
        int t = idx >> 5, p = idx & 31;
        double freq = pow(10000.0, -((double)(2 * p)) / 64.0);
        double f = (double)t * freq;
        g_cos[idx] = (float)cos(f);
        g_sin[idx] = (float)sin(f);
    }
}

// ---------------------------------------------------------------------------
// fp32 -> fp16 convert (x input)
// ---------------------------------------------------------------------------
__global__ void convert_x_kernel(const float* __restrict__ src,
                                 __half* __restrict__ hi, int n4) {
    int i = blockIdx.x * blockDim.x + threadIdx.x;
    if (i >= n4) return;
    float4 v = ((const float4*)src)[i];
    uint2 o;
    o.x = pack_h2(v.x, v.y);
    o.y = pack_h2(v.z, v.w);
    ((uint2*)hi)[i] = o;
}

// ---------------------------------------------------------------------------
// Weight transpose:  W[K][N] fp32 -> T[N][K] fp16
// ---------------------------------------------------------------------------
__global__ void transpose_h_kernel(const float* __restrict__ W,
                                   __half* __restrict__ Thi,
                                   int K, int N) {
    __shared__ float t[32][33];
    int k0 = blockIdx.y * 32, n0 = blockIdx.x * 32;
    int tx = threadIdx.x, ty = threadIdx.y;   // 32 x 8
#pragma unroll
    for (int j = 0; j < 4; j++)
        t[ty + j * 8][tx] = W[(size_t)(k0 + ty + j * 8) * N + n0 + tx];
    __syncthreads();
#pragma unroll
    for (int j = 0; j < 4; j++) {
        int n = n0 + ty + j * 8, k = k0 + tx;
        Thi[(size_t)n * K + k] = __float2half_rn(t[tx][ty + j * 8]);
    }
}

// ---------------------------------------------------------------------------
// Shared GEMM body (fp16 1-term, fp32 accum). CTA tile 128x128, BK=32,
// 2-stage cp.async, 8 warps 2(M)x4(N).
// mode: 0 = fp32 out, 1 = Q (rope+scale, fp16), 2 = K (rope, fp16), 3 = V (fp16).
// ---------------------------------------------------------------------------
#define GBK    32
#define TSTR   40                         // smem row stride in fp16 (80 B)
#define TILE_BYTES (128 * TSTR * 2)       // 10240
#define STAGE_BYTES (2 * TILE_BYTES)      // A + B = 20480
#define SMEM_GEMM (2 * STAGE_BYTES)       // 40960

__device__ __forceinline__ void gemm_body(
    uint32_t smem_base, int tid,
    const __half* __restrict__ Ahi,
    const __half* __restrict__ BThi,
    const float* __restrict__ bias,
    float* __restrict__ C,
    __half* __restrict__ Chi,
    size_t rowBase, size_t colBase,
    int N, int K, int mode)
{
    const int wid = tid >> 5;
    const int lid = tid & 31;
    const int warpM = wid & 1;
    const int warpN = wid >> 1;

    const int NC = K / GBK;

    auto prefetch = [&](int stage, int k0) {
        uint32_t st = smem_base + stage * STAGE_BYTES;
#pragma unroll
        for (int t = 0; t < 2; t++) {
            int cidx = tid + t * 256;
            int r  = cidx >> 2;
            int ch = cidx & 3;
            uint32_t doff = r * (TSTR * 2) + ch * 16;
            size_t goffA = (rowBase + r) * (size_t)K + k0 + ch * 8;
            size_t goffB = (colBase + r) * (size_t)K + k0 + ch * 8;
            CP_ASYNC16(st + doff,              (const char*)(Ahi  + goffA));
            CP_ASYNC16(st + TILE_BYTES + doff, (const char*)(BThi + goffB));
        }
        CP_COMMIT();
    };

    float acc[4][4][4];
#pragma unroll
    for (int i = 0; i < 4; i++)
#pragma unroll
        for (int j = 0; j < 4; j++)
#pragma unroll
            for (int q = 0; q < 4; q++) acc[i][j][q] = 0.f;

    const int laneRow = (lid & 7) + ((lid >> 3) & 1) * 8;
    const int laneK   = (lid >> 4) * 8;

    prefetch(0, 0);

    for (int kc = 0; kc < NC; ++kc) {
        const int s = kc & 1;
        if (kc + 1 < NC) prefetch(s ^ 1, (kc + 1) * GBK);
        if (kc + 1 < NC) { CP_WAIT(1); } else { CP_WAIT(0); }
        __syncthreads();

        const uint32_t st = smem_base + s * STAGE_BYTES;
        const uint32_t aHib = st;
        const uint32_t bHib = st + TILE_BYTES;

#pragma unroll
        for (int k16 = 0; k16 < GBK; k16 += 16) {
            const int kk = k16 + laneK;
            uint32_t bH[2][4];
#pragma unroll
            for (int nt = 0; nt < 2; nt++) {
                int row = warpN * 32 + nt * 16 + laneRow;
                uint32_t off = (row * TSTR + kk) * 2;
                ldsm_x4(bH[nt], bHib + off);
            }
#pragma unroll
            for (int mp = 0; mp < 4; mp += 2) {
                uint32_t aH[2][4];
#pragma unroll
                for (int i = 0; i < 2; i++) {
                    int row = warpM * 64 + (mp + i) * 16 + laneRow;
                    uint32_t off = (row * TSTR + kk) * 2;
                    ldsm_x4(aH[i], aHib + off);
                }
#pragma unroll
                for (int i = 0; i < 2; i++)
#pragma unroll
                    for (int nt = 0; nt < 2; nt++) {
                        mma_f16(acc[mp+i][2*nt],   aH[i], bH[nt][0], bH[nt][2]);
                        mma_f16(acc[mp+i][2*nt+1], aH[i], bH[nt][1], bH[nt][3]);
                    }
            }
        }
        __syncthreads();
    }

    // Epilogue
#pragma unroll
    for (int mi = 0; mi < 4; mi++) {
#pragma unroll
        for (int nj = 0; nj < 4; nj++) {
            int row0 = (int)rowBase + warpM * 64 + mi * 16 + (lid >> 2);
            int row1 = row0 + 8;
            int col  = (int)colBase + warpN * 32 + nj * 8 + (lid & 3) * 2;
            float b0 = __ldg(bias + col), b1 = __ldg(bias + col + 1);
            float v0 = acc[mi][nj][0] + b0, v1 = acc[mi][nj][1] + b1;
            float v2 = acc[mi][nj][2] + b0, v3 = acc[mi][nj][3] + b1;
            int d = col & (DH_ - 1);
            if (mode >= 1 && mode <= 2 && d < 64) {   // RoPE for Q,K
                int p = d >> 1;
                int s0 = row0 & (S_ - 1);
                int s1 = row1 & (S_ - 1);
                float c0 = g_cos[s0 * ROT_ + p], sn0 = g_sin[s0 * ROT_ + p];
                float c1 = g_cos[s1 * ROT_ + p], sn1 = g_sin[s1 * ROT_ + p];
                float a0 = v0, bb0 = v1, a1 = v2, bb1 = v3;
                v0 = a0 * c0 - bb0 * sn0;  v1 = bb0 * c0 + a0 * sn0;
                v2 = a1 * c1 - bb1 * sn1;  v3 = bb1 * c1 + a1 * sn1;
            }
            if (mode == 0) {
                *(float2*)(C + (size_t)row0 * N + col) = make_float2(v0, v1);
                *(float2*)(C + (size_t)row1 * N + col) = make_float2(v2, v3);
            } else {
                if (mode == 1) { v0 *= QSCALE; v1 *= QSCALE; v2 *= QSCALE; v3 *= QSCALE; }
                *(uint32_t*)(Chi + (size_t)row0 * N + col) = pack_h2(v0, v1);
                *(uint32_t*)(Chi + (size_t)row1 * N + col) = pack_h2(v2, v3);
            }
        }
    }
}

// ---------------------------------------------------------------------------
// Merged Q/K/V projection: grid (24, 64). bx<16 -> Q, 16..19 -> K, 20..23 -> V.
// ---------------------------------------------------------------------------
__global__ __launch_bounds__(256, 2)
void qkv_proj_kernel(const __half* __restrict__ xhi,
                     const __half* __restrict__ wq,
                     const __half* __restrict__ wk,
                     const __half* __restrict__ wv,
                     const float* __restrict__ bq,
                     const float* __restrict__ bk,
                     const float* __restrict__ bv,
                     __half* __restrict__ qout,
                     __half* __restrict__ kout,
                     __half* __restrict__ vout)
{
    extern __shared__ char smem[];
    const uint32_t smem_base = smem_u32(smem);
    const int bx = blockIdx.x;
    const size_t rowBase = (size_t)blockIdx.y * 128;

    const __half* B;
    const float* bias;
    __half* Chi;
    size_t colBase;
    int N, mode;
    if (bx < 16)      { B = wq; bias = bq; Chi = qout; colBase = (size_t)bx * 128;        N = F_;       mode = 1; }
    else if (bx < 20) { B = wk; bias = bk; Chi = kout; colBase = (size_t)(bx - 16) * 128; N = G_ * DH_; mode = 2; }
    else              { B = wv; bias = bv; Chi = vout; colBase = (size_t)(bx - 20) * 128; N = G_ * DH_; mode = 3; }

    gemm_body(smem_base, threadIdx.x, xhi, B, bias, nullptr, Chi,
              rowBase, colBase, N, F_, mode);
}

// ---------------------------------------------------------------------------
// O projection (fp32 out)
// ---------------------------------------------------------------------------
__global__ __launch_bounds__(256, 2)
void o_proj_kernel(const __half* __restrict__ ahi,
                   const __half* __restrict__ wo,
                   const float* __restrict__ bo,
                   float* __restrict__ out)
{
    extern __shared__ char smem[];
    const uint32_t smem_base = smem_u32(smem);
    gemm_body(smem_base, threadIdx.x, ahi, wo, bo, out, nullptr,
              (size_t)blockIdx.y * 128, (size_t)blockIdx.x * 128, F_, F_, 0);
}

// ---------------------------------------------------------------------------
// Tensor-core flash attention (fp16 operands, fp32 accum, causal, GQA).
// CTA: 128 q rows x 128 kv cols per block (wide KV block halves softmax passes).
// 8 warps x 16 q rows.
// ---------------------------------------------------------------------------
#define FSTR   272                 // bytes per smem row (128 fp16 + 8 pad)
#define FTILEB (64 * FSTR)         // 17408 bytes per 64-row tile
#define FQOFF  (8 * FTILEB)        // Q after 2 KV stages (4 tiles each: K2+V2)
#define SMEM_FLASH (10 * FTILEB)   // 174080

__global__ __launch_bounds__(256)
void flash_mma_kernel()
{
    extern __shared__ char fsm[];
    const uint32_t sb = smem_u32(fsm);
    const int tid = threadIdx.x;
    const int wid = tid >> 5;
    const int lid = tid & 31;
    const int qb  = 15 - (int)blockIdx.x;   // big tiles first
    const int h   = blockIdx.y;
    const int b   = blockIdx.z;
    const int g   = h >> 2;
    const int qbase = qb * 128;

    // Q: 128 rows x 128 fp16
#pragma unroll
    for (int i = 0; i < 8; i++) {
        int q = tid + i * 256;
        int r = q >> 4, ch = q & 15;
        size_t off = (((size_t)(b * S_ + qbase + r)) * H_ + h) * DH_ + ch * 8;
        uint32_t dst = sb + FQOFF + r * FSTR + ch * 16;
        CP_ASYNC16(dst, (const char*)(g_qhi + off));
    }
    CP_COMMIT();
    CP_WAIT(0);
    __syncthreads();

    // KV prefetch: 128 rows K + 128 rows V per stage
    auto prefetch = [&](int jblk, int stage) {
        uint32_t st = sb + stage * 4 * FTILEB;
        size_t base = (((size_t)(b * S_ + jblk * 128)) * G_ + g) * DH_;
#pragma unroll
        for (int i = 0; i < 8; i++) {
            int q = tid + i * 256;      // 0..2047
            int r = q >> 4, ch = q & 15;
            size_t off = base + (size_t)r * (G_ * DH_) + ch * 8;
            uint32_t d = st + r * FSTR + ch * 16;
            CP_ASYNC16(d,              (const char*)(g_khi + off));
            CP_ASYNC16(d + 2*FTILEB,   (const char*)(g_vhi + off));
        }
        CP_COMMIT();
    };

    float O[16][4];
#pragma unroll
    for (int i = 0; i < 16; i++)
#pragma unroll
        for (int q = 0; q < 4; q++) O[i][q] = 0.f;
    float m2[2] = {-1e30f, -1e30f};
    float l2[2] = {0.f, 0.f};

    const int nblocks = qb + 1;
    prefetch(0, 0);

    const uint32_t qaddrH = sb + FQOFF + (wid * 16 + (lid & 15)) * FSTR + (lid >> 4) * 16;
    const uint32_t lanebase = (lid & 15) * FSTR + (lid >> 4) * 16;
    const int warpRow0 = qbase + wid * 16;

    for (int j = 0; j < nblocks; j++) {
        const int st = j & 1;
        if (j + 1 < nblocks) { prefetch(j + 1, st ^ 1); CP_WAIT(1); }
        else                 { CP_WAIT(0); }
        __syncthreads();

        const uint32_t kH = sb + st * 4 * FTILEB + lanebase;

        // S = Q K^T over a 128-wide KV block
        float sacc[16][4];
#pragma unroll
        for (int nb = 0; nb < 16; nb++)
#pragma unroll
            for (int q = 0; q < 4; q++) sacc[nb][q] = 0.f;

#pragma unroll
        for (int kc = 0; kc < 8; kc++) {
            uint32_t qh[4];
            ldsm_x4(qh, qaddrH + kc * 32);
#pragma unroll
            for (int n16 = 0; n16 < 8; n16++) {
                uint32_t rH[4];
                ldsm_x4(rH, kH + n16 * (16 * FSTR) + kc * 32);
                mma_f16(sacc[2*n16],   qh, rH[0], rH[2]);
                mma_f16(sacc[2*n16+1], qh, rH[1], rH[3]);
            }
        }

        // causal mask (block straddling the diagonal)
        if (j * 128 + 127 > warpRow0) {
#pragma unroll
            for (int nb = 0; nb < 16; nb++)
#pragma unroll
                for (int q = 0; q < 4; q++) {
                    int col = j * 128 + nb * 8 + (lid & 3) * 2 + (q & 1);
                    int row = warpRow0 + (lid >> 2) + (q >> 1) * 8;
                    if (col > row) sacc[nb][q] = -1e30f;
                }
        }

        // online softmax (one update per 128-wide block)
#pragma unroll
        for (int rh = 0; rh < 2; rh++) {
            float rmax = -1e30f;
#pragma unroll
            for (int nb = 0; nb < 16; nb++)
                rmax = fmaxf(rmax, fmaxf(sacc[nb][rh*2], sacc[nb][rh*2+1]));
            rmax = fmaxf(rmax, __shfl_xor_sync(0xffffffffu, rmax, 1));
            rmax = fmaxf(rmax, __shfl_xor_sync(0xffffffffu, rmax, 2));
            float mnew = fmaxf(m2[rh], rmax);
            float alpha = exp2f(m2[rh] - mnew);
            float rsum = 0.f;
#pragma unroll
            for (int nb = 0; nb < 16; nb++) {
                float p0 = exp2f(sacc[nb][rh*2]   - mnew);
                float p1 = exp2f(sacc[nb][rh*2+1] - mnew);
                sacc[nb][rh*2] = p0; sacc[nb][rh*2+1] = p1;
                rsum += p0 + p1;
            }
            rsum += __shfl_xor_sync(0xffffffffu, rsum, 1);
            rsum += __shfl_xor_sync(0xffffffffu, rsum, 2);
            l2[rh] = l2[rh] * alpha + rsum;
            m2[rh] = mnew;
#pragma unroll
            for (int nb = 0; nb < 16; nb++) {
                O[nb][rh*2]   *= alpha;
                O[nb][rh*2+1] *= alpha;
            }
        }

        // P fragments (8 k16 chunks across the 128 kv positions)
        uint32_t ph[8][4];
#pragma unroll
        for (int kc = 0; kc < 8; kc++)
#pragma unroll
            for (int t = 0; t < 4; t++) {
                int nb = 2*kc + (t >> 1);
                ph[kc][t] = pack_h2(sacc[nb][(t & 1) * 2], sacc[nb][(t & 1) * 2 + 1]);
            }

        const uint32_t vbase = sb + st * 4 * FTILEB + 2*FTILEB + lanebase;
#pragma unroll
        for (int kc = 0; kc < 8; kc++) {
            uint32_t vrow = vbase + kc * (16 * FSTR);
#pragma unroll
            for (int ng = 0; ng < 8; ng++) {
                uint32_t vh[4];
                ldsm_x4_t(vh, vrow + ng * 32);
                mma_f16(O[2*ng],   ph[kc], vh[0], vh[1]);
                mma_f16(O[2*ng+1], ph[kc], vh[2], vh[3]);
            }
        }
        __syncthreads();
    }

    // Epilogue: normalize, write fp16
    const float inv0 = 1.f / l2[0];
    const float inv1 = 1.f / l2[1];
    const int r0 = qbase + wid * 16 + (lid >> 2);
#pragma unroll
    for (int nb = 0; nb < 16; nb++) {
        int col = h * DH_ + nb * 8 + (lid & 3) * 2;
        size_t base0 = ((size_t)(b * S_ + r0)) * F_ + col;
        size_t base1 = ((size_t)(b * S_ + r0 + 8)) * F_ + col;
        *(uint32_t*)(g_ahi + base0) = pack_h2(O[nb][0] * inv0, O[nb][1] * inv0);
        *(uint32_t*)(g_ahi + base1) = pack_h2(O[nb][2] * inv1, O[nb][3] * inv1);
    }
}

// ---------------------------------------------------------------------------
extern "C" void kernel_launch(void* const* d_in, const int* in_sizes, int n_in,
                              void* d_out, int out_size)
{
    const float* x  = (const float*)d_in[0];
    const float* wq = (const float*)d_in[1];
    const float* bq = (const float*)d_in[2];
    const float* wk = (const float*)d_in[3];
    const float* bk = (const float*)d_in[4];
    const float* wv = (const float*)d_in[5];
    const float* bv = (const float*)d_in[6];
    const float* wo = (const float*)d_in[7];
    const float* bo = (const float*)d_in[8];
    float* out = (float*)d_out;

    __half *xhi, *ahi;
    cudaGetSymbolAddress((void**)&xhi, g_xhi);
    cudaGetSymbolAddress((void**)&ahi, g_ahi);
    __half *qhi, *khi, *vhi;
    cudaGetSymbolAddress((void**)&qhi, g_qhi);
    cudaGetSymbolAddress((void**)&khi, g_khi);
    cudaGetSymbolAddress((void**)&vhi, g_vhi);
    __half *wqh, *wkh, *wvh, *woh;
    cudaGetSymbolAddress((void**)&wqh, g_wqT_hi);
    cudaGetSymbolAddress((void**)&wkh, g_wkT_hi);
    cudaGetSymbolAddress((void**)&wvh, g_wvT_hi);
    cudaGetSymbolAddress((void**)&woh, g_woT_hi);

    const int M = MTOT;       // 8192
    const int NKV = G_ * DH_; // 512

    rope_init_kernel<<<(S_ * ROT_ + 255) / 256, 256>>>();

    convert_x_kernel<<<(M * F_ / 4 + 255) / 256, 256>>>(x, xhi, M * F_ / 4);

    transpose_h_kernel<<<dim3(F_ / 32, F_ / 32), dim3(32, 8)>>>(wq, wqh, F_, F_);
    transpose_h_kernel<<<dim3(NKV / 32, F_ / 32), dim3(32, 8)>>>(wk, wkh, F_, NKV);
    transpose_h_kernel<<<dim3(NKV / 32, F_ / 32), dim3(32, 8)>>>(wv, wvh, F_, NKV);
    transpose_h_kernel<<<dim3(F_ / 32, F_ / 32), dim3(32, 8)>>>(wo, woh, F_, F_);

    cudaFuncSetAttribute(qkv_proj_kernel, cudaFuncAttributeMaxDynamicSharedMemorySize, SMEM_GEMM);
    cudaFuncSetAttribute(o_proj_kernel, cudaFuncAttributeMaxDynamicSharedMemorySize, SMEM_GEMM);

    // Merged Q/K/V projection (all 1-term, RoPE fused for Q,K; Q pre-scaled)
    qkv_proj_kernel<<<dim3(24, M / 128), 256, SMEM_GEMM>>>(
        xhi, wqh, wkh, wvh, bq, bk, bv, qhi, khi, vhi);

    // Flash attention (128-wide KV blocks)
    cudaFuncSetAttribute(flash_mma_kernel, cudaFuncAttributeMaxDynamicSharedMemorySize, SMEM_FLASH);
    flash_mma_kernel<<<dim3(S_ / 128, H_, B_), 256, SMEM_FLASH>>>();

    // Output projection (1-term, fp32 out)
    o_proj_kernel<<<dim3(F_ / 128, M / 128), 256, SMEM_GEMM>>>(ahi, woh, bo, out);
}

// round 14
// speedup vs baseline: 2.5194x; 1.0075x over previous
#include <cuda_runtime.h>
#include <cuda_fp16.h>
#include <cstdint>
#include <math.h>

// Problem constants
#define B_   4
#define S_   2048
#define F_   2048
#define H_   16
#define G_   4
#define DH_  128
#define ROT_ 32

#define MTOT (B_*S_)   // 8192
#define QSCALE 0.12751743f   // log2(e)/sqrt(128)

// ---------------------------------------------------------------------------
// Static scratch (fp16)
// ---------------------------------------------------------------------------
__device__ __align__(16) __half g_qhi[MTOT*F_];
__device__ __align__(16) __half g_khi[MTOT*G_*DH_];
__device__ __align__(16) __half g_vhi[MTOT*G_*DH_];
__device__ __align__(16) __half g_xhi[MTOT*F_];
__device__ __align__(16) __half g_ahi[MTOT*F_];
__device__ __align__(16) __half g_wqT_hi[F_*F_];
__device__ __align__(16) __half g_wkT_hi[G_*DH_*F_];
__device__ __align__(16) __half g_wvT_hi[G_*DH_*F_];
__device__ __align__(16) __half g_woT_hi[F_*F_];
__device__ float g_cos[S_*ROT_];
__device__ float g_sin[S_*ROT_];

// ---------------------------------------------------------------------------
// Baseline-legal PTX helpers (sm_80+)
// ---------------------------------------------------------------------------
__device__ __forceinline__ uint32_t smem_u32(const void* p) {
    uint32_t a;
    asm("{ .reg .u64 t; cvta.to.shared.u64 t, %1; cvt.u32.u64 %0, t; }" : "=r"(a) : "l"(p));
    return a;
}
__device__ __forceinline__ void ldsm_x4(uint32_t* r, uint32_t addr) {
    asm volatile("ldmatrix.sync.aligned.m8n8.x4.shared.b16 {%0,%1,%2,%3}, [%4];"
                 : "=r"(r[0]), "=r"(r[1]), "=r"(r[2]), "=r"(r[3]) : "r"(addr));
}
__device__ __forceinline__ void ldsm_x4_t(uint32_t* r, uint32_t addr) {
    asm volatile("ldmatrix.sync.aligned.m8n8.x4.trans.shared.b16 {%0,%1,%2,%3}, [%4];"
                 : "=r"(r[0]), "=r"(r[1]), "=r"(r[2]), "=r"(r[3]) : "r"(addr));
}
__device__ __forceinline__ void mma_f16(float* c, const uint32_t* a, uint32_t b0, uint32_t b1) {
    asm volatile("mma.sync.aligned.m16n8k16.row.col.f32.f16.f16.f32 "
                 "{%0,%1,%2,%3}, {%4,%5,%6,%7}, {%8,%9}, {%0,%1,%2,%3};"
                 : "+f"(c[0]), "+f"(c[1]), "+f"(c[2]), "+f"(c[3])
                 : "r"(a[0]), "r"(a[1]), "r"(a[2]), "r"(a[3]), "r"(b0), "r"(b1));
}
#define CP_ASYNC16(dst, src) \
    asm volatile("cp.async.cg.shared.global [%0], [%1], 16;" :: "r"(dst), "l"(src) : "memory")
#define CP_COMMIT()  asm volatile("cp.async.commit_group;" ::: "memory")
#define CP_WAIT(n)   asm volatile("cp.async.wait_group %0;" :: "n"(n) : "memory")

__device__ __forceinline__ uint32_t pack_h2(float a, float b) {
    __half2 h = __floats2half2_rn(a, b);
    return *(uint32_t*)&h;
}

// ---------------------------------------------------------------------------
// RoPE table init
// ---------------------------------------------------------------------------
__global__ void rope_init_kernel() {
    int idx = blockIdx.x * blockDim.x + threadIdx.x;
    if (idx < S_ * ROT_) {
        int t = idx >> 5, p = idx & 31;
        double freq = pow(10000.0, -((double)(2 * p)) / 64.0);
        double f = (double)t * freq;
        g_cos[idx] = (float)cos(f);
        g_sin[idx] = (float)sin(f);
    }
}

// ---------------------------------------------------------------------------
// fp32 -> fp16 convert (x input)
// ---------------------------------------------------------------------------
__global__ void convert_x_kernel(const float* __restrict__ src,
                                 __half* __restrict__ hi, int n4) {
    int i = blockIdx.x * blockDim.x + threadIdx.x;
    if (i >= n4) return;
    float4 v = ((const float4*)src)[i];
    uint2 o;
    o.x = pack_h2(v.x, v.y);
    o.y = pack_h2(v.z, v.w);
    ((uint2*)hi)[i] = o;
}

// ---------------------------------------------------------------------------
// Weight transpose:  W[K][N] fp32 -> T[N][K] fp16
// ---------------------------------------------------------------------------
__global__ void transpose_h_kernel(const float* __restrict__ W,
                                   __half* __restrict__ Thi,
                                   int K, int N) {
    __shared__ float t[32][33];
    int k0 = blockIdx.y * 32, n0 = blockIdx.x * 32;
    int tx = threadIdx.x, ty = threadIdx.y;   // 32 x 8
#pragma unroll
    for (int j = 0; j < 4; j++)
        t[ty + j * 8][tx] = W[(size_t)(k0 + ty + j * 8) * N + n0 + tx];
    __syncthreads();
#pragma unroll
    for (int j = 0; j < 4; j++) {
        int n = n0 + ty + j * 8, k = k0 + tx;
        Thi[(size_t)n * K + k] = __float2half_rn(t[tx][ty + j * 8]);
    }
}

// ---------------------------------------------------------------------------
// Shared GEMM body (fp16 1-term, fp32 accum). CTA tile 128x128, BK=32,
// 2-stage cp.async, 8 warps 2(M)x4(N).
// mode: 0 = fp32 out, 1 = Q (rope+scale, fp16), 2 = K (rope, fp16), 3 = V (fp16).
// ---------------------------------------------------------------------------
#define GBK    32
#define TSTR   40                         // smem row stride in fp16 (80 B)
#define TILE_BYTES (128 * TSTR * 2)       // 10240
#define STAGE_BYTES (2 * TILE_BYTES)      // A + B = 20480
#define SMEM_GEMM (2 * STAGE_BYTES)       // 40960

__device__ __forceinline__ void gemm_body(
    uint32_t smem_base, int tid,
    const __half* __restrict__ Ahi,
    const __half* __restrict__ BThi,
    const float* __restrict__ bias,
    float* __restrict__ C,
    __half* __restrict__ Chi,
    size_t rowBase, size_t colBase,
    int N, int K, int mode)
{
    const int wid = tid >> 5;
    const int lid = tid & 31;
    const int warpM = wid & 1;
    const int warpN = wid >> 1;

    const int NC = K / GBK;

    auto prefetch = [&](int stage, int k0) {
        uint32_t st = smem_base + stage * STAGE_BYTES;
#pragma unroll
        for (int t = 0; t < 2; t++) {
            int cidx = tid + t * 256;
            int r  = cidx >> 2;
            int ch = cidx & 3;
            uint32_t doff = r * (TSTR * 2) + ch * 16;
            size_t goffA = (rowBase + r) * (size_t)K + k0 + ch * 8;
            size_t goffB = (colBase + r) * (size_t)K + k0 + ch * 8;
            CP_ASYNC16(st + doff,              (const char*)(Ahi  + goffA));
            CP_ASYNC16(st + TILE_BYTES + doff, (const char*)(BThi + goffB));
        }
        CP_COMMIT();
    };

    float acc[4][4][4];
#pragma unroll
    for (int i = 0; i < 4; i++)
#pragma unroll
        for (int j = 0; j < 4; j++)
#pragma unroll
            for (int q = 0; q < 4; q++) acc[i][j][q] = 0.f;

    const int laneRow = (lid & 7) + ((lid >> 3) & 1) * 8;
    const int laneK   = (lid >> 4) * 8;

    prefetch(0, 0);

    for (int kc = 0; kc < NC; ++kc) {
        const int s = kc & 1;
        if (kc + 1 < NC) prefetch(s ^ 1, (kc + 1) * GBK);
        if (kc + 1 < NC) { CP_WAIT(1); } else { CP_WAIT(0); }
        __syncthreads();

        const uint32_t st = smem_base + s * STAGE_BYTES;
        const uint32_t aHib = st;
        const uint32_t bHib = st + TILE_BYTES;

#pragma unroll
        for (int k16 = 0; k16 < GBK; k16 += 16) {
            const int kk = k16 + laneK;
            uint32_t bH[2][4];
#pragma unroll
            for (int nt = 0; nt < 2; nt++) {
                int row = warpN * 32 + nt * 16 + laneRow;
                uint32_t off = (row * TSTR + kk) * 2;
                ldsm_x4(bH[nt], bHib + off);
            }
#pragma unroll
            for (int mp = 0; mp < 4; mp += 2) {
                uint32_t aH[2][4];
#pragma unroll
                for (int i = 0; i < 2; i++) {
                    int row = warpM * 64 + (mp + i) * 16 + laneRow;
                    uint32_t off = (row * TSTR + kk) * 2;
                    ldsm_x4(aH[i], aHib + off);
                }
#pragma unroll
                for (int i = 0; i < 2; i++)
#pragma unroll
                    for (int nt = 0; nt < 2; nt++) {
                        mma_f16(acc[mp+i][2*nt],   aH[i], bH[nt][0], bH[nt][2]);
                        mma_f16(acc[mp+i][2*nt+1], aH[i], bH[nt][1], bH[nt][3]);
                    }
            }
        }
        __syncthreads();
    }

    // Epilogue
#pragma unroll
    for (int mi = 0; mi < 4; mi++) {
#pragma unroll
        for (int nj = 0; nj < 4; nj++) {
            int row0 = (int)rowBase + warpM * 64 + mi * 16 + (lid >> 2);
            int row1 = row0 + 8;
            int col  = (int)colBase + warpN * 32 + nj * 8 + (lid & 3) * 2;
            float b0 = __ldg(bias + col), b1 = __ldg(bias + col + 1);
            float v0 = acc[mi][nj][0] + b0, v1 = acc[mi][nj][1] + b1;
            float v2 = acc[mi][nj][2] + b0, v3 = acc[mi][nj][3] + b1;
            int d = col & (DH_ - 1);
            if (mode >= 1 && mode <= 2 && d < 64) {   // RoPE for Q,K
                int p = d >> 1;
                int s0 = row0 & (S_ - 1);
                int s1 = row1 & (S_ - 1);
                float c0 = g_cos[s0 * ROT_ + p], sn0 = g_sin[s0 * ROT_ + p];
                float c1 = g_cos[s1 * ROT_ + p], sn1 = g_sin[s1 * ROT_ + p];
                float a0 = v0, bb0 = v1, a1 = v2, bb1 = v3;
                v0 = a0 * c0 - bb0 * sn0;  v1 = bb0 * c0 + a0 * sn0;
                v2 = a1 * c1 - bb1 * sn1;  v3 = bb1 * c1 + a1 * sn1;
            }
            if (mode == 0) {
                *(float2*)(C + (size_t)row0 * N + col) = make_float2(v0, v1);
                *(float2*)(C + (size_t)row1 * N + col) = make_float2(v2, v3);
            } else {
                if (mode == 1) { v0 *= QSCALE; v1 *= QSCALE; v2 *= QSCALE; v3 *= QSCALE; }
                *(uint32_t*)(Chi + (size_t)row0 * N + col) = pack_h2(v0, v1);
                *(uint32_t*)(Chi + (size_t)row1 * N + col) = pack_h2(v2, v3);
            }
        }
    }
}

// ---------------------------------------------------------------------------
// Merged Q/K/V projection: grid (24, 64). bx<16 -> Q, 16..19 -> K, 20..23 -> V.
// ---------------------------------------------------------------------------
__global__ __launch_bounds__(256, 2)
void qkv_proj_kernel(const __half* __restrict__ xhi,
                     const __half* __restrict__ wq,
                     const __half* __restrict__ wk,
                     const __half* __restrict__ wv,
                     const float* __restrict__ bq,
                     const float* __restrict__ bk,
                     const float* __restrict__ bv,
                     __half* __restrict__ qout,
                     __half* __restrict__ kout,
                     __half* __restrict__ vout)
{
    extern __shared__ char smem[];
    const uint32_t smem_base = smem_u32(smem);
    const int bx = blockIdx.x;
    const size_t rowBase = (size_t)blockIdx.y * 128;

    const __half* B;
    const float* bias;
    __half* Chi;
    size_t colBase;
    int N, mode;
    if (bx < 16)      { B = wq; bias = bq; Chi = qout; colBase = (size_t)bx * 128;        N = F_;       mode = 1; }
    else if (bx < 20) { B = wk; bias = bk; Chi = kout; colBase = (size_t)(bx - 16) * 128; N = G_ * DH_; mode = 2; }
    else              { B = wv; bias = bv; Chi = vout; colBase = (size_t)(bx - 20) * 128; N = G_ * DH_; mode = 3; }

    gemm_body(smem_base, threadIdx.x, xhi, B, bias, nullptr, Chi,
              rowBase, colBase, N, F_, mode);
}

// ---------------------------------------------------------------------------
// O projection (fp32 out)
// ---------------------------------------------------------------------------
__global__ __launch_bounds__(256, 2)
void o_proj_kernel(const __half* __restrict__ ahi,
                   const __half* __restrict__ wo,
                   const float* __restrict__ bo,
                   float* __restrict__ out)
{
    extern __shared__ char smem[];
    const uint32_t smem_base = smem_u32(smem);
    gemm_body(smem_base, threadIdx.x, ahi, wo, bo, out, nullptr,
              (size_t)blockIdx.y * 128, (size_t)blockIdx.x * 128, F_, F_, 0);
}

// ---------------------------------------------------------------------------
// Tensor-core flash attention (fp16 operands, fp32 accum, causal, GQA).
// CTA: 64 q rows x 128 kv cols, 4 warps (128 threads), single KV buffer,
// 2 CTAs/SM for cross-CTA phase overlap (MMA of one covers softmax of other).
// ---------------------------------------------------------------------------
#define FSTR   272                 // bytes per smem row (128 fp16 + 8 pad)
#define FTILEB (64 * FSTR)         // 17408 bytes per 64-row tile
#define FKOFF  0                   // K: 128 rows (2 tiles)
#define FVOFF  (2 * FTILEB)        // V: 128 rows (2 tiles)
#define FQOFF  (4 * FTILEB)        // Q: 64 rows  (1 tile)
#define SMEM_FLASH (5 * FTILEB)    // 87040 -> 2 CTAs/SM

__global__ __launch_bounds__(128)
void flash_mma_kernel()
{
    extern __shared__ char fsm[];
    const uint32_t sb = smem_u32(fsm);
    const int tid = threadIdx.x;
    const int wid = tid >> 5;       // 0..3
    const int lid = tid & 31;
    const int qb  = 31 - (int)blockIdx.x;   // 64-row q tile; big tiles first
    const int h   = blockIdx.y;
    const int b   = blockIdx.z;
    const int g   = h >> 2;
    const int qbase = qb * 64;

    // Q: 64 rows x 128 fp16 = 1024 chunks; 128 threads x 8
#pragma unroll
    for (int i = 0; i < 8; i++) {
        int q = tid + i * 128;
        int r = q >> 4, ch = q & 15;
        size_t off = (((size_t)(b * S_ + qbase + r)) * H_ + h) * DH_ + ch * 8;
        CP_ASYNC16(sb + FQOFF + r * FSTR + ch * 16, (const char*)(g_qhi + off));
    }
    CP_COMMIT();
    CP_WAIT(0);

    float O[16][4];
#pragma unroll
    for (int i = 0; i < 16; i++)
#pragma unroll
        for (int q = 0; q < 4; q++) O[i][q] = 0.f;
    float m2[2] = {-1e30f, -1e30f};
    float l2[2] = {0.f, 0.f};

    const int nblocks = qb / 2 + 1;   // 128-wide kv blocks covering rows <= qbase+63

    const uint32_t qaddrH = sb + FQOFF + (wid * 16 + (lid & 15)) * FSTR + (lid >> 4) * 16;
    const uint32_t lanebase = (lid & 15) * FSTR + (lid >> 4) * 16;
    const int warpRow0 = qbase + wid * 16;

    for (int j = 0; j < nblocks; j++) {
        __syncthreads();   // previous iteration done reading K/V
        // load K,V block (128 rows each): 2048 chunks x2; 128 threads x16 each
        {
            size_t base = (((size_t)(b * S_ + j * 128)) * G_ + g) * DH_;
#pragma unroll
            for (int i = 0; i < 16; i++) {
                int q = tid + i * 128;
                int r = q >> 4, ch = q & 15;
                size_t off = base + (size_t)r * (G_ * DH_) + ch * 8;
                uint32_t d = r * FSTR + ch * 16;
                CP_ASYNC16(sb + FKOFF + d, (const char*)(g_khi + off));
                CP_ASYNC16(sb + FVOFF + d, (const char*)(g_vhi + off));
            }
            CP_COMMIT();
            CP_WAIT(0);
        }
        __syncthreads();

        const uint32_t kH = sb + FKOFF + lanebase;

        float sacc[16][4];
#pragma unroll
        for (int nb = 0; nb < 16; nb++)
#pragma unroll
            for (int q = 0; q < 4; q++) sacc[nb][q] = 0.f;

#pragma unroll
        for (int kc = 0; kc < 8; kc++) {
            uint32_t qh[4];
            ldsm_x4(qh, qaddrH + kc * 32);
#pragma unroll
            for (int n16 = 0; n16 < 8; n16++) {
                uint32_t rH[4];
                ldsm_x4(rH, kH + n16 * (16 * FSTR) + kc * 32);
                mma_f16(sacc[2*n16],   qh, rH[0], rH[2]);
                mma_f16(sacc[2*n16+1], qh, rH[1], rH[3]);
            }
        }

        // causal mask
        if (j * 128 + 127 > warpRow0) {
#pragma unroll
            for (int nb = 0; nb < 16; nb++)
#pragma unroll
                for (int q = 0; q < 4; q++) {
                    int col = j * 128 + nb * 8 + (lid & 3) * 2 + (q & 1);
                    int row = warpRow0 + (lid >> 2) + (q >> 1) * 8;
                    if (col > row) sacc[nb][q] = -1e30f;
                }
        }

        // online softmax
#pragma unroll
        for (int rh = 0; rh < 2; rh++) {
            float rmax = -1e30f;
#pragma unroll
            for (int nb = 0; nb < 16; nb++)
                rmax = fmaxf(rmax, fmaxf(sacc[nb][rh*2], sacc[nb][rh*2+1]));
            rmax = fmaxf(rmax, __shfl_xor_sync(0xffffffffu, rmax, 1));
            rmax = fmaxf(rmax, __shfl_xor_sync(0xffffffffu, rmax, 2));
            float mnew = fmaxf(m2[rh], rmax);
            float alpha = exp2f(m2[rh] - mnew);
            float rsum = 0.f;
#pragma unroll
            for (int nb = 0; nb < 16; nb++) {
                float p0 = exp2f(sacc[nb][rh*2]   - mnew);
                float p1 = exp2f(sacc[nb][rh*2+1] - mnew);
                sacc[nb][rh*2] = p0; sacc[nb][rh*2+1] = p1;
                rsum += p0 + p1;
            }
            rsum += __shfl_xor_sync(0xffffffffu, rsum, 1);
            rsum += __shfl_xor_sync(0xffffffffu, rsum, 2);
            l2[rh] = l2[rh] * alpha + rsum;
            m2[rh] = mnew;
#pragma unroll
            for (int nb = 0; nb < 16; nb++) {
                O[nb][rh*2]   *= alpha;
                O[nb][rh*2+1] *= alpha;
            }
        }

        // P fragments
        uint32_t ph[8][4];
#pragma unroll
        for (int kc = 0; kc < 8; kc++)
#pragma unroll
            for (int t = 0; t < 4; t++) {
                int nb = 2*kc + (t >> 1);
                ph[kc][t] = pack_h2(sacc[nb][(t & 1) * 2], sacc[nb][(t & 1) * 2 + 1]);
            }

        const uint32_t vb = sb + FVOFF + lanebase;
#pragma unroll
        for (int kc = 0; kc < 8; kc++) {
            uint32_t vrow = vb + kc * (16 * FSTR);
#pragma unroll
            for (int ng = 0; ng < 8; ng++) {
                uint32_t vh[4];
                ldsm_x4_t(vh, vrow + ng * 32);
                mma_f16(O[2*ng],   ph[kc], vh[0], vh[1]);
                mma_f16(O[2*ng+1], ph[kc], vh[2], vh[3]);
            }
        }
    }

    // Epilogue: normalize, write fp16
    const float inv0 = 1.f / l2[0];
    const float inv1 = 1.f / l2[1];
    const int r0 = qbase + wid * 16 + (lid >> 2);
#pragma unroll
    for (int nb = 0; nb < 16; nb++) {
        int col = h * DH_ + nb * 8 + (lid & 3) * 2;
        size_t base0 = ((size_t)(b * S_ + r0)) * F_ + col;
        size_t base1 = ((size_t)(b * S_ + r0 + 8)) * F_ + col;
        *(uint32_t*)(g_ahi + base0) = pack_h2(O[nb][0] * inv0, O[nb][1] * inv0);
        *(uint32_t*)(g_ahi + base1) = pack_h2(O[nb][2] * inv1, O[nb][3] * inv1);
    }
}

// ---------------------------------------------------------------------------
extern "C" void kernel_launch(void* const* d_in, const int* in_sizes, int n_in,
                              void* d_out, int out_size)
{
    const float* x  = (const float*)d_in[0];
    const float* wq = (const float*)d_in[1];
    const float* bq = (const float*)d_in[2];
    const float* wk = (const float*)d_in[3];
    const float* bk = (const float*)d_in[4];
    const float* wv = (const float*)d_in[5];
    const float* bv = (const float*)d_in[6];
    const float* wo = (const float*)d_in[7];
    const float* bo = (const float*)d_in[8];
    float* out = (float*)d_out;

    __half *xhi, *ahi;
    cudaGetSymbolAddress((void**)&xhi, g_xhi);
    cudaGetSymbolAddress((void**)&ahi, g_ahi);
    __half *qhi, *khi, *vhi;
    cudaGetSymbolAddress((void**)&qhi, g_qhi);
    cudaGetSymbolAddress((void**)&khi, g_khi);
    cudaGetSymbolAddress((void**)&vhi, g_vhi);
    __half *wqh, *wkh, *wvh, *woh;
    cudaGetSymbolAddress((void**)&wqh, g_wqT_hi);
    cudaGetSymbolAddress((void**)&wkh, g_wkT_hi);
    cudaGetSymbolAddress((void**)&wvh, g_wvT_hi);
    cudaGetSymbolAddress((void**)&woh, g_woT_hi);

    const int M = MTOT;       // 8192
    const int NKV = G_ * DH_; // 512

    rope_init_kernel<<<(S_ * ROT_ + 255) / 256, 256>>>();

    convert_x_kernel<<<(M * F_ / 4 + 255) / 256, 256>>>(x, xhi, M * F_ / 4);

    transpose_h_kernel<<<dim3(F_ / 32, F_ / 32), dim3(32, 8)>>>(wq, wqh, F_, F_);
    transpose_h_kernel<<<dim3(NKV / 32, F_ / 32), dim3(32, 8)>>>(wk, wkh, F_, NKV);
    transpose_h_kernel<<<dim3(NKV / 32, F_ / 32), dim3(32, 8)>>>(wv, wvh, F_, NKV);
    transpose_h_kernel<<<dim3(F_ / 32, F_ / 32), dim3(32, 8)>>>(wo, woh, F_, F_);

    cudaFuncSetAttribute(qkv_proj_kernel, cudaFuncAttributeMaxDynamicSharedMemorySize, SMEM_GEMM);
    cudaFuncSetAttribute(o_proj_kernel, cudaFuncAttributeMaxDynamicSharedMemorySize, SMEM_GEMM);

    // Merged Q/K/V projection (all 1-term, RoPE fused for Q,K; Q pre-scaled)
    qkv_proj_kernel<<<dim3(24, M / 128), 256, SMEM_GEMM>>>(
        xhi, wqh, wkh, wvh, bq, bk, bv, qhi, khi, vhi);

    // Flash attention (64 q-rows x 128 kv, 2 CTAs/SM overlap)
    cudaFuncSetAttribute(flash_mma_kernel, cudaFuncAttributeMaxDynamicSharedMemorySize, SMEM_FLASH);
    flash_mma_kernel<<<dim3(S_ / 64, H_, B_), 128, SMEM_FLASH>>>();

    // Output projection (1-term, fp32 out)
    o_proj_kernel<<<dim3(F_ / 128, M / 128), 256, SMEM_GEMM>>>(ahi, woh, bo, out);
}